// round 10
// baseline (speedup 1.0000x reference)
#include <cuda_runtime.h>
#include <cuda_bf16.h>
#include <cuda_fp8.h>
#include <math.h>
#include <cstdint>

#define C 1024
#define BATCH 16
#define D 128
#define CB (C*BATCH)
#define CC (C*C)

#define LDK 72                     // padded SMEM row (bf16 elems)
#define TILE_E (128*LDK)           // elems per 128-row bf16 tile
#define TILE_B (TILE_E*2)          // bytes per 128-row bf16 tile (18432)
#define ATILE_E (64*LDK)           // elems per 64-row bf16 tile
#define ATILE_B (ATILE_E*2)        // 9216
#define BUF2_B (2*TILE_B)          // 2-tile slot bytes (36864)
#define BUF4_B (4*TILE_B)          // 4-tile buffer bytes (73728)
#define HBUF_B (2*ATILE_B + 2*TILE_B)  // htmp buffer (55296)

#define LDK8 144                   // padded fp8 row (bytes), K=128
#define TILE8_B (128*LDK8)         // 18432 = TILE_B

// ---------------- scratch (static device memory, no runtime allocation) ----
__device__ uint8_t g_F8[BATCH*CC];           // e4m3 exp(B_t)*mask[col]   [b][i][k]
__device__ uint8_t g_GT8[BATCH*CC];          // e4m3 exp(B_t)^T*mask[col] [b][j][k]
__device__ float g_sumF[BATCH*C];
__device__ float g_sumG[BATCH*C];
__device__ float g_sum2[BATCH*C];
__device__ __nv_bfloat16 g_E2hi[BATCH*CC];   // masked exp(B_new) [b][i][j]
__device__ __nv_bfloat16 g_E2lo[BATCH*CC];
__device__ __nv_bfloat16 g_h1hi[CB*D];
__device__ __nv_bfloat16 g_h1lo[CB*D];
__device__ __nv_bfloat16 g_h2hi[CB*D];
__device__ __nv_bfloat16 g_h2lo[CB*D];
__device__ __nv_bfloat16 g_hThi[BATCH*D*C];  // [b][d][c]
__device__ __nv_bfloat16 g_hTlo[BATCH*D*C];
__device__ __nv_bfloat16 g_mhi[(size_t)CB*384]; // m' = [h, ht, h*ht]
__device__ __nv_bfloat16 g_mlo[(size_t)CB*384];
__device__ __nv_bfloat16 g_Whi[256*384];
__device__ __nv_bfloat16 g_Wlo[256*384];
__device__ float g_z[(size_t)CB*256];

// ----------------------------------------------------------------- helpers
__device__ __forceinline__ uint32_t smem_u32(const void* p) {
    uint32_t a;
    asm("{ .reg .u64 t; cvta.to.shared.u64 t, %1; cvt.u32.u64 %0, t; }" : "=r"(a) : "l"(p));
    return a;
}
__device__ __forceinline__ void mma16816(float* c, const uint32_t* a, const uint32_t* b) {
    asm volatile(
        "mma.sync.aligned.m16n8k16.row.col.f32.bf16.bf16.f32 "
        "{%0,%1,%2,%3}, {%4,%5,%6,%7}, {%8,%9}, {%0,%1,%2,%3};"
        : "+f"(c[0]), "+f"(c[1]), "+f"(c[2]), "+f"(c[3])
        : "r"(a[0]), "r"(a[1]), "r"(a[2]), "r"(a[3]), "r"(b[0]), "r"(b[1]));
}
__device__ __forceinline__ void mma16832f8(float* c, const uint32_t* a, const uint32_t* b) {
    asm volatile(
        "mma.sync.aligned.m16n8k32.row.col.f32.e4m3.e4m3.f32 "
        "{%0,%1,%2,%3}, {%4,%5,%6,%7}, {%8,%9}, {%0,%1,%2,%3};"
        : "+f"(c[0]), "+f"(c[1]), "+f"(c[2]), "+f"(c[3])
        : "r"(a[0]), "r"(a[1]), "r"(a[2]), "r"(a[3]), "r"(b[0]), "r"(b[1]));
}
__device__ __forceinline__ void cp16(uint32_t s, const void* g) {
    asm volatile("cp.async.ca.shared.global [%0], [%1], 16;" :: "r"(s), "l"(g));
}
#define CP_COMMIT() asm volatile("cp.async.commit_group;" ::: "memory")
#define CP_WAITN(n) asm volatile("cp.async.wait_group %0;" :: "n"(n) : "memory")

__device__ __forceinline__ void split2(float2 v, __nv_bfloat162& hi, __nv_bfloat162& lo) {
    hi.x = __float2bfloat16(v.x); lo.x = __float2bfloat16(v.x - __bfloat162float(hi.x));
    hi.y = __float2bfloat16(v.y); lo.y = __float2bfloat16(v.y - __bfloat162float(hi.y));
}
__device__ __forceinline__ uint8_t to_e4m3(float x) {
    return (uint8_t)__nv_cvt_float_to_fp8(x, __NV_SATFINITE, __NV_E4M3);
}

// load one 2-tile bf16 chunk (A, B), 128 rows x 64 bf16 each
__device__ __forceinline__ void issue_single(
    uint32_t sb, int tid,
    const __nv_bfloat16* A, const __nv_bfloat16* Bp, size_t rs)
{
#pragma unroll
    for (int q = 0; q < 4; q++) {
        int idx = q*256 + tid;
        int row = idx >> 3, seg = idx & 7;
        size_t g = (size_t)row*rs + seg*8;
        uint32_t so = row*(LDK*2) + seg*16;
        cp16(sb +          so, A  + g);
        cp16(sb + TILE_B + so, Bp + g);
    }
}

// load one 2-tile fp8 chunk (A, B), 128 rows x 128 e4m3 bytes each (K=128)
__device__ __forceinline__ void issue_fp8_128(
    uint32_t sb, int tid, const uint8_t* A, const uint8_t* Bp, size_t rs)
{
#pragma unroll
    for (int q = 0; q < 8; q++) {
        int idx = q*256 + tid;
        int tile = idx >> 10;
        int row  = (idx >> 3) & 127;
        int seg  = idx & 7;
        const uint8_t* src = tile ? Bp : A;
        cp16(sb + tile*TILE8_B + row*LDK8 + seg*16,
             src + (size_t)row*rs + seg*16);
    }
}

// load one 4-tile bf16 chunk (Ah, Al, Bh, Bl), 128 rows each
__device__ __forceinline__ void issue_tiles(
    uint32_t sb, int tid,
    const __nv_bfloat16* Ah, const __nv_bfloat16* Al,
    const __nv_bfloat16* Bh, const __nv_bfloat16* Bl,
    size_t rsA, size_t rsB)
{
#pragma unroll
    for (int q = 0; q < 4; q++) {
        int idx = q*256 + tid;
        int row = idx >> 3, seg = idx & 7;
        size_t gA = (size_t)row*rsA + seg*8;
        size_t gB = (size_t)row*rsB + seg*8;
        uint32_t so = row*(LDK*2) + seg*16;
        cp16(sb +            so, Ah + gA);
        cp16(sb +   TILE_B + so, Al + gA);
        cp16(sb + 2*TILE_B + so, Bh + gB);
        cp16(sb + 3*TILE_B + so, Bl + gB);
    }
}

// load htmp chunk: A 64 rows hi/lo + B 128 rows hi/lo
__device__ __forceinline__ void issue_tiles64(
    uint32_t sb, int tid,
    const __nv_bfloat16* Ah, const __nv_bfloat16* Al,
    const __nv_bfloat16* Bh, const __nv_bfloat16* Bl,
    size_t rsA, size_t rsB)
{
#pragma unroll
    for (int q = 0; q < 2; q++) {
        int idx = q*256 + tid;                 // 0..511
        int row = idx >> 3, seg = idx & 7;     // row 0..63
        size_t g = (size_t)row*rsA + seg*8;
        uint32_t so = row*(LDK*2) + seg*16;
        cp16(sb +           so, Ah + g);
        cp16(sb + ATILE_B + so, Al + g);
    }
#pragma unroll
    for (int q = 0; q < 4; q++) {
        int idx = q*256 + tid;
        int row = idx >> 3, seg = idx & 7;     // row 0..127
        size_t g = (size_t)row*rsB + seg*8;
        uint32_t so = row*(LDK*2) + seg*16;
        cp16(sb + 2*ATILE_B +          so, Bh + g);
        cp16(sb + 2*ATILE_B + TILE_B + so, Bl + g);
    }
}

// bf16 single-precision chunk (K=64): acc += A.B^T   (128x128 tile geometry)
__device__ __forceinline__ void compute_chunk1(
    const __nv_bfloat16* base, float acc[4][4][4], int wm, int wn, int lid)
{
    const __nv_bfloat16* sA = base;
    const __nv_bfloat16* sB = base + TILE_E;
    int lrow = lid >> 2;
    int lcol2 = (lid & 3) << 1;
#pragma unroll
    for (int ks = 0; ks < 4; ks++) {
        int k0 = ks*16 + lcol2;
        uint32_t a[4][4];
        int rbase = wm*64 + lrow;
#pragma unroll
        for (int im = 0; im < 4; im++) {
            int r = rbase + im*16;
            a[im][0] = *(const uint32_t*)(sA + r*LDK + k0);
            a[im][1] = *(const uint32_t*)(sA + (r+8)*LDK + k0);
            a[im][2] = *(const uint32_t*)(sA + r*LDK + k0 + 8);
            a[im][3] = *(const uint32_t*)(sA + (r+8)*LDK + k0 + 8);
        }
        uint32_t bb[4][2];
        int nbase = wn*32 + lrow;
#pragma unroll
        for (int jn = 0; jn < 4; jn++) {
            int n = nbase + jn*8;
            bb[jn][0] = *(const uint32_t*)(sB + n*LDK + k0);
            bb[jn][1] = *(const uint32_t*)(sB + n*LDK + k0 + 8);
        }
#pragma unroll
        for (int im = 0; im < 4; im++)
#pragma unroll
            for (int jn = 0; jn < 4; jn++)
                mma16816(acc[im][jn], a[im], bb[jn]);
    }
}

// fp8 chunk (K=128): acc += A.B^T via 4 x m16n8k32 ksteps
__device__ __forceinline__ void compute_chunk_fp8(
    const uint8_t* base, float acc[4][4][4], int wm, int wn, int lid)
{
    const uint8_t* sA = base;
    const uint8_t* sB = base + TILE8_B;
    int lrow = lid >> 2;
    int l4 = (lid & 3) << 2;
#pragma unroll
    for (int ks = 0; ks < 4; ks++) {
        int koff = ks*32 + l4;
        uint32_t a[4][4];
        int rbase = wm*64 + lrow;
#pragma unroll
        for (int im = 0; im < 4; im++) {
            int r = rbase + im*16;
            a[im][0] = *(const uint32_t*)(sA + r*LDK8 + koff);
            a[im][1] = *(const uint32_t*)(sA + (r+8)*LDK8 + koff);
            a[im][2] = *(const uint32_t*)(sA + r*LDK8 + koff + 16);
            a[im][3] = *(const uint32_t*)(sA + (r+8)*LDK8 + koff + 16);
        }
        uint32_t bb[4][2];
        int nbase = wn*32 + lrow;
#pragma unroll
        for (int jn = 0; jn < 4; jn++) {
            int n = nbase + jn*8;
            bb[jn][0] = *(const uint32_t*)(sB + n*LDK8 + koff);
            bb[jn][1] = *(const uint32_t*)(sB + n*LDK8 + koff + 16);
        }
#pragma unroll
        for (int im = 0; im < 4; im++)
#pragma unroll
            for (int jn = 0; jn < 4; jn++)
                mma16832f8(acc[im][jn], a[im], bb[jn]);
    }
}

// split-bf16 (3-mma) chunk, 128x128 tile: acc += A.B^T
__device__ __forceinline__ void compute_chunk(
    const __nv_bfloat16* base, float acc[4][4][4], int wm, int wn, int lid)
{
    const __nv_bfloat16* sAh = base;
    const __nv_bfloat16* sAl = base + TILE_E;
    const __nv_bfloat16* sBh = base + 2*TILE_E;
    const __nv_bfloat16* sBl = base + 3*TILE_E;
    int lrow = lid >> 2;
    int lcol2 = (lid & 3) << 1;
#pragma unroll
    for (int ks = 0; ks < 4; ks++) {
        int k0 = ks*16 + lcol2;
        uint32_t ah[4][4], al[4][4];
        int rbase = wm*64 + lrow;
#pragma unroll
        for (int im = 0; im < 4; im++) {
            int r = rbase + im*16;
            ah[im][0] = *(const uint32_t*)(sAh + r*LDK + k0);
            ah[im][1] = *(const uint32_t*)(sAh + (r+8)*LDK + k0);
            ah[im][2] = *(const uint32_t*)(sAh + r*LDK + k0 + 8);
            ah[im][3] = *(const uint32_t*)(sAh + (r+8)*LDK + k0 + 8);
            al[im][0] = *(const uint32_t*)(sAl + r*LDK + k0);
            al[im][1] = *(const uint32_t*)(sAl + (r+8)*LDK + k0);
            al[im][2] = *(const uint32_t*)(sAl + r*LDK + k0 + 8);
            al[im][3] = *(const uint32_t*)(sAl + (r+8)*LDK + k0 + 8);
        }
        uint32_t bh[4][2], bl[4][2];
        int nbase = wn*32 + lrow;
#pragma unroll
        for (int jn = 0; jn < 4; jn++) {
            int n = nbase + jn*8;
            bh[jn][0] = *(const uint32_t*)(sBh + n*LDK + k0);
            bh[jn][1] = *(const uint32_t*)(sBh + n*LDK + k0 + 8);
            bl[jn][0] = *(const uint32_t*)(sBl + n*LDK + k0);
            bl[jn][1] = *(const uint32_t*)(sBl + n*LDK + k0 + 8);
        }
#pragma unroll
        for (int im = 0; im < 4; im++)
#pragma unroll
            for (int jn = 0; jn < 4; jn++) {
                mma16816(acc[im][jn], ah[im], bh[jn]);
                mma16816(acc[im][jn], ah[im], bl[jn]);
                mma16816(acc[im][jn], al[im], bh[jn]);
            }
    }
}

// split-bf16 (3-mma) chunk, 64x128 tile (A 64 rows): acc[2][4][4]
__device__ __forceinline__ void compute_chunk64(
    const __nv_bfloat16* base, float acc[2][4][4], int wm, int wn, int lid)
{
    const __nv_bfloat16* sAh = base;
    const __nv_bfloat16* sAl = base + ATILE_E;
    const __nv_bfloat16* sBh = base + 2*ATILE_E;
    const __nv_bfloat16* sBl = base + 2*ATILE_E + TILE_E;
    int lrow = lid >> 2;
    int lcol2 = (lid & 3) << 1;
#pragma unroll
    for (int ks = 0; ks < 4; ks++) {
        int k0 = ks*16 + lcol2;
        uint32_t ah[2][4], al[2][4];
        int rbase = wm*32 + lrow;
#pragma unroll
        for (int im = 0; im < 2; im++) {
            int r = rbase + im*16;
            ah[im][0] = *(const uint32_t*)(sAh + r*LDK + k0);
            ah[im][1] = *(const uint32_t*)(sAh + (r+8)*LDK + k0);
            ah[im][2] = *(const uint32_t*)(sAh + r*LDK + k0 + 8);
            ah[im][3] = *(const uint32_t*)(sAh + (r+8)*LDK + k0 + 8);
            al[im][0] = *(const uint32_t*)(sAl + r*LDK + k0);
            al[im][1] = *(const uint32_t*)(sAl + (r+8)*LDK + k0);
            al[im][2] = *(const uint32_t*)(sAl + r*LDK + k0 + 8);
            al[im][3] = *(const uint32_t*)(sAl + (r+8)*LDK + k0 + 8);
        }
        uint32_t bh[4][2], bl[4][2];
        int nbase = wn*32 + lrow;
#pragma unroll
        for (int jn = 0; jn < 4; jn++) {
            int n = nbase + jn*8;
            bh[jn][0] = *(const uint32_t*)(sBh + n*LDK + k0);
            bh[jn][1] = *(const uint32_t*)(sBh + n*LDK + k0 + 8);
            bl[jn][0] = *(const uint32_t*)(sBl + n*LDK + k0);
            bl[jn][1] = *(const uint32_t*)(sBl + n*LDK + k0 + 8);
        }
#pragma unroll
        for (int im = 0; im < 2; im++)
#pragma unroll
            for (int jn = 0; jn < 4; jn++) {
                mma16816(acc[im][jn], ah[im], bh[jn]);
                mma16816(acc[im][jn], ah[im], bl[jn]);
                mma16816(acc[im][jn], al[im], bh[jn]);
            }
    }
}

// ---------------------------------------------------------------- FC kernel
__global__ void __launch_bounds__(256) fc_kernel(
    const float* __restrict__ h,
    const float* __restrict__ W1, const float* __restrict__ b1,
    const float* __restrict__ W2, const float* __restrict__ b2)
{
    __shared__ float As[16][64];
    __shared__ float Bs[16][64];
    int t  = threadIdx.x;
    int tx = t & 15, ty = t >> 4;
    int bm = blockIdx.x, bn = blockIdx.y;

    float acc[4][4] = {};
    int ar = t >> 2;
    int kc = (t & 3) << 2;
    int rowA = bm*64 + ar;
    int e    = bn*64 + ar;
    const float* Bptr = (e < 128) ? (W1 + e*128) : (W2 + (e-128)*128);

    for (int kt = 0; kt < 128; kt += 16) {
        float4 av = *(const float4*)(h + (size_t)rowA*128 + kt + kc);
        float4 bv = *(const float4*)(Bptr + kt + kc);
        As[kc+0][ar]=av.x; As[kc+1][ar]=av.y; As[kc+2][ar]=av.z; As[kc+3][ar]=av.w;
        Bs[kc+0][ar]=bv.x; Bs[kc+1][ar]=bv.y; Bs[kc+2][ar]=bv.z; Bs[kc+3][ar]=bv.w;
        __syncthreads();
#pragma unroll
        for (int k = 0; k < 16; k++) {
            float a[4], bb[4];
#pragma unroll
            for (int i = 0; i < 4; i++) a[i]  = As[k][ty*4+i];
#pragma unroll
            for (int j = 0; j < 4; j++) bb[j] = Bs[k][tx*4+j];
#pragma unroll
            for (int i = 0; i < 4; i++)
#pragma unroll
                for (int j = 0; j < 4; j++)
                    acc[i][j] += a[i]*bb[j];
        }
        __syncthreads();
    }

#pragma unroll
    for (int i = 0; i < 4; i++) {
        int r = bm*64 + ty*4 + i;
        int c = r >> 4, b = r & 15;
#pragma unroll
        for (int j = 0; j < 4; j++) {
            int ee = bn*64 + tx*4 + j;
            float bias = (ee < 128) ? b1[ee] : b2[ee-128];
            float v = acc[i][j] + bias;
            v = v > 0.f ? v : 0.f;
            __nv_bfloat16 hi = __float2bfloat16(v);
            __nv_bfloat16 lo = __float2bfloat16(v - __bfloat162float(hi));
            size_t idx = ((size_t)(b*C + c))*D + (ee & 127);
            if (ee < 128) { g_h1hi[idx] = hi; g_h1lo[idx] = lo; }
            else          { g_h2hi[idx] = hi; g_h2lo[idx] = lo; }
        }
    }
}

// ----------------- fused exp of B_t on 128x128 tiles (e4m3 smem tile) -------
#define LDT 132   // byte stride of the e4m3 tile
__global__ void __launch_bounds__(256) esplit_kernel(
    const float* __restrict__ Bt, const int* __restrict__ mask)
{
    __shared__ uint8_t tile[128*LDT];    // quantized raw exp, [x][y]
    __shared__ float scol[128];
    int b  = blockIdx.z;
    int x0 = blockIdx.y * 128;
    int y0 = blockIdx.x * 128;
    int w = threadIdx.x >> 5, lid = threadIdx.x & 31;

    if (threadIdx.x < 128) scol[threadIdx.x] = 0.f;
    __syncthreads();

    int4 my4 = *(const int4*)(mask + b*C + y0 + lid*4);
    float yf0 = my4.x ? 1.f : 0.f, yf1 = my4.y ? 1.f : 0.f;
    float yf2 = my4.z ? 1.f : 0.f, yf3 = my4.w ? 1.f : 0.f;
    uint32_t ymask = (my4.x ? 0xFFu : 0) | (my4.y ? 0xFF00u : 0)
                   | (my4.z ? 0xFF0000u : 0) | (my4.w ? 0xFF000000u : 0);

    float gs0 = 0.f, gs1 = 0.f, gs2 = 0.f, gs3 = 0.f;
#pragma unroll 4
    for (int i = 0; i < 16; i++) {
        int xl = w*16 + i;
        int x = x0 + xl;
        float4 v = *(const float4*)(Bt + (size_t)b*CC + (size_t)x*C + y0 + lid*4);
        float e0 = __expf(v.x), e1 = __expf(v.y), e2 = __expf(v.z), e3 = __expf(v.w);
        // row sum (y-masked, fp32 exact)
        float s = e0*yf0 + e1*yf1 + e2*yf2 + e3*yf3;
#pragma unroll
        for (int o = 16; o > 0; o >>= 1) s += __shfl_xor_sync(0xffffffffu, s, o);
        if (lid == 0) atomicAdd(g_sumF + b*C + x, s);
        // quantize raw exp once
        uint32_t pk =  (uint32_t)to_e4m3(e0)        | ((uint32_t)to_e4m3(e1) << 8)
                    | ((uint32_t)to_e4m3(e2) << 16) | ((uint32_t)to_e4m3(e3) << 24);
        *(uint32_t*)(tile + xl*LDT + lid*4) = pk;
        *(uint32_t*)(g_F8 + (size_t)b*CC + (size_t)x*C + y0 + lid*4) = pk & ymask;
        // column partial sums (x-masked, fp32 exact)
        float mrow = mask[b*C + x] ? 1.f : 0.f;
        gs0 += e0*mrow; gs1 += e1*mrow; gs2 += e2*mrow; gs3 += e3*mrow;
    }
    atomicAdd(&scol[lid*4 + 0], gs0);
    atomicAdd(&scol[lid*4 + 1], gs1);
    atomicAdd(&scol[lid*4 + 2], gs2);
    atomicAdd(&scol[lid*4 + 3], gs3);
    __syncthreads();
    if (threadIdx.x < 128)
        atomicAdd(g_sumG + b*C + y0 + threadIdx.x, scol[threadIdx.x]);

    // pass 2: transposed masked bytes -> GT8 (coalesced uint32 stores)
    int xq = lid*4;
    const int* mk = mask + b*C + x0 + xq;
    uint32_t xmask = (mk[0] ? 0xFFu : 0) | (mk[1] ? 0xFF00u : 0)
                   | (mk[2] ? 0xFF0000u : 0) | (mk[3] ? 0xFF000000u : 0);
#pragma unroll 4
    for (int i = 0; i < 16; i++) {
        int yl = w*16 + i;
        int y = y0 + yl;
        uint32_t pk =  (uint32_t)tile[(xq+0)*LDT + yl]
                    | ((uint32_t)tile[(xq+1)*LDT + yl] << 8)
                    | ((uint32_t)tile[(xq+2)*LDT + yl] << 16)
                    | ((uint32_t)tile[(xq+3)*LDT + yl] << 24);
        *(uint32_t*)(g_GT8 + (size_t)b*CC + (size_t)y*C + x0 + xq) = pk & xmask;
    }
}

// ------------------------------------ hT transpose: h(c,b,d) -> [b][d][c] hi/lo
__global__ void __launch_bounds__(256) ht_transpose_kernel(const float* __restrict__ h)
{
    __shared__ float tileT[32][33];
    int b  = blockIdx.z;
    int c0 = blockIdx.x * 32;
    int d0 = blockIdx.y * 32;
    int tx = threadIdx.x & 31, ty = threadIdx.x >> 5;

#pragma unroll
    for (int r = ty; r < 32; r += 8)
        tileT[r][tx] = h[(size_t)((c0 + r)*16 + b)*128 + d0 + tx];
    __syncthreads();
#pragma unroll
    for (int r = ty; r < 32; r += 8) {
        float x = tileT[tx][r];
        __nv_bfloat16 hi = __float2bfloat16(x);
        __nv_bfloat16 lo = __float2bfloat16(x - __bfloat162float(hi));
        size_t o = (size_t)b*D*C + (size_t)(d0 + r)*C + c0 + tx;
        g_hThi[o] = hi;
        g_hTlo[o] = lo;
    }
}

// --------- folded weight stack + sum zeroing --------------------------------
__global__ void __launch_bounds__(256) wsplit_kernel(
    const float* __restrict__ Wr, const float* __restrict__ Wg)
{
    int idx = blockIdx.x*256 + threadIdx.x;
    if (idx < 3*BATCH*C) {
        if (idx < BATCH*C)          g_sumF[idx] = 0.f;
        else if (idx < 2*BATCH*C)   g_sumG[idx - BATCH*C] = 0.f;
        else                        g_sum2[idx - 2*BATCH*C] = 0.f;
    }
    int n = idx / 384, k = idx % 384;
    const float* W = (n < 128) ? (Wr + n*512) : (Wg + (n-128)*512);
    float x;
    if (k < 128)       x = W[k] + W[384 + k];
    else if (k < 256)  x = W[k] - W[k + 256];     // W1 - W3
    else               x = W[k];
    __nv_bfloat16 hi = __float2bfloat16(x);
    g_Whi[idx] = hi;
    g_Wlo[idx] = __float2bfloat16(x - __bfloat162float(hi));
}

// ============================ B_new GEMM + fused softmax epilogue ===========
__global__ void __launch_bounds__(256, 2) bnew_mma_kernel(
    const float* __restrict__ gamma_p, const int* __restrict__ mask,
    float* __restrict__ out)
{
    extern __shared__ char smc[];
    __shared__ int   sMask[128];
    __shared__ float sRow[128];
    int tid = threadIdx.x, wid = tid >> 5, lid = tid & 31;
    int b = blockIdx.z, it = blockIdx.y, jt = blockIdx.x;
    int wm = wid & 1, wn = wid >> 1;
    uint32_t sb = smem_u32(smc);

    if (tid < 128) { sMask[tid] = mask[b*C + jt*128 + tid]; sRow[tid] = 0.f; }

    float acc[4][4][4] = {};
    float gma = gamma_p[0];
    int lrow = lid >> 2, lcol2 = (lid & 3) << 1;

    auto issue = [&](int c) {
        uint32_t slot = sb + (uint32_t)(c % 3)*BUF2_B;
        if (c < 8) {
            const uint8_t* A  = g_F8  + ((size_t)b*C + (size_t)it*128)*C + (size_t)c*128;
            const uint8_t* Bp = g_GT8 + ((size_t)b*C + (size_t)jt*128)*C + (size_t)c*128;
            issue_fp8_128(slot, tid, A, Bp, C);
        } else {
            int tm = (c - 8) >> 1, kh = (c - 8) & 1;
            const __nv_bfloat16* A1 = (tm < 2)  ? g_h1hi : g_h1lo;
            const __nv_bfloat16* B1 = (tm == 1) ? g_h2lo : g_h2hi;
            issue_single(slot, tid,
                         A1 + ((size_t)b*C + (size_t)it*128)*D + kh*64,
                         B1 + ((size_t)b*C + (size_t)jt*128)*D + kh*64, D);
        }
    };

    issue(0); CP_COMMIT();
    issue(1); CP_COMMIT();
    issue(2); CP_COMMIT();

    for (int c = 0; c < 14; c++) {
        int n = 13 - c; if (n > 2) n = 2;
        switch (n) {
            case 2: CP_WAITN(2); break;
            case 1: CP_WAITN(1); break;
            default: CP_WAITN(0); break;
        }
        __syncthreads();
        if (c == 8) {
            float invR[8], invCv[8];
#pragma unroll
            for (int im = 0; im < 4; im++) {
                int r = it*128 + wm*64 + lrow + im*16;
                invR[2*im]   = gma / g_sumF[b*C + r];
                invR[2*im+1] = gma / g_sumF[b*C + r + 8];
            }
#pragma unroll
            for (int jn = 0; jn < 4; jn++) {
                int cj = jt*128 + wn*32 + lcol2 + jn*8;
                invCv[2*jn]   = 1.0f / g_sumG[b*C + cj];
                invCv[2*jn+1] = 1.0f / g_sumG[b*C + cj + 1];
            }
#pragma unroll
            for (int im = 0; im < 4; im++)
#pragma unroll
                for (int jn = 0; jn < 4; jn++) {
                    acc[im][jn][0] *= invR[2*im]   * invCv[2*jn];
                    acc[im][jn][1] *= invR[2*im]   * invCv[2*jn+1];
                    acc[im][jn][2] *= invR[2*im+1] * invCv[2*jn];
                    acc[im][jn][3] *= invR[2*im+1] * invCv[2*jn+1];
                }
        }
        char* base = smc + (c % 3)*BUF2_B;
        if (c < 8) compute_chunk_fp8((const uint8_t*)base, acc, wm, wn, lid);
        else       compute_chunk1((const __nv_bfloat16*)base, acc, wm, wn, lid);
        __syncthreads();
        if (c + 3 < 14) { issue(c + 3); CP_COMMIT(); }
    }

    // ---- epilogue: diag zero, store fp32, fused masked exp + row sums ----
    int gi0 = it*128 + wm*64 + lrow;
    int gj0 = jt*128 + wn*32 + lcol2;
    float* obase = out + (size_t)b*CC;
#pragma unroll
    for (int im = 0; im < 4; im++) {
        int r = gi0 + im*16;
        float rp0 = 0.f, rp1 = 0.f;
#pragma unroll
        for (int jn = 0; jn < 4; jn++) {
            int cj = gj0 + jn*8;
            int lc = wn*32 + lcol2 + jn*8;
            float2 v0 = make_float2(acc[im][jn][0], acc[im][jn][1]);
            float2 v1 = make_float2(acc[im][jn][2], acc[im][jn][3]);
            if (r == cj)        v0.x = 0.f;
            else if (r == cj+1) v0.y = 0.f;
            if (r+8 == cj)      v1.x = 0.f;
            else if (r+8 == cj+1) v1.y = 0.f;
            *(float2*)(obase + (size_t)r*C + cj)     = v0;
            *(float2*)(obase + (size_t)(r+8)*C + cj) = v1;

            int m0 = sMask[lc], m1 = sMask[lc+1];
            float2 e0 = make_float2(m0 ? __expf(v0.x) : 0.f, m1 ? __expf(v0.y) : 0.f);
            float2 e1 = make_float2(m0 ? __expf(v1.x) : 0.f, m1 ? __expf(v1.y) : 0.f);
            rp0 += e0.x + e0.y;
            rp1 += e1.x + e1.y;
            __nv_bfloat162 h0, l0, h1, l1;
            split2(e0, h0, l0);
            split2(e1, h1, l1);
            size_t o0 = (size_t)b*CC + (size_t)r*C + cj;
            size_t o1 = (size_t)b*CC + (size_t)(r+8)*C + cj;
            *(__nv_bfloat162*)(g_E2hi + o0) = h0;
            *(__nv_bfloat162*)(g_E2lo + o0) = l0;
            *(__nv_bfloat162*)(g_E2hi + o1) = h1;
            *(__nv_bfloat162*)(g_E2lo + o1) = l1;
        }
        atomicAdd(&sRow[wm*64 + lrow + im*16],     rp0);
        atomicAdd(&sRow[wm*64 + lrow + im*16 + 8], rp1);
    }
    __syncthreads();
    if (tid < 128) atomicAdd(g_sum2 + b*C + it*128 + tid, sRow[tid]);
}

// ============================ h_tmp GEMM (M=64) + m' construction ============
__global__ void __launch_bounds__(256, 2) htmp_mma_kernel(const float* __restrict__ h)
{
    extern __shared__ char smc[];
    __nv_bfloat16* sm = (__nv_bfloat16*)smc;
    int tid = threadIdx.x, wid = tid >> 5, lid = tid & 31;
    int it = blockIdx.x, b = blockIdx.y;       // it over C/64 tiles
    int wm = wid & 1, wn = wid >> 1;
    uint32_t sb = smem_u32(sm);

    float acc[2][4][4] = {};

    auto issue = [&](int c, int buf) {
        size_t offA = ((size_t)b*C + (size_t)it*64)*C + (size_t)c*64;
        size_t offB = (size_t)b*D*C + (size_t)c*64;
        issue_tiles64(sb + buf*HBUF_B, tid,
                      g_E2hi + offA, g_E2lo + offA,
                      g_hThi + offB, g_hTlo + offB, C, C);
    };

    issue(0, 0); CP_COMMIT();
    for (int c = 0; c < 16; c++) {
        if (c + 1 < 16) { issue(c + 1, (c + 1) & 1); CP_COMMIT(); CP_WAITN(1); }
        else CP_WAITN(0);
        __syncthreads();
        compute_chunk64(sm + (c & 1)*(HBUF_B/2), acc, wm, wn, lid);
        __syncthreads();
    }

    int lrow = lid >> 2, lcol2 = (lid & 3) << 1;
    int ci0 = it*64 + wm*32 + lrow;
    int d0  = wn*32 + lcol2;
#pragma unroll
    for (int im = 0; im < 2; im++) {
#pragma unroll
        for (int half = 0; half < 2; half++) {
            int cg = ci0 + im*16 + half*8;
            int r  = cg*16 + b;
            float inv = 1.0f / g_sum2[b*C + cg];
#pragma unroll
            for (int jn = 0; jn < 4; jn++) {
                int dj = d0 + jn*8;
                float2 ht = half ? make_float2(acc[im][jn][2], acc[im][jn][3])
                                 : make_float2(acc[im][jn][0], acc[im][jn][1]);
                ht.x *= inv; ht.y *= inv;
                float2 hv = *(const float2*)(h + (size_t)r*128 + dj);
                float2 seg[3];
                seg[0] = hv;
                seg[1] = ht;
                seg[2] = make_float2(hv.x*ht.x, hv.y*ht.y);
#pragma unroll
                for (int s = 0; s < 3; s++) {
                    __nv_bfloat162 hi, lo;
                    split2(seg[s], hi, lo);
                    size_t o = (size_t)r*384 + s*128 + dj;
                    *(__nv_bfloat162*)(g_mhi + o) = hi;
                    *(__nv_bfloat162*)(g_mlo + o) = lo;
                }
            }
        }
    }
}

// ============================ gate GEMM: z = m' . W'^T =======================
__global__ void __launch_bounds__(256) gate_mma_kernel()
{
    extern __shared__ char smc[];
    __nv_bfloat16* sm = (__nv_bfloat16*)smc;
    int tid = threadIdx.x, wid = tid >> 5, lid = tid & 31;
    int bm = blockIdx.x, half = blockIdx.y;
    int wm = wid & 1, wn = wid >> 1;
    uint32_t sb = smem_u32(sm);

    float acc[4][4][4] = {};

    auto issue = [&](int c, int buf) {
        size_t offA = ((size_t)bm*128)*384 + (size_t)c*64;
        size_t offB = ((size_t)half*128)*384 + (size_t)c*64;
        issue_tiles(sb + buf*BUF4_B, tid,
                    g_mhi + offA, g_mlo + offA,
                    g_Whi + offB, g_Wlo + offB, 384, 384);
    };

    issue(0, 0); CP_COMMIT();
    for (int c = 0; c < 6; c++) {
        if (c + 1 < 6) { issue(c + 1, (c + 1) & 1); CP_COMMIT(); CP_WAITN(1); }
        else CP_WAITN(0);
        __syncthreads();
        compute_chunk(sm + (c & 1)*4*TILE_E, acc, wm, wn, lid);
        __syncthreads();
    }

    int lrow = lid >> 2, lcol2 = (lid & 3) << 1;
    int r0 = bm*128 + wm*64 + lrow;
    int n0 = half*128 + wn*32 + lcol2;
#pragma unroll
    for (int im = 0; im < 4; im++) {
        int r = r0 + im*16;
#pragma unroll
        for (int jn = 0; jn < 4; jn++) {
            int n = n0 + jn*8;
            *(float2*)(g_z + (size_t)r*256 + n)     = make_float2(acc[im][jn][0], acc[im][jn][1]);
            *(float2*)(g_z + (size_t)(r+8)*256 + n) = make_float2(acc[im][jn][2], acc[im][jn][3]);
        }
    }
}

// ------------------------------------------------ combine: o = x*g + (1-g)*h
__global__ void __launch_bounds__(256) combine_kernel(
    const float* __restrict__ h, float* __restrict__ o)
{
    int idx = blockIdx.x*256 + threadIdx.x;
    int r = idx >> 5, q = idx & 31;
    float4 zr = *(const float4*)(g_z + (size_t)r*256 + q*4);
    float4 zg = *(const float4*)(g_z + (size_t)r*256 + 128 + q*4);
    float4 hv = *(const float4*)(h + (size_t)r*128 + q*4);
    float4 ov;
    { float x = fmaxf(zr.x, 0.f), gg = 1.0f/(1.0f + __expf(-zg.x)); ov.x = x*gg + (1.0f-gg)*hv.x; }
    { float x = fmaxf(zr.y, 0.f), gg = 1.0f/(1.0f + __expf(-zg.y)); ov.y = x*gg + (1.0f-gg)*hv.y; }
    { float x = fmaxf(zr.z, 0.f), gg = 1.0f/(1.0f + __expf(-zg.z)); ov.z = x*gg + (1.0f-gg)*hv.z; }
    { float x = fmaxf(zr.w, 0.f), gg = 1.0f/(1.0f + __expf(-zg.w)); ov.w = x*gg + (1.0f-gg)*hv.w; }
    *(float4*)(o + (size_t)r*128 + q*4) = ov;
}

// ---------------------------------------------------------------------------
extern "C" void kernel_launch(void* const* d_in, const int* in_sizes, int n_in,
                              void* d_out, int out_size)
{
    const float* h   = (const float*)d_in[0];
    const int*   hm  = (const int*)  d_in[1];
    const float* Bt  = (const float*)d_in[2];
    const float* W1w = (const float*)d_in[3];
    const float* W1b = (const float*)d_in[4];
    const float* W2w = (const float*)d_in[5];
    const float* W2b = (const float*)d_in[6];
    const float* gam = (const float*)d_in[7];
    const float* Wrw = (const float*)d_in[8];
    const float* Wgw = (const float*)d_in[9];

    float* o_out    = (float*)d_out;
    float* bnew_out = (float*)d_out + (size_t)CB*D;

    const int BNEW_SMEM = 3*BUF2_B;        // 110592 -> 2 CTAs/SM
    const int HTMP_SMEM = 2*HBUF_B;        // 110592 -> 2 CTAs/SM
    const int GATE_SMEM = 2*BUF4_B;        // 147456
    cudaFuncSetAttribute(bnew_mma_kernel, cudaFuncAttributeMaxDynamicSharedMemorySize, BNEW_SMEM);
    cudaFuncSetAttribute(htmp_mma_kernel, cudaFuncAttributeMaxDynamicSharedMemorySize, HTMP_SMEM);
    cudaFuncSetAttribute(gate_mma_kernel, cudaFuncAttributeMaxDynamicSharedMemorySize, GATE_SMEM);

    wsplit_kernel<<<256*384/256, 256>>>(Wrw, Wgw);   // also zeroes sums
    fc_kernel<<<dim3(CB/64, 4), 256>>>(h, W1w, W1b, W2w, W2b);
    ht_transpose_kernel<<<dim3(C/32, D/32, BATCH), 256>>>(h);
    esplit_kernel<<<dim3(8, 8, BATCH), 256>>>(Bt, hm);
    bnew_mma_kernel<<<dim3(C/128, C/128, BATCH), 256, BNEW_SMEM>>>(gam, hm, bnew_out);
    htmp_mma_kernel<<<dim3(C/64, BATCH), 256, HTMP_SMEM>>>(h);
    gate_mma_kernel<<<dim3(CB/128, 2), 256, GATE_SMEM>>>();
    combine_kernel<<<CB*32/256, 256>>>(h, o_out);
}

// round 11
// speedup vs baseline: 1.0535x; 1.0535x over previous
#include <cuda_runtime.h>
#include <cuda_bf16.h>
#include <cuda_fp8.h>
#include <math.h>
#include <cstdint>

#define C 1024
#define BATCH 16
#define D 128
#define CB (C*BATCH)
#define CC (C*C)

#define LDK 72                     // padded SMEM row (bf16 elems)
#define TILE_E (128*LDK)           // elems per 128-row bf16 tile
#define TILE_B (TILE_E*2)          // bytes per 128-row bf16 tile (18432)
#define BUF2_B (2*TILE_B)          // 2-tile slot bytes (36864)
#define BUF4_B (4*TILE_B)          // 4-tile buffer bytes (73728)

#define LDK8 144                   // padded fp8 row (bytes), K=128
#define TILE8_B (128*LDK8)         // 18432 = TILE_B

// ---------------- scratch (static device memory, no runtime allocation) ----
__device__ uint8_t g_F8[BATCH*CC];           // e4m3 exp(B_t)*mask[col]   [b][i][k]
__device__ uint8_t g_GT8[BATCH*CC];          // e4m3 exp(B_t)^T*mask[col] [b][j][k]
__device__ float g_sumF[BATCH*C];
__device__ float g_sumG[BATCH*C];
__device__ float g_sum2[BATCH*C];
__device__ __nv_bfloat16 g_E2hi[BATCH*CC];   // masked exp(B_new) [b][i][j]
__device__ __nv_bfloat16 g_E2lo[BATCH*CC];
__device__ __nv_bfloat16 g_h1hi[CB*D];
__device__ __nv_bfloat16 g_h1lo[CB*D];
__device__ __nv_bfloat16 g_h2hi[CB*D];
__device__ __nv_bfloat16 g_h2lo[CB*D];
__device__ __nv_bfloat16 g_hThi[BATCH*D*C];  // [b][d][c]
__device__ __nv_bfloat16 g_hTlo[BATCH*D*C];
__device__ __nv_bfloat16 g_mhi[(size_t)CB*384]; // m' = [h, ht, h*ht]
__device__ __nv_bfloat16 g_mlo[(size_t)CB*384];
__device__ __nv_bfloat16 g_Whi[256*384];
__device__ __nv_bfloat16 g_Wlo[256*384];
__device__ float g_z[(size_t)CB*256];

// ----------------------------------------------------------------- helpers
__device__ __forceinline__ uint32_t smem_u32(const void* p) {
    uint32_t a;
    asm("{ .reg .u64 t; cvta.to.shared.u64 t, %1; cvt.u32.u64 %0, t; }" : "=r"(a) : "l"(p));
    return a;
}
__device__ __forceinline__ void mma16816(float* c, const uint32_t* a, const uint32_t* b) {
    asm volatile(
        "mma.sync.aligned.m16n8k16.row.col.f32.bf16.bf16.f32 "
        "{%0,%1,%2,%3}, {%4,%5,%6,%7}, {%8,%9}, {%0,%1,%2,%3};"
        : "+f"(c[0]), "+f"(c[1]), "+f"(c[2]), "+f"(c[3])
        : "r"(a[0]), "r"(a[1]), "r"(a[2]), "r"(a[3]), "r"(b[0]), "r"(b[1]));
}
__device__ __forceinline__ void mma16832f8(float* c, const uint32_t* a, const uint32_t* b) {
    asm volatile(
        "mma.sync.aligned.m16n8k32.row.col.f32.e4m3.e4m3.f32 "
        "{%0,%1,%2,%3}, {%4,%5,%6,%7}, {%8,%9}, {%0,%1,%2,%3};"
        : "+f"(c[0]), "+f"(c[1]), "+f"(c[2]), "+f"(c[3])
        : "r"(a[0]), "r"(a[1]), "r"(a[2]), "r"(a[3]), "r"(b[0]), "r"(b[1]));
}
__device__ __forceinline__ void cp16(uint32_t s, const void* g) {
    asm volatile("cp.async.ca.shared.global [%0], [%1], 16;" :: "r"(s), "l"(g));
}
#define CP_COMMIT() asm volatile("cp.async.commit_group;" ::: "memory")
#define CP_WAITN(n) asm volatile("cp.async.wait_group %0;" :: "n"(n) : "memory")

__device__ __forceinline__ void split2(float2 v, __nv_bfloat162& hi, __nv_bfloat162& lo) {
    hi.x = __float2bfloat16(v.x); lo.x = __float2bfloat16(v.x - __bfloat162float(hi.x));
    hi.y = __float2bfloat16(v.y); lo.y = __float2bfloat16(v.y - __bfloat162float(hi.y));
}
__device__ __forceinline__ uint8_t to_e4m3(float x) {
    return (uint8_t)__nv_cvt_float_to_fp8(x, __NV_SATFINITE, __NV_E4M3);
}

// load one 2-tile bf16 chunk (A, B), 128 rows x 64 bf16 each
__device__ __forceinline__ void issue_single(
    uint32_t sb, int tid,
    const __nv_bfloat16* A, const __nv_bfloat16* Bp, size_t rs)
{
#pragma unroll
    for (int q = 0; q < 4; q++) {
        int idx = q*256 + tid;
        int row = idx >> 3, seg = idx & 7;
        size_t g = (size_t)row*rs + seg*8;
        uint32_t so = row*(LDK*2) + seg*16;
        cp16(sb +          so, A  + g);
        cp16(sb + TILE_B + so, Bp + g);
    }
}

// load one 2-tile fp8 chunk (A, B), 128 rows x 128 e4m3 bytes each (K=128)
__device__ __forceinline__ void issue_fp8_128(
    uint32_t sb, int tid, const uint8_t* A, const uint8_t* Bp, size_t rs)
{
#pragma unroll
    for (int q = 0; q < 8; q++) {
        int idx = q*256 + tid;
        int tile = idx >> 10;
        int row  = (idx >> 3) & 127;
        int seg  = idx & 7;
        const uint8_t* src = tile ? Bp : A;
        cp16(sb + tile*TILE8_B + row*LDK8 + seg*16,
             src + (size_t)row*rs + seg*16);
    }
}

// load one 4-tile bf16 chunk (Ah, Al, Bh, Bl), 128 rows each
__device__ __forceinline__ void issue_tiles(
    uint32_t sb, int tid,
    const __nv_bfloat16* Ah, const __nv_bfloat16* Al,
    const __nv_bfloat16* Bh, const __nv_bfloat16* Bl,
    size_t rsA, size_t rsB)
{
#pragma unroll
    for (int q = 0; q < 4; q++) {
        int idx = q*256 + tid;
        int row = idx >> 3, seg = idx & 7;
        size_t gA = (size_t)row*rsA + seg*8;
        size_t gB = (size_t)row*rsB + seg*8;
        uint32_t so = row*(LDK*2) + seg*16;
        cp16(sb +            so, Ah + gA);
        cp16(sb +   TILE_B + so, Al + gA);
        cp16(sb + 2*TILE_B + so, Bh + gB);
        cp16(sb + 3*TILE_B + so, Bl + gB);
    }
}

// bf16 single-precision chunk (K=64): acc += A.B^T   (128x128 tile geometry)
__device__ __forceinline__ void compute_chunk1(
    const __nv_bfloat16* base, float acc[4][4][4], int wm, int wn, int lid)
{
    const __nv_bfloat16* sA = base;
    const __nv_bfloat16* sB = base + TILE_E;
    int lrow = lid >> 2;
    int lcol2 = (lid & 3) << 1;
#pragma unroll
    for (int ks = 0; ks < 4; ks++) {
        int k0 = ks*16 + lcol2;
        uint32_t a[4][4];
        int rbase = wm*64 + lrow;
#pragma unroll
        for (int im = 0; im < 4; im++) {
            int r = rbase + im*16;
            a[im][0] = *(const uint32_t*)(sA + r*LDK + k0);
            a[im][1] = *(const uint32_t*)(sA + (r+8)*LDK + k0);
            a[im][2] = *(const uint32_t*)(sA + r*LDK + k0 + 8);
            a[im][3] = *(const uint32_t*)(sA + (r+8)*LDK + k0 + 8);
        }
        uint32_t bb[4][2];
        int nbase = wn*32 + lrow;
#pragma unroll
        for (int jn = 0; jn < 4; jn++) {
            int n = nbase + jn*8;
            bb[jn][0] = *(const uint32_t*)(sB + n*LDK + k0);
            bb[jn][1] = *(const uint32_t*)(sB + n*LDK + k0 + 8);
        }
#pragma unroll
        for (int im = 0; im < 4; im++)
#pragma unroll
            for (int jn = 0; jn < 4; jn++)
                mma16816(acc[im][jn], a[im], bb[jn]);
    }
}

// fp8 chunk (K=128): acc += A.B^T via 4 x m16n8k32 ksteps
__device__ __forceinline__ void compute_chunk_fp8(
    const uint8_t* base, float acc[4][4][4], int wm, int wn, int lid)
{
    const uint8_t* sA = base;
    const uint8_t* sB = base + TILE8_B;
    int lrow = lid >> 2;
    int l4 = (lid & 3) << 2;
#pragma unroll
    for (int ks = 0; ks < 4; ks++) {
        int koff = ks*32 + l4;
        uint32_t a[4][4];
        int rbase = wm*64 + lrow;
#pragma unroll
        for (int im = 0; im < 4; im++) {
            int r = rbase + im*16;
            a[im][0] = *(const uint32_t*)(sA + r*LDK8 + koff);
            a[im][1] = *(const uint32_t*)(sA + (r+8)*LDK8 + koff);
            a[im][2] = *(const uint32_t*)(sA + r*LDK8 + koff + 16);
            a[im][3] = *(const uint32_t*)(sA + (r+8)*LDK8 + koff + 16);
        }
        uint32_t bb[4][2];
        int nbase = wn*32 + lrow;
#pragma unroll
        for (int jn = 0; jn < 4; jn++) {
            int n = nbase + jn*8;
            bb[jn][0] = *(const uint32_t*)(sB + n*LDK8 + koff);
            bb[jn][1] = *(const uint32_t*)(sB + n*LDK8 + koff + 16);
        }
#pragma unroll
        for (int im = 0; im < 4; im++)
#pragma unroll
            for (int jn = 0; jn < 4; jn++)
                mma16832f8(acc[im][jn], a[im], bb[jn]);
    }
}

// split-bf16 (3-mma) chunk, 128x128 tile: acc += A.B^T
__device__ __forceinline__ void compute_chunk(
    const __nv_bfloat16* base, float acc[4][4][4], int wm, int wn, int lid)
{
    const __nv_bfloat16* sAh = base;
    const __nv_bfloat16* sAl = base + TILE_E;
    const __nv_bfloat16* sBh = base + 2*TILE_E;
    const __nv_bfloat16* sBl = base + 3*TILE_E;
    int lrow = lid >> 2;
    int lcol2 = (lid & 3) << 1;
#pragma unroll
    for (int ks = 0; ks < 4; ks++) {
        int k0 = ks*16 + lcol2;
        uint32_t ah[4][4], al[4][4];
        int rbase = wm*64 + lrow;
#pragma unroll
        for (int im = 0; im < 4; im++) {
            int r = rbase + im*16;
            ah[im][0] = *(const uint32_t*)(sAh + r*LDK + k0);
            ah[im][1] = *(const uint32_t*)(sAh + (r+8)*LDK + k0);
            ah[im][2] = *(const uint32_t*)(sAh + r*LDK + k0 + 8);
            ah[im][3] = *(const uint32_t*)(sAh + (r+8)*LDK + k0 + 8);
            al[im][0] = *(const uint32_t*)(sAl + r*LDK + k0);
            al[im][1] = *(const uint32_t*)(sAl + (r+8)*LDK + k0);
            al[im][2] = *(const uint32_t*)(sAl + r*LDK + k0 + 8);
            al[im][3] = *(const uint32_t*)(sAl + (r+8)*LDK + k0 + 8);
        }
        uint32_t bh[4][2], bl[4][2];
        int nbase = wn*32 + lrow;
#pragma unroll
        for (int jn = 0; jn < 4; jn++) {
            int n = nbase + jn*8;
            bh[jn][0] = *(const uint32_t*)(sBh + n*LDK + k0);
            bh[jn][1] = *(const uint32_t*)(sBh + n*LDK + k0 + 8);
            bl[jn][0] = *(const uint32_t*)(sBl + n*LDK + k0);
            bl[jn][1] = *(const uint32_t*)(sBl + n*LDK + k0 + 8);
        }
#pragma unroll
        for (int im = 0; im < 4; im++)
#pragma unroll
            for (int jn = 0; jn < 4; jn++) {
                mma16816(acc[im][jn], ah[im], bh[jn]);
                mma16816(acc[im][jn], ah[im], bl[jn]);
                mma16816(acc[im][jn], al[im], bh[jn]);
            }
    }
}

// ---------------------------------------------------------------- FC kernel
__global__ void __launch_bounds__(256) fc_kernel(
    const float* __restrict__ h,
    const float* __restrict__ W1, const float* __restrict__ b1,
    const float* __restrict__ W2, const float* __restrict__ b2)
{
    __shared__ float As[16][64];
    __shared__ float Bs[16][64];
    int t  = threadIdx.x;
    int tx = t & 15, ty = t >> 4;
    int bm = blockIdx.x, bn = blockIdx.y;

    float acc[4][4] = {};
    int ar = t >> 2;
    int kc = (t & 3) << 2;
    int rowA = bm*64 + ar;
    int e    = bn*64 + ar;
    const float* Bptr = (e < 128) ? (W1 + e*128) : (W2 + (e-128)*128);

    for (int kt = 0; kt < 128; kt += 16) {
        float4 av = *(const float4*)(h + (size_t)rowA*128 + kt + kc);
        float4 bv = *(const float4*)(Bptr + kt + kc);
        As[kc+0][ar]=av.x; As[kc+1][ar]=av.y; As[kc+2][ar]=av.z; As[kc+3][ar]=av.w;
        Bs[kc+0][ar]=bv.x; Bs[kc+1][ar]=bv.y; Bs[kc+2][ar]=bv.z; Bs[kc+3][ar]=bv.w;
        __syncthreads();
#pragma unroll
        for (int k = 0; k < 16; k++) {
            float a[4], bb[4];
#pragma unroll
            for (int i = 0; i < 4; i++) a[i]  = As[k][ty*4+i];
#pragma unroll
            for (int j = 0; j < 4; j++) bb[j] = Bs[k][tx*4+j];
#pragma unroll
            for (int i = 0; i < 4; i++)
#pragma unroll
                for (int j = 0; j < 4; j++)
                    acc[i][j] += a[i]*bb[j];
        }
        __syncthreads();
    }

#pragma unroll
    for (int i = 0; i < 4; i++) {
        int r = bm*64 + ty*4 + i;
        int c = r >> 4, b = r & 15;
#pragma unroll
        for (int j = 0; j < 4; j++) {
            int ee = bn*64 + tx*4 + j;
            float bias = (ee < 128) ? b1[ee] : b2[ee-128];
            float v = acc[i][j] + bias;
            v = v > 0.f ? v : 0.f;
            __nv_bfloat16 hi = __float2bfloat16(v);
            __nv_bfloat16 lo = __float2bfloat16(v - __bfloat162float(hi));
            size_t idx = ((size_t)(b*C + c))*D + (ee & 127);
            if (ee < 128) { g_h1hi[idx] = hi; g_h1lo[idx] = lo; }
            else          { g_h2hi[idx] = hi; g_h2lo[idx] = lo; }
        }
    }
}

// ----------------- fused exp of B_t on 128x128 tiles (e4m3 smem tile) -------
#define LDT 132   // byte stride of the e4m3 tile
__global__ void __launch_bounds__(256) esplit_kernel(
    const float* __restrict__ Bt, const int* __restrict__ mask)
{
    __shared__ uint8_t tile[128*LDT];    // quantized raw exp, [x][y]
    __shared__ float scol[128];
    int b  = blockIdx.z;
    int x0 = blockIdx.y * 128;
    int y0 = blockIdx.x * 128;
    int w = threadIdx.x >> 5, lid = threadIdx.x & 31;

    if (threadIdx.x < 128) scol[threadIdx.x] = 0.f;
    __syncthreads();

    int4 my4 = *(const int4*)(mask + b*C + y0 + lid*4);
    float yf0 = my4.x ? 1.f : 0.f, yf1 = my4.y ? 1.f : 0.f;
    float yf2 = my4.z ? 1.f : 0.f, yf3 = my4.w ? 1.f : 0.f;
    uint32_t ymask = (my4.x ? 0xFFu : 0) | (my4.y ? 0xFF00u : 0)
                   | (my4.z ? 0xFF0000u : 0) | (my4.w ? 0xFF000000u : 0);

    float gs0 = 0.f, gs1 = 0.f, gs2 = 0.f, gs3 = 0.f;
#pragma unroll 4
    for (int i = 0; i < 16; i++) {
        int xl = w*16 + i;
        int x = x0 + xl;
        float4 v = *(const float4*)(Bt + (size_t)b*CC + (size_t)x*C + y0 + lid*4);
        float e0 = __expf(v.x), e1 = __expf(v.y), e2 = __expf(v.z), e3 = __expf(v.w);
        float s = e0*yf0 + e1*yf1 + e2*yf2 + e3*yf3;
#pragma unroll
        for (int o = 16; o > 0; o >>= 1) s += __shfl_xor_sync(0xffffffffu, s, o);
        if (lid == 0) atomicAdd(g_sumF + b*C + x, s);
        uint32_t pk =  (uint32_t)to_e4m3(e0)        | ((uint32_t)to_e4m3(e1) << 8)
                    | ((uint32_t)to_e4m3(e2) << 16) | ((uint32_t)to_e4m3(e3) << 24);
        *(uint32_t*)(tile + xl*LDT + lid*4) = pk;
        *(uint32_t*)(g_F8 + (size_t)b*CC + (size_t)x*C + y0 + lid*4) = pk & ymask;
        float mrow = mask[b*C + x] ? 1.f : 0.f;
        gs0 += e0*mrow; gs1 += e1*mrow; gs2 += e2*mrow; gs3 += e3*mrow;
    }
    atomicAdd(&scol[lid*4 + 0], gs0);
    atomicAdd(&scol[lid*4 + 1], gs1);
    atomicAdd(&scol[lid*4 + 2], gs2);
    atomicAdd(&scol[lid*4 + 3], gs3);
    __syncthreads();
    if (threadIdx.x < 128)
        atomicAdd(g_sumG + b*C + y0 + threadIdx.x, scol[threadIdx.x]);

    // pass 2: transposed masked bytes -> GT8 (coalesced uint32 stores)
    int xq = lid*4;
    const int* mk = mask + b*C + x0 + xq;
    uint32_t xmask = (mk[0] ? 0xFFu : 0) | (mk[1] ? 0xFF00u : 0)
                   | (mk[2] ? 0xFF0000u : 0) | (mk[3] ? 0xFF000000u : 0);
#pragma unroll 4
    for (int i = 0; i < 16; i++) {
        int yl = w*16 + i;
        int y = y0 + yl;
        uint32_t pk =  (uint32_t)tile[(xq+0)*LDT + yl]
                    | ((uint32_t)tile[(xq+1)*LDT + yl] << 8)
                    | ((uint32_t)tile[(xq+2)*LDT + yl] << 16)
                    | ((uint32_t)tile[(xq+3)*LDT + yl] << 24);
        *(uint32_t*)(g_GT8 + (size_t)b*CC + (size_t)y*C + x0 + xq) = pk & xmask;
    }
}

// ------------------------------------ hT transpose: h(c,b,d) -> [b][d][c] hi/lo
__global__ void __launch_bounds__(256) ht_transpose_kernel(const float* __restrict__ h)
{
    __shared__ float tileT[32][33];
    int b  = blockIdx.z;
    int c0 = blockIdx.x * 32;
    int d0 = blockIdx.y * 32;
    int tx = threadIdx.x & 31, ty = threadIdx.x >> 5;

#pragma unroll
    for (int r = ty; r < 32; r += 8)
        tileT[r][tx] = h[(size_t)((c0 + r)*16 + b)*128 + d0 + tx];
    __syncthreads();
#pragma unroll
    for (int r = ty; r < 32; r += 8) {
        float x = tileT[tx][r];
        __nv_bfloat16 hi = __float2bfloat16(x);
        __nv_bfloat16 lo = __float2bfloat16(x - __bfloat162float(hi));
        size_t o = (size_t)b*D*C + (size_t)(d0 + r)*C + c0 + tx;
        g_hThi[o] = hi;
        g_hTlo[o] = lo;
    }
}

// --------- folded weight stack + sum zeroing --------------------------------
__global__ void __launch_bounds__(256) wsplit_kernel(
    const float* __restrict__ Wr, const float* __restrict__ Wg)
{
    int idx = blockIdx.x*256 + threadIdx.x;
    if (idx < 3*BATCH*C) {
        if (idx < BATCH*C)          g_sumF[idx] = 0.f;
        else if (idx < 2*BATCH*C)   g_sumG[idx - BATCH*C] = 0.f;
        else                        g_sum2[idx - 2*BATCH*C] = 0.f;
    }
    int n = idx / 384, k = idx % 384;
    const float* W = (n < 128) ? (Wr + n*512) : (Wg + (n-128)*512);
    float x;
    if (k < 128)       x = W[k] + W[384 + k];
    else if (k < 256)  x = W[k] - W[k + 256];     // W1 - W3
    else               x = W[k];
    __nv_bfloat16 hi = __float2bfloat16(x);
    g_Whi[idx] = hi;
    g_Wlo[idx] = __float2bfloat16(x - __bfloat162float(hi));
}

// ============================ B_new GEMM + fused softmax epilogue ===========
__global__ void __launch_bounds__(256, 2) bnew_mma_kernel(
    const float* __restrict__ gamma_p, const int* __restrict__ mask,
    float* __restrict__ out)
{
    extern __shared__ char smc[];
    __shared__ int   sMask[128];
    __shared__ float sRow[128];
    int tid = threadIdx.x, wid = tid >> 5, lid = tid & 31;
    int b = blockIdx.z, it = blockIdx.y, jt = blockIdx.x;
    int wm = wid & 1, wn = wid >> 1;
    uint32_t sb = smem_u32(smc);

    if (tid < 128) { sMask[tid] = mask[b*C + jt*128 + tid]; sRow[tid] = 0.f; }

    float acc[4][4][4] = {};
    float gma = gamma_p[0];
    int lrow = lid >> 2, lcol2 = (lid & 3) << 1;

    auto issue = [&](int c) {
        uint32_t slot = sb + (uint32_t)(c % 3)*BUF2_B;
        if (c < 8) {
            const uint8_t* A  = g_F8  + ((size_t)b*C + (size_t)it*128)*C + (size_t)c*128;
            const uint8_t* Bp = g_GT8 + ((size_t)b*C + (size_t)jt*128)*C + (size_t)c*128;
            issue_fp8_128(slot, tid, A, Bp, C);
        } else {
            int tm = (c - 8) >> 1, kh = (c - 8) & 1;
            const __nv_bfloat16* A1 = (tm < 2)  ? g_h1hi : g_h1lo;
            const __nv_bfloat16* B1 = (tm == 1) ? g_h2lo : g_h2hi;
            issue_single(slot, tid,
                         A1 + ((size_t)b*C + (size_t)it*128)*D + kh*64,
                         B1 + ((size_t)b*C + (size_t)jt*128)*D + kh*64, D);
        }
    };

    issue(0); CP_COMMIT();
    issue(1); CP_COMMIT();
    issue(2); CP_COMMIT();

    for (int c = 0; c < 14; c++) {
        int n = 13 - c; if (n > 2) n = 2;
        switch (n) {
            case 2: CP_WAITN(2); break;
            case 1: CP_WAITN(1); break;
            default: CP_WAITN(0); break;
        }
        __syncthreads();
        if (c == 8) {
            float invR[8], invCv[8];
#pragma unroll
            for (int im = 0; im < 4; im++) {
                int r = it*128 + wm*64 + lrow + im*16;
                invR[2*im]   = gma / g_sumF[b*C + r];
                invR[2*im+1] = gma / g_sumF[b*C + r + 8];
            }
#pragma unroll
            for (int jn = 0; jn < 4; jn++) {
                int cj = jt*128 + wn*32 + lcol2 + jn*8;
                invCv[2*jn]   = 1.0f / g_sumG[b*C + cj];
                invCv[2*jn+1] = 1.0f / g_sumG[b*C + cj + 1];
            }
#pragma unroll
            for (int im = 0; im < 4; im++)
#pragma unroll
                for (int jn = 0; jn < 4; jn++) {
                    acc[im][jn][0] *= invR[2*im]   * invCv[2*jn];
                    acc[im][jn][1] *= invR[2*im]   * invCv[2*jn+1];
                    acc[im][jn][2] *= invR[2*im+1] * invCv[2*jn];
                    acc[im][jn][3] *= invR[2*im+1] * invCv[2*jn+1];
                }
        }
        char* base = smc + (c % 3)*BUF2_B;
        if (c < 8) compute_chunk_fp8((const uint8_t*)base, acc, wm, wn, lid);
        else       compute_chunk1((const __nv_bfloat16*)base, acc, wm, wn, lid);
        __syncthreads();
        if (c + 3 < 14) { issue(c + 3); CP_COMMIT(); }
    }

    // ---- epilogue: diag zero, store fp32, fused masked exp + row sums ----
    int gi0 = it*128 + wm*64 + lrow;
    int gj0 = jt*128 + wn*32 + lcol2;
    float* obase = out + (size_t)b*CC;
#pragma unroll
    for (int im = 0; im < 4; im++) {
        int r = gi0 + im*16;
        float rp0 = 0.f, rp1 = 0.f;
#pragma unroll
        for (int jn = 0; jn < 4; jn++) {
            int cj = gj0 + jn*8;
            int lc = wn*32 + lcol2 + jn*8;
            float2 v0 = make_float2(acc[im][jn][0], acc[im][jn][1]);
            float2 v1 = make_float2(acc[im][jn][2], acc[im][jn][3]);
            if (r == cj)        v0.x = 0.f;
            else if (r == cj+1) v0.y = 0.f;
            if (r+8 == cj)      v1.x = 0.f;
            else if (r+8 == cj+1) v1.y = 0.f;
            *(float2*)(obase + (size_t)r*C + cj)     = v0;
            *(float2*)(obase + (size_t)(r+8)*C + cj) = v1;

            int m0 = sMask[lc], m1 = sMask[lc+1];
            float2 e0 = make_float2(m0 ? __expf(v0.x) : 0.f, m1 ? __expf(v0.y) : 0.f);
            float2 e1 = make_float2(m0 ? __expf(v1.x) : 0.f, m1 ? __expf(v1.y) : 0.f);
            rp0 += e0.x + e0.y;
            rp1 += e1.x + e1.y;
            __nv_bfloat162 h0, l0, h1, l1;
            split2(e0, h0, l0);
            split2(e1, h1, l1);
            size_t o0 = (size_t)b*CC + (size_t)r*C + cj;
            size_t o1 = (size_t)b*CC + (size_t)(r+8)*C + cj;
            *(__nv_bfloat162*)(g_E2hi + o0) = h0;
            *(__nv_bfloat162*)(g_E2lo + o0) = l0;
            *(__nv_bfloat162*)(g_E2hi + o1) = h1;
            *(__nv_bfloat162*)(g_E2lo + o1) = l1;
        }
        atomicAdd(&sRow[wm*64 + lrow + im*16],     rp0);
        atomicAdd(&sRow[wm*64 + lrow + im*16 + 8], rp1);
    }
    __syncthreads();
    if (tid < 128) atomicAdd(g_sum2 + b*C + it*128 + tid, sRow[tid]);
}

// ============================ h_tmp GEMM (M=128) + m' construction ===========
__global__ void __launch_bounds__(256) htmp_mma_kernel(const float* __restrict__ h)
{
    extern __shared__ char smc[];
    __nv_bfloat16* sm = (__nv_bfloat16*)smc;
    int tid = threadIdx.x, wid = tid >> 5, lid = tid & 31;
    int it = blockIdx.x, b = blockIdx.y;
    int wm = wid & 1, wn = wid >> 1;
    uint32_t sb = smem_u32(sm);

    float acc[4][4][4] = {};

    auto issue = [&](int c, int buf) {
        size_t offA = ((size_t)b*C + (size_t)it*128)*C + (size_t)c*64;
        size_t offB = (size_t)b*D*C + (size_t)c*64;
        issue_tiles(sb + buf*BUF4_B, tid,
                    g_E2hi + offA, g_E2lo + offA,
                    g_hThi + offB, g_hTlo + offB, C, C);
    };

    issue(0, 0); CP_COMMIT();
    for (int c = 0; c < 16; c++) {
        if (c + 1 < 16) { issue(c + 1, (c + 1) & 1); CP_COMMIT(); CP_WAITN(1); }
        else CP_WAITN(0);
        __syncthreads();
        compute_chunk(sm + (c & 1)*4*TILE_E, acc, wm, wn, lid);
        __syncthreads();
    }

    int lrow = lid >> 2, lcol2 = (lid & 3) << 1;
    int ci0 = it*128 + wm*64 + lrow;
    int d0  = wn*32 + lcol2;
#pragma unroll
    for (int im = 0; im < 4; im++) {
#pragma unroll
        for (int half = 0; half < 2; half++) {
            int cg = ci0 + im*16 + half*8;
            int r  = cg*16 + b;
            float inv = 1.0f / g_sum2[b*C + cg];
#pragma unroll
            for (int jn = 0; jn < 4; jn++) {
                int dj = d0 + jn*8;
                float2 ht = half ? make_float2(acc[im][jn][2], acc[im][jn][3])
                                 : make_float2(acc[im][jn][0], acc[im][jn][1]);
                ht.x *= inv; ht.y *= inv;
                float2 hv = *(const float2*)(h + (size_t)r*128 + dj);
                float2 seg[3];
                seg[0] = hv;
                seg[1] = ht;
                seg[2] = make_float2(hv.x*ht.x, hv.y*ht.y);
#pragma unroll
                for (int s = 0; s < 3; s++) {
                    __nv_bfloat162 hi, lo;
                    split2(seg[s], hi, lo);
                    size_t o = (size_t)r*384 + s*128 + dj;
                    *(__nv_bfloat162*)(g_mhi + o) = hi;
                    *(__nv_bfloat162*)(g_mlo + o) = lo;
                }
            }
        }
    }
}

// ============================ gate GEMM: z = m' . W'^T =======================
__global__ void __launch_bounds__(256) gate_mma_kernel()
{
    extern __shared__ char smc[];
    __nv_bfloat16* sm = (__nv_bfloat16*)smc;
    int tid = threadIdx.x, wid = tid >> 5, lid = tid & 31;
    int bm = blockIdx.x, half = blockIdx.y;
    int wm = wid & 1, wn = wid >> 1;
    uint32_t sb = smem_u32(sm);

    float acc[4][4][4] = {};

    auto issue = [&](int c, int buf) {
        size_t offA = ((size_t)bm*128)*384 + (size_t)c*64;
        size_t offB = ((size_t)half*128)*384 + (size_t)c*64;
        issue_tiles(sb + buf*BUF4_B, tid,
                    g_mhi + offA, g_mlo + offA,
                    g_Whi + offB, g_Wlo + offB, 384, 384);
    };

    issue(0, 0); CP_COMMIT();
    for (int c = 0; c < 6; c++) {
        if (c + 1 < 6) { issue(c + 1, (c + 1) & 1); CP_COMMIT(); CP_WAITN(1); }
        else CP_WAITN(0);
        __syncthreads();
        compute_chunk(sm + (c & 1)*4*TILE_E, acc, wm, wn, lid);
        __syncthreads();
    }

    int lrow = lid >> 2, lcol2 = (lid & 3) << 1;
    int r0 = bm*128 + wm*64 + lrow;
    int n0 = half*128 + wn*32 + lcol2;
#pragma unroll
    for (int im = 0; im < 4; im++) {
        int r = r0 + im*16;
#pragma unroll
        for (int jn = 0; jn < 4; jn++) {
            int n = n0 + jn*8;
            *(float2*)(g_z + (size_t)r*256 + n)     = make_float2(acc[im][jn][0], acc[im][jn][1]);
            *(float2*)(g_z + (size_t)(r+8)*256 + n) = make_float2(acc[im][jn][2], acc[im][jn][3]);
        }
    }
}

// ------------------------------------------------ combine: o = x*g + (1-g)*h
__global__ void __launch_bounds__(256) combine_kernel(
    const float* __restrict__ h, float* __restrict__ o)
{
    int idx = blockIdx.x*256 + threadIdx.x;
    int r = idx >> 5, q = idx & 31;
    float4 zr = *(const float4*)(g_z + (size_t)r*256 + q*4);
    float4 zg = *(const float4*)(g_z + (size_t)r*256 + 128 + q*4);
    float4 hv = *(const float4*)(h + (size_t)r*128 + q*4);
    float4 ov;
    { float x = fmaxf(zr.x, 0.f), gg = 1.0f/(1.0f + __expf(-zg.x)); ov.x = x*gg + (1.0f-gg)*hv.x; }
    { float x = fmaxf(zr.y, 0.f), gg = 1.0f/(1.0f + __expf(-zg.y)); ov.y = x*gg + (1.0f-gg)*hv.y; }
    { float x = fmaxf(zr.z, 0.f), gg = 1.0f/(1.0f + __expf(-zg.z)); ov.z = x*gg + (1.0f-gg)*hv.z; }
    { float x = fmaxf(zr.w, 0.f), gg = 1.0f/(1.0f + __expf(-zg.w)); ov.w = x*gg + (1.0f-gg)*hv.w; }
    *(float4*)(o + (size_t)r*128 + q*4) = ov;
}

// ---------------------------------------------------------------------------
extern "C" void kernel_launch(void* const* d_in, const int* in_sizes, int n_in,
                              void* d_out, int out_size)
{
    const float* h   = (const float*)d_in[0];
    const int*   hm  = (const int*)  d_in[1];
    const float* Bt  = (const float*)d_in[2];
    const float* W1w = (const float*)d_in[3];
    const float* W1b = (const float*)d_in[4];
    const float* W2w = (const float*)d_in[5];
    const float* W2b = (const float*)d_in[6];
    const float* gam = (const float*)d_in[7];
    const float* Wrw = (const float*)d_in[8];
    const float* Wgw = (const float*)d_in[9];

    float* o_out    = (float*)d_out;
    float* bnew_out = (float*)d_out + (size_t)CB*D;

    const int BNEW_SMEM = 3*BUF2_B;        // 110592 -> 2 CTAs/SM
    const int MMA_SMEM  = 2*BUF4_B;        // 147456
    cudaFuncSetAttribute(bnew_mma_kernel, cudaFuncAttributeMaxDynamicSharedMemorySize, BNEW_SMEM);
    cudaFuncSetAttribute(htmp_mma_kernel, cudaFuncAttributeMaxDynamicSharedMemorySize, MMA_SMEM);
    cudaFuncSetAttribute(gate_mma_kernel, cudaFuncAttributeMaxDynamicSharedMemorySize, MMA_SMEM);

    wsplit_kernel<<<256*384/256, 256>>>(Wrw, Wgw);   // also zeroes sums
    fc_kernel<<<dim3(CB/64, 4), 256>>>(h, W1w, W1b, W2w, W2b);
    ht_transpose_kernel<<<dim3(C/32, D/32, BATCH), 256>>>(h);
    esplit_kernel<<<dim3(8, 8, BATCH), 256>>>(Bt, hm);
    bnew_mma_kernel<<<dim3(C/128, C/128, BATCH), 256, BNEW_SMEM>>>(gam, hm, bnew_out);
    htmp_mma_kernel<<<dim3(C/128, BATCH), 256, MMA_SMEM>>>(h);
    gate_mma_kernel<<<dim3(CB/128, 2), 256, MMA_SMEM>>>();
    combine_kernel<<<CB*32/256, 256>>>(h, o_out);
}

// round 12
// speedup vs baseline: 1.1024x; 1.0464x over previous
#include <cuda_runtime.h>
#include <cuda_bf16.h>
#include <cuda_fp8.h>
#include <math.h>
#include <cstdint>

#define C 1024
#define BATCH 16
#define D 128
#define CB (C*BATCH)
#define CC (C*C)

#define LDK 72                     // padded SMEM row (bf16 elems) -> 144 bytes
#define LDKB 144                   // row stride in bytes (shared by bf16 & fp8)
#define TILE_E (128*LDK)           // elems per 128-row bf16 tile
#define TILE_B (TILE_E*2)          // bytes per 128-row bf16 tile (18432)
#define BUF2_B (2*TILE_B)          // 2-tile slot bytes (36864)
#define BUF4_B (4*TILE_B)          // 4-tile buffer bytes (73728)

#define LDK8 144                   // padded fp8 row (bytes), K=128
#define TILE8_B (128*LDK8)         // 18432 = TILE_B

// ---------------- scratch (static device memory, no runtime allocation) ----
__device__ uint8_t g_F8[BATCH*CC];           // e4m3 exp(B_t)*mask[col]   [b][i][k]
__device__ uint8_t g_GT8[BATCH*CC];          // e4m3 exp(B_t)^T*mask[col] [b][j][k]
__device__ float g_sumF[BATCH*C];
__device__ float g_sumG[BATCH*C];
__device__ float g_sum2[BATCH*C];
__device__ __nv_bfloat16 g_E2hi[BATCH*CC];   // masked exp(B_new) [b][i][j]
__device__ __nv_bfloat16 g_E2lo[BATCH*CC];
__device__ __nv_bfloat16 g_h1hi[CB*D];
__device__ __nv_bfloat16 g_h1lo[CB*D];
__device__ __nv_bfloat16 g_h2hi[CB*D];
__device__ __nv_bfloat16 g_h2lo[CB*D];
__device__ __nv_bfloat16 g_hThi[BATCH*D*C];  // [b][d][c]
__device__ __nv_bfloat16 g_hTlo[BATCH*D*C];
__device__ __nv_bfloat16 g_mhi[(size_t)CB*384]; // m' = [h, ht, h*ht]
__device__ __nv_bfloat16 g_mlo[(size_t)CB*384];
__device__ __nv_bfloat16 g_Whi[256*384];
__device__ __nv_bfloat16 g_Wlo[256*384];
__device__ float g_z[(size_t)CB*256];

// ----------------------------------------------------------------- helpers
__device__ __forceinline__ uint32_t smem_u32(const void* p) {
    uint32_t a;
    asm("{ .reg .u64 t; cvta.to.shared.u64 t, %1; cvt.u32.u64 %0, t; }" : "=r"(a) : "l"(p));
    return a;
}
__device__ __forceinline__ void mma16816(float* c, const uint32_t* a, const uint32_t* b) {
    asm volatile(
        "mma.sync.aligned.m16n8k16.row.col.f32.bf16.bf16.f32 "
        "{%0,%1,%2,%3}, {%4,%5,%6,%7}, {%8,%9}, {%0,%1,%2,%3};"
        : "+f"(c[0]), "+f"(c[1]), "+f"(c[2]), "+f"(c[3])
        : "r"(a[0]), "r"(a[1]), "r"(a[2]), "r"(a[3]), "r"(b[0]), "r"(b[1]));
}
__device__ __forceinline__ void mma16832f8(float* c, const uint32_t* a, const uint32_t* b) {
    asm volatile(
        "mma.sync.aligned.m16n8k32.row.col.f32.e4m3.e4m3.f32 "
        "{%0,%1,%2,%3}, {%4,%5,%6,%7}, {%8,%9}, {%0,%1,%2,%3};"
        : "+f"(c[0]), "+f"(c[1]), "+f"(c[2]), "+f"(c[3])
        : "r"(a[0]), "r"(a[1]), "r"(a[2]), "r"(a[3]), "r"(b[0]), "r"(b[1]));
}
__device__ __forceinline__ void ldsm4(uint32_t a, uint32_t* r) {
    asm volatile("ldmatrix.sync.aligned.m8n8.x4.shared.b16 {%0,%1,%2,%3}, [%4];"
        : "=r"(r[0]), "=r"(r[1]), "=r"(r[2]), "=r"(r[3]) : "r"(a));
}
__device__ __forceinline__ void cp16(uint32_t s, const void* g) {
    asm volatile("cp.async.ca.shared.global [%0], [%1], 16;" :: "r"(s), "l"(g));
}
#define CP_COMMIT() asm volatile("cp.async.commit_group;" ::: "memory")
#define CP_WAITN(n) asm volatile("cp.async.wait_group %0;" :: "n"(n) : "memory")

__device__ __forceinline__ void split2(float2 v, __nv_bfloat162& hi, __nv_bfloat162& lo) {
    hi.x = __float2bfloat16(v.x); lo.x = __float2bfloat16(v.x - __bfloat162float(hi.x));
    hi.y = __float2bfloat16(v.y); lo.y = __float2bfloat16(v.y - __bfloat162float(hi.y));
}
__device__ __forceinline__ uint8_t to_e4m3(float x) {
    return (uint8_t)__nv_cvt_float_to_fp8(x, __NV_SATFINITE, __NV_E4M3);
}

// ldmatrix per-lane address offsets (row stride LDKB=144 for all tiles):
// A-side x4: m0=(r0..7,+0B) m1=(r8..15,+0B) m2=(r0..7,+16B) m3=(r8..15,+16B)
__device__ __forceinline__ uint32_t a_lane_off(int warp_row, int lid) {
    int mi = lid >> 3, l7 = lid & 7;
    return (uint32_t)((warp_row + (mi & 1)*8 + l7)*LDKB + (mi >> 1)*16);
}
// B-side x4 (covers 2 jn): m0=(n0..7,+0B) m1=(n0..7,+16B) m2=(n8..15,+0B) m3=(n8..15,+16B)
__device__ __forceinline__ uint32_t b_lane_off(int warp_col, int lid) {
    int mi = lid >> 3, l7 = lid & 7;
    return (uint32_t)((warp_col + (mi >> 1)*8 + l7)*LDKB + (mi & 1)*16);
}

// load one 2-tile bf16 chunk (A, B), 128 rows x 64 bf16 each
__device__ __forceinline__ void issue_single(
    uint32_t sb, int tid,
    const __nv_bfloat16* A, const __nv_bfloat16* Bp, size_t rs)
{
#pragma unroll
    for (int q = 0; q < 4; q++) {
        int idx = q*256 + tid;
        int row = idx >> 3, seg = idx & 7;
        size_t g = (size_t)row*rs + seg*8;
        uint32_t so = row*LDKB + seg*16;
        cp16(sb +          so, A  + g);
        cp16(sb + TILE_B + so, Bp + g);
    }
}

// load one 2-tile fp8 chunk (A, B), 128 rows x 128 e4m3 bytes each (K=128)
__device__ __forceinline__ void issue_fp8_128(
    uint32_t sb, int tid, const uint8_t* A, const uint8_t* Bp, size_t rs)
{
#pragma unroll
    for (int q = 0; q < 8; q++) {
        int idx = q*256 + tid;
        int tile = idx >> 10;
        int row  = (idx >> 3) & 127;
        int seg  = idx & 7;
        const uint8_t* src = tile ? Bp : A;
        cp16(sb + tile*TILE8_B + row*LDK8 + seg*16,
             src + (size_t)row*rs + seg*16);
    }
}

// load one 4-tile bf16 chunk (Ah, Al, Bh, Bl), 128 rows each
__device__ __forceinline__ void issue_tiles(
    uint32_t sb, int tid,
    const __nv_bfloat16* Ah, const __nv_bfloat16* Al,
    const __nv_bfloat16* Bh, const __nv_bfloat16* Bl,
    size_t rsA, size_t rsB)
{
#pragma unroll
    for (int q = 0; q < 4; q++) {
        int idx = q*256 + tid;
        int row = idx >> 3, seg = idx & 7;
        size_t gA = (size_t)row*rsA + seg*8;
        size_t gB = (size_t)row*rsB + seg*8;
        uint32_t so = row*LDKB + seg*16;
        cp16(sb +            so, Ah + gA);
        cp16(sb +   TILE_B + so, Al + gA);
        cp16(sb + 2*TILE_B + so, Bh + gB);
        cp16(sb + 3*TILE_B + so, Bl + gB);
    }
}

// bf16 single-precision chunk (K=64), ldmatrix operands
__device__ __forceinline__ void compute_chunk1(
    uint32_t sA, uint32_t sB, float acc[4][4][4], int wm, int wn, int lid)
{
    uint32_t aoff = sA + a_lane_off(wm*64, lid);
    uint32_t boff = sB + b_lane_off(wn*32, lid);
#pragma unroll
    for (int ks = 0; ks < 4; ks++) {
        uint32_t a[4][4], bb[2][4];
#pragma unroll
        for (int im = 0; im < 4; im++) ldsm4(aoff + im*(16*LDKB) + ks*32, a[im]);
#pragma unroll
        for (int p = 0; p < 2; p++)  ldsm4(boff + p*(16*LDKB) + ks*32, bb[p]);
#pragma unroll
        for (int im = 0; im < 4; im++)
#pragma unroll
            for (int jn = 0; jn < 4; jn++)
                mma16816(acc[im][jn], a[im], &bb[jn>>1][(jn&1)*2]);
    }
}

// fp8 chunk (K=128): 4 x m16n8k32 ksteps, ldmatrix operands
__device__ __forceinline__ void compute_chunk_fp8(
    uint32_t sA, uint32_t sB, float acc[4][4][4], int wm, int wn, int lid)
{
    uint32_t aoff = sA + a_lane_off(wm*64, lid);
    uint32_t boff = sB + b_lane_off(wn*32, lid);
#pragma unroll
    for (int ks = 0; ks < 4; ks++) {
        uint32_t a[4][4], bb[2][4];
#pragma unroll
        for (int im = 0; im < 4; im++) ldsm4(aoff + im*(16*LDKB) + ks*32, a[im]);
#pragma unroll
        for (int p = 0; p < 2; p++)  ldsm4(boff + p*(16*LDKB) + ks*32, bb[p]);
#pragma unroll
        for (int im = 0; im < 4; im++)
#pragma unroll
            for (int jn = 0; jn < 4; jn++)
                mma16832f8(acc[im][jn], a[im], &bb[jn>>1][(jn&1)*2]);
    }
}

// split-bf16 (3-mma) chunk, 128x128 tile, ldmatrix operands
__device__ __forceinline__ void compute_chunk(
    uint32_t base, float acc[4][4][4], int wm, int wn, int lid)
{
    uint32_t aoffh = base +            a_lane_off(wm*64, lid);
    uint32_t aoffl = base +   TILE_B + a_lane_off(wm*64, lid);
    uint32_t boffh = base + 2*TILE_B + b_lane_off(wn*32, lid);
    uint32_t boffl = base + 3*TILE_B + b_lane_off(wn*32, lid);
#pragma unroll
    for (int ks = 0; ks < 4; ks++) {
        uint32_t ah[4][4], al[4][4], bh[2][4], bl[2][4];
#pragma unroll
        for (int im = 0; im < 4; im++) {
            ldsm4(aoffh + im*(16*LDKB) + ks*32, ah[im]);
            ldsm4(aoffl + im*(16*LDKB) + ks*32, al[im]);
        }
#pragma unroll
        for (int p = 0; p < 2; p++) {
            ldsm4(boffh + p*(16*LDKB) + ks*32, bh[p]);
            ldsm4(boffl + p*(16*LDKB) + ks*32, bl[p]);
        }
#pragma unroll
        for (int im = 0; im < 4; im++)
#pragma unroll
            for (int jn = 0; jn < 4; jn++) {
                mma16816(acc[im][jn], ah[im], &bh[jn>>1][(jn&1)*2]);
                mma16816(acc[im][jn], ah[im], &bl[jn>>1][(jn&1)*2]);
                mma16816(acc[im][jn], al[im], &bh[jn>>1][(jn&1)*2]);
            }
    }
}

// ---------------------------------------------------------------- FC kernel
__global__ void __launch_bounds__(256) fc_kernel(
    const float* __restrict__ h,
    const float* __restrict__ W1, const float* __restrict__ b1,
    const float* __restrict__ W2, const float* __restrict__ b2)
{
    __shared__ float As[16][64];
    __shared__ float Bs[16][64];
    int t  = threadIdx.x;
    int tx = t & 15, ty = t >> 4;
    int bm = blockIdx.x, bn = blockIdx.y;

    float acc[4][4] = {};
    int ar = t >> 2;
    int kc = (t & 3) << 2;
    int rowA = bm*64 + ar;
    int e    = bn*64 + ar;
    const float* Bptr = (e < 128) ? (W1 + e*128) : (W2 + (e-128)*128);

    for (int kt = 0; kt < 128; kt += 16) {
        float4 av = *(const float4*)(h + (size_t)rowA*128 + kt + kc);
        float4 bv = *(const float4*)(Bptr + kt + kc);
        As[kc+0][ar]=av.x; As[kc+1][ar]=av.y; As[kc+2][ar]=av.z; As[kc+3][ar]=av.w;
        Bs[kc+0][ar]=bv.x; Bs[kc+1][ar]=bv.y; Bs[kc+2][ar]=bv.z; Bs[kc+3][ar]=bv.w;
        __syncthreads();
#pragma unroll
        for (int k = 0; k < 16; k++) {
            float a[4], bb[4];
#pragma unroll
            for (int i = 0; i < 4; i++) a[i]  = As[k][ty*4+i];
#pragma unroll
            for (int j = 0; j < 4; j++) bb[j] = Bs[k][tx*4+j];
#pragma unroll
            for (int i = 0; i < 4; i++)
#pragma unroll
                for (int j = 0; j < 4; j++)
                    acc[i][j] += a[i]*bb[j];
        }
        __syncthreads();
    }

#pragma unroll
    for (int i = 0; i < 4; i++) {
        int r = bm*64 + ty*4 + i;
        int c = r >> 4, b = r & 15;
#pragma unroll
        for (int j = 0; j < 4; j++) {
            int ee = bn*64 + tx*4 + j;
            float bias = (ee < 128) ? b1[ee] : b2[ee-128];
            float v = acc[i][j] + bias;
            v = v > 0.f ? v : 0.f;
            __nv_bfloat16 hi = __float2bfloat16(v);
            __nv_bfloat16 lo = __float2bfloat16(v - __bfloat162float(hi));
            size_t idx = ((size_t)(b*C + c))*D + (ee & 127);
            if (ee < 128) { g_h1hi[idx] = hi; g_h1lo[idx] = lo; }
            else          { g_h2hi[idx] = hi; g_h2lo[idx] = lo; }
        }
    }
}

// ----------------- fused exp of B_t on 128x128 tiles (e4m3 smem tile) -------
#define LDT 132   // byte stride of the e4m3 tile
__global__ void __launch_bounds__(256) esplit_kernel(
    const float* __restrict__ Bt, const int* __restrict__ mask)
{
    __shared__ uint8_t tile[128*LDT];
    __shared__ float scol[128];
    int b  = blockIdx.z;
    int x0 = blockIdx.y * 128;
    int y0 = blockIdx.x * 128;
    int w = threadIdx.x >> 5, lid = threadIdx.x & 31;

    if (threadIdx.x < 128) scol[threadIdx.x] = 0.f;
    __syncthreads();

    int4 my4 = *(const int4*)(mask + b*C + y0 + lid*4);
    float yf0 = my4.x ? 1.f : 0.f, yf1 = my4.y ? 1.f : 0.f;
    float yf2 = my4.z ? 1.f : 0.f, yf3 = my4.w ? 1.f : 0.f;
    uint32_t ymask = (my4.x ? 0xFFu : 0) | (my4.y ? 0xFF00u : 0)
                   | (my4.z ? 0xFF0000u : 0) | (my4.w ? 0xFF000000u : 0);

    float gs0 = 0.f, gs1 = 0.f, gs2 = 0.f, gs3 = 0.f;
#pragma unroll 4
    for (int i = 0; i < 16; i++) {
        int xl = w*16 + i;
        int x = x0 + xl;
        float4 v = *(const float4*)(Bt + (size_t)b*CC + (size_t)x*C + y0 + lid*4);
        float e0 = __expf(v.x), e1 = __expf(v.y), e2 = __expf(v.z), e3 = __expf(v.w);
        float s = e0*yf0 + e1*yf1 + e2*yf2 + e3*yf3;
#pragma unroll
        for (int o = 16; o > 0; o >>= 1) s += __shfl_xor_sync(0xffffffffu, s, o);
        if (lid == 0) atomicAdd(g_sumF + b*C + x, s);
        uint32_t pk =  (uint32_t)to_e4m3(e0)        | ((uint32_t)to_e4m3(e1) << 8)
                    | ((uint32_t)to_e4m3(e2) << 16) | ((uint32_t)to_e4m3(e3) << 24);
        *(uint32_t*)(tile + xl*LDT + lid*4) = pk;
        *(uint32_t*)(g_F8 + (size_t)b*CC + (size_t)x*C + y0 + lid*4) = pk & ymask;
        float mrow = mask[b*C + x] ? 1.f : 0.f;
        gs0 += e0*mrow; gs1 += e1*mrow; gs2 += e2*mrow; gs3 += e3*mrow;
    }
    atomicAdd(&scol[lid*4 + 0], gs0);
    atomicAdd(&scol[lid*4 + 1], gs1);
    atomicAdd(&scol[lid*4 + 2], gs2);
    atomicAdd(&scol[lid*4 + 3], gs3);
    __syncthreads();
    if (threadIdx.x < 128)
        atomicAdd(g_sumG + b*C + y0 + threadIdx.x, scol[threadIdx.x]);

    int xq = lid*4;
    const int* mk = mask + b*C + x0 + xq;
    uint32_t xmask = (mk[0] ? 0xFFu : 0) | (mk[1] ? 0xFF00u : 0)
                   | (mk[2] ? 0xFF0000u : 0) | (mk[3] ? 0xFF000000u : 0);
#pragma unroll 4
    for (int i = 0; i < 16; i++) {
        int yl = w*16 + i;
        int y = y0 + yl;
        uint32_t pk =  (uint32_t)tile[(xq+0)*LDT + yl]
                    | ((uint32_t)tile[(xq+1)*LDT + yl] << 8)
                    | ((uint32_t)tile[(xq+2)*LDT + yl] << 16)
                    | ((uint32_t)tile[(xq+3)*LDT + yl] << 24);
        *(uint32_t*)(g_GT8 + (size_t)b*CC + (size_t)y*C + x0 + xq) = pk & xmask;
    }
}

// ------------------------------------ hT transpose: h(c,b,d) -> [b][d][c] hi/lo
__global__ void __launch_bounds__(256) ht_transpose_kernel(const float* __restrict__ h)
{
    __shared__ float tileT[32][33];
    int b  = blockIdx.z;
    int c0 = blockIdx.x * 32;
    int d0 = blockIdx.y * 32;
    int tx = threadIdx.x & 31, ty = threadIdx.x >> 5;

#pragma unroll
    for (int r = ty; r < 32; r += 8)
        tileT[r][tx] = h[(size_t)((c0 + r)*16 + b)*128 + d0 + tx];
    __syncthreads();
#pragma unroll
    for (int r = ty; r < 32; r += 8) {
        float x = tileT[tx][r];
        __nv_bfloat16 hi = __float2bfloat16(x);
        __nv_bfloat16 lo = __float2bfloat16(x - __bfloat162float(hi));
        size_t o = (size_t)b*D*C + (size_t)(d0 + r)*C + c0 + tx;
        g_hThi[o] = hi;
        g_hTlo[o] = lo;
    }
}

// --------- folded weight stack + sum zeroing --------------------------------
__global__ void __launch_bounds__(256) wsplit_kernel(
    const float* __restrict__ Wr, const float* __restrict__ Wg)
{
    int idx = blockIdx.x*256 + threadIdx.x;
    if (idx < 3*BATCH*C) {
        if (idx < BATCH*C)          g_sumF[idx] = 0.f;
        else if (idx < 2*BATCH*C)   g_sumG[idx - BATCH*C] = 0.f;
        else                        g_sum2[idx - 2*BATCH*C] = 0.f;
    }
    int n = idx / 384, k = idx % 384;
    const float* W = (n < 128) ? (Wr + n*512) : (Wg + (n-128)*512);
    float x;
    if (k < 128)       x = W[k] + W[384 + k];
    else if (k < 256)  x = W[k] - W[k + 256];     // W1 - W3
    else               x = W[k];
    __nv_bfloat16 hi = __float2bfloat16(x);
    g_Whi[idx] = hi;
    g_Wlo[idx] = __float2bfloat16(x - __bfloat162float(hi));
}

// ============================ B_new GEMM + fused softmax epilogue ===========
__global__ void __launch_bounds__(256, 2) bnew_mma_kernel(
    const float* __restrict__ gamma_p, const int* __restrict__ mask,
    float* __restrict__ out)
{
    extern __shared__ char smc[];
    __shared__ int   sMask[128];
    __shared__ float sRow[128];
    int tid = threadIdx.x, wid = tid >> 5, lid = tid & 31;
    int b = blockIdx.z, it = blockIdx.y, jt = blockIdx.x;
    int wm = wid & 1, wn = wid >> 1;
    uint32_t sb = smem_u32(smc);

    if (tid < 128) { sMask[tid] = mask[b*C + jt*128 + tid]; sRow[tid] = 0.f; }

    float acc[4][4][4] = {};
    float gma = gamma_p[0];
    int lrow = lid >> 2, lcol2 = (lid & 3) << 1;

    auto issue = [&](int c) {
        uint32_t slot = sb + (uint32_t)(c % 3)*BUF2_B;
        if (c < 8) {
            const uint8_t* A  = g_F8  + ((size_t)b*C + (size_t)it*128)*C + (size_t)c*128;
            const uint8_t* Bp = g_GT8 + ((size_t)b*C + (size_t)jt*128)*C + (size_t)c*128;
            issue_fp8_128(slot, tid, A, Bp, C);
        } else {
            int tm = (c - 8) >> 1, kh = (c - 8) & 1;
            const __nv_bfloat16* A1 = (tm < 2)  ? g_h1hi : g_h1lo;
            const __nv_bfloat16* B1 = (tm == 1) ? g_h2lo : g_h2hi;
            issue_single(slot, tid,
                         A1 + ((size_t)b*C + (size_t)it*128)*D + kh*64,
                         B1 + ((size_t)b*C + (size_t)jt*128)*D + kh*64, D);
        }
    };

    issue(0); CP_COMMIT();
    issue(1); CP_COMMIT();
    issue(2); CP_COMMIT();

    for (int c = 0; c < 14; c++) {
        int n = 13 - c; if (n > 2) n = 2;
        switch (n) {
            case 2: CP_WAITN(2); break;
            case 1: CP_WAITN(1); break;
            default: CP_WAITN(0); break;
        }
        __syncthreads();
        if (c == 8) {
            float invR[8], invCv[8];
#pragma unroll
            for (int im = 0; im < 4; im++) {
                int r = it*128 + wm*64 + lrow + im*16;
                invR[2*im]   = gma / g_sumF[b*C + r];
                invR[2*im+1] = gma / g_sumF[b*C + r + 8];
            }
#pragma unroll
            for (int jn = 0; jn < 4; jn++) {
                int cj = jt*128 + wn*32 + lcol2 + jn*8;
                invCv[2*jn]   = 1.0f / g_sumG[b*C + cj];
                invCv[2*jn+1] = 1.0f / g_sumG[b*C + cj + 1];
            }
#pragma unroll
            for (int im = 0; im < 4; im++)
#pragma unroll
                for (int jn = 0; jn < 4; jn++) {
                    acc[im][jn][0] *= invR[2*im]   * invCv[2*jn];
                    acc[im][jn][1] *= invR[2*im]   * invCv[2*jn+1];
                    acc[im][jn][2] *= invR[2*im+1] * invCv[2*jn];
                    acc[im][jn][3] *= invR[2*im+1] * invCv[2*jn+1];
                }
        }
        uint32_t base = sb + (uint32_t)(c % 3)*BUF2_B;
        if (c < 8) compute_chunk_fp8(base, base + TILE8_B, acc, wm, wn, lid);
        else       compute_chunk1(base, base + TILE_B, acc, wm, wn, lid);
        __syncthreads();
        if (c + 3 < 14) { issue(c + 3); CP_COMMIT(); }
    }

    // ---- epilogue: diag zero, store fp32, fused masked exp + row sums ----
    int gi0 = it*128 + wm*64 + lrow;
    int gj0 = jt*128 + wn*32 + lcol2;
    float* obase = out + (size_t)b*CC;
#pragma unroll
    for (int im = 0; im < 4; im++) {
        int r = gi0 + im*16;
        float rp0 = 0.f, rp1 = 0.f;
#pragma unroll
        for (int jn = 0; jn < 4; jn++) {
            int cj = gj0 + jn*8;
            int lc = wn*32 + lcol2 + jn*8;
            float2 v0 = make_float2(acc[im][jn][0], acc[im][jn][1]);
            float2 v1 = make_float2(acc[im][jn][2], acc[im][jn][3]);
            if (r == cj)        v0.x = 0.f;
            else if (r == cj+1) v0.y = 0.f;
            if (r+8 == cj)      v1.x = 0.f;
            else if (r+8 == cj+1) v1.y = 0.f;
            *(float2*)(obase + (size_t)r*C + cj)     = v0;
            *(float2*)(obase + (size_t)(r+8)*C + cj) = v1;

            int m0 = sMask[lc], m1 = sMask[lc+1];
            float2 e0 = make_float2(m0 ? __expf(v0.x) : 0.f, m1 ? __expf(v0.y) : 0.f);
            float2 e1 = make_float2(m0 ? __expf(v1.x) : 0.f, m1 ? __expf(v1.y) : 0.f);
            rp0 += e0.x + e0.y;
            rp1 += e1.x + e1.y;
            __nv_bfloat162 h0, l0, h1, l1;
            split2(e0, h0, l0);
            split2(e1, h1, l1);
            size_t o0 = (size_t)b*CC + (size_t)r*C + cj;
            size_t o1 = (size_t)b*CC + (size_t)(r+8)*C + cj;
            *(__nv_bfloat162*)(g_E2hi + o0) = h0;
            *(__nv_bfloat162*)(g_E2lo + o0) = l0;
            *(__nv_bfloat162*)(g_E2hi + o1) = h1;
            *(__nv_bfloat162*)(g_E2lo + o1) = l1;
        }
        atomicAdd(&sRow[wm*64 + lrow + im*16],     rp0);
        atomicAdd(&sRow[wm*64 + lrow + im*16 + 8], rp1);
    }
    __syncthreads();
    if (tid < 128) atomicAdd(g_sum2 + b*C + it*128 + tid, sRow[tid]);
}

// ============================ h_tmp GEMM (M=128) + m' construction ===========
__global__ void __launch_bounds__(256) htmp_mma_kernel(const float* __restrict__ h)
{
    extern __shared__ char smc[];
    int tid = threadIdx.x, wid = tid >> 5, lid = tid & 31;
    int it = blockIdx.x, b = blockIdx.y;
    int wm = wid & 1, wn = wid >> 1;
    uint32_t sb = smem_u32(smc);

    float acc[4][4][4] = {};

    auto issue = [&](int c, int buf) {
        size_t offA = ((size_t)b*C + (size_t)it*128)*C + (size_t)c*64;
        size_t offB = (size_t)b*D*C + (size_t)c*64;
        issue_tiles(sb + buf*BUF4_B, tid,
                    g_E2hi + offA, g_E2lo + offA,
                    g_hThi + offB, g_hTlo + offB, C, C);
    };

    issue(0, 0); CP_COMMIT();
    for (int c = 0; c < 16; c++) {
        if (c + 1 < 16) { issue(c + 1, (c + 1) & 1); CP_COMMIT(); CP_WAITN(1); }
        else CP_WAITN(0);
        __syncthreads();
        compute_chunk(sb + (uint32_t)(c & 1)*BUF4_B, acc, wm, wn, lid);
        __syncthreads();
    }

    int lrow = lid >> 2, lcol2 = (lid & 3) << 1;
    int ci0 = it*128 + wm*64 + lrow;
    int d0  = wn*32 + lcol2;
#pragma unroll
    for (int im = 0; im < 4; im++) {
#pragma unroll
        for (int half = 0; half < 2; half++) {
            int cg = ci0 + im*16 + half*8;
            int r  = cg*16 + b;
            float inv = 1.0f / g_sum2[b*C + cg];
#pragma unroll
            for (int jn = 0; jn < 4; jn++) {
                int dj = d0 + jn*8;
                float2 ht = half ? make_float2(acc[im][jn][2], acc[im][jn][3])
                                 : make_float2(acc[im][jn][0], acc[im][jn][1]);
                ht.x *= inv; ht.y *= inv;
                float2 hv = *(const float2*)(h + (size_t)r*128 + dj);
                float2 seg[3];
                seg[0] = hv;
                seg[1] = ht;
                seg[2] = make_float2(hv.x*ht.x, hv.y*ht.y);
#pragma unroll
                for (int s = 0; s < 3; s++) {
                    __nv_bfloat162 hi, lo;
                    split2(seg[s], hi, lo);
                    size_t o = (size_t)r*384 + s*128 + dj;
                    *(__nv_bfloat162*)(g_mhi + o) = hi;
                    *(__nv_bfloat162*)(g_mlo + o) = lo;
                }
            }
        }
    }
}

// ============================ gate GEMM: z = m' . W'^T =======================
__global__ void __launch_bounds__(256) gate_mma_kernel()
{
    extern __shared__ char smc[];
    int tid = threadIdx.x, wid = tid >> 5, lid = tid & 31;
    int bm = blockIdx.x, half = blockIdx.y;
    int wm = wid & 1, wn = wid >> 1;
    uint32_t sb = smem_u32(smc);

    float acc[4][4][4] = {};

    auto issue = [&](int c, int buf) {
        size_t offA = ((size_t)bm*128)*384 + (size_t)c*64;
        size_t offB = ((size_t)half*128)*384 + (size_t)c*64;
        issue_tiles(sb + buf*BUF4_B, tid,
                    g_mhi + offA, g_mlo + offA,
                    g_Whi + offB, g_Wlo + offB, 384, 384);
    };

    issue(0, 0); CP_COMMIT();
    for (int c = 0; c < 6; c++) {
        if (c + 1 < 6) { issue(c + 1, (c + 1) & 1); CP_COMMIT(); CP_WAITN(1); }
        else CP_WAITN(0);
        __syncthreads();
        compute_chunk(sb + (uint32_t)(c & 1)*BUF4_B, acc, wm, wn, lid);
        __syncthreads();
    }

    int lrow = lid >> 2, lcol2 = (lid & 3) << 1;
    int r0 = bm*128 + wm*64 + lrow;
    int n0 = half*128 + wn*32 + lcol2;
#pragma unroll
    for (int im = 0; im < 4; im++) {
        int r = r0 + im*16;
#pragma unroll
        for (int jn = 0; jn < 4; jn++) {
            int n = n0 + jn*8;
            *(float2*)(g_z + (size_t)r*256 + n)     = make_float2(acc[im][jn][0], acc[im][jn][1]);
            *(float2*)(g_z + (size_t)(r+8)*256 + n) = make_float2(acc[im][jn][2], acc[im][jn][3]);
        }
    }
}

// ------------------------------------------------ combine: o = x*g + (1-g)*h
__global__ void __launch_bounds__(256) combine_kernel(
    const float* __restrict__ h, float* __restrict__ o)
{
    int idx = blockIdx.x*256 + threadIdx.x;
    int r = idx >> 5, q = idx & 31;
    float4 zr = *(const float4*)(g_z + (size_t)r*256 + q*4);
    float4 zg = *(const float4*)(g_z + (size_t)r*256 + 128 + q*4);
    float4 hv = *(const float4*)(h + (size_t)r*128 + q*4);
    float4 ov;
    { float x = fmaxf(zr.x, 0.f), gg = 1.0f/(1.0f + __expf(-zg.x)); ov.x = x*gg + (1.0f-gg)*hv.x; }
    { float x = fmaxf(zr.y, 0.f), gg = 1.0f/(1.0f + __expf(-zg.y)); ov.y = x*gg + (1.0f-gg)*hv.y; }
    { float x = fmaxf(zr.z, 0.f), gg = 1.0f/(1.0f + __expf(-zg.z)); ov.z = x*gg + (1.0f-gg)*hv.z; }
    { float x = fmaxf(zr.w, 0.f), gg = 1.0f/(1.0f + __expf(-zg.w)); ov.w = x*gg + (1.0f-gg)*hv.w; }
    *(float4*)(o + (size_t)r*128 + q*4) = ov;
}

// ---------------------------------------------------------------------------
extern "C" void kernel_launch(void* const* d_in, const int* in_sizes, int n_in,
                              void* d_out, int out_size)
{
    const float* h   = (const float*)d_in[0];
    const int*   hm  = (const int*)  d_in[1];
    const float* Bt  = (const float*)d_in[2];
    const float* W1w = (const float*)d_in[3];
    const float* W1b = (const float*)d_in[4];
    const float* W2w = (const float*)d_in[5];
    const float* W2b = (const float*)d_in[6];
    const float* gam = (const float*)d_in[7];
    const float* Wrw = (const float*)d_in[8];
    const float* Wgw = (const float*)d_in[9];

    float* o_out    = (float*)d_out;
    float* bnew_out = (float*)d_out + (size_t)CB*D;

    const int BNEW_SMEM = 3*BUF2_B;        // 110592 -> 2 CTAs/SM
    const int MMA_SMEM  = 2*BUF4_B;        // 147456
    cudaFuncSetAttribute(bnew_mma_kernel, cudaFuncAttributeMaxDynamicSharedMemorySize, BNEW_SMEM);
    cudaFuncSetAttribute(htmp_mma_kernel, cudaFuncAttributeMaxDynamicSharedMemorySize, MMA_SMEM);
    cudaFuncSetAttribute(gate_mma_kernel, cudaFuncAttributeMaxDynamicSharedMemorySize, MMA_SMEM);

    wsplit_kernel<<<256*384/256, 256>>>(Wrw, Wgw);   // also zeroes sums
    fc_kernel<<<dim3(CB/64, 4), 256>>>(h, W1w, W1b, W2w, W2b);
    ht_transpose_kernel<<<dim3(C/32, D/32, BATCH), 256>>>(h);
    esplit_kernel<<<dim3(8, 8, BATCH), 256>>>(Bt, hm);
    bnew_mma_kernel<<<dim3(C/128, C/128, BATCH), 256, BNEW_SMEM>>>(gam, hm, bnew_out);
    htmp_mma_kernel<<<dim3(C/128, BATCH), 256, MMA_SMEM>>>(h);
    gate_mma_kernel<<<dim3(CB/128, 2), 256, MMA_SMEM>>>();
    combine_kernel<<<CB*32/256, 256>>>(h, o_out);
}

// round 13
// speedup vs baseline: 1.1316x; 1.0265x over previous
#include <cuda_runtime.h>
#include <cuda_bf16.h>
#include <cuda_fp8.h>
#include <math.h>
#include <cstdint>

#define C 1024
#define BATCH 16
#define D 128
#define CB (C*BATCH)
#define CC (C*C)

#define LDK 72                     // padded SMEM row (bf16 elems) -> 144 bytes
#define LDKB 144                   // row stride in bytes (shared by bf16 & fp8)
#define TILE_E (128*LDK)           // elems per 128-row bf16 tile
#define TILE_B (TILE_E*2)          // bytes per 128-row bf16 tile (18432)
#define BUF2_B (2*TILE_B)          // 2-tile slot bytes (36864)
#define BUF4_B (4*TILE_B)          // 4-tile slot bytes (73728)

#define LDK8 144                   // padded fp8 row (bytes), K=128
#define TILE8_B (128*LDK8)         // 18432 = TILE_B

// ---------------- scratch (static device memory, no runtime allocation) ----
__device__ uint8_t g_F8[BATCH*CC];           // e4m3 exp(B_t)*mask[col]   [b][i][k]
__device__ uint8_t g_GT8[BATCH*CC];          // e4m3 exp(B_t)^T*mask[col] [b][j][k]
__device__ float g_sumF[BATCH*C];
__device__ float g_sumG[BATCH*C];
__device__ float g_sum2[BATCH*C];
__device__ __nv_bfloat16 g_E2hi[BATCH*CC];   // masked exp(B_new) [b][i][j]
__device__ __nv_bfloat16 g_E2lo[BATCH*CC];
__device__ __nv_bfloat16 g_h1hi[CB*D];
__device__ __nv_bfloat16 g_h1lo[CB*D];
__device__ __nv_bfloat16 g_h2hi[CB*D];
__device__ __nv_bfloat16 g_h2lo[CB*D];
__device__ __nv_bfloat16 g_hThi[BATCH*D*C];  // [b][d][c]
__device__ __nv_bfloat16 g_hTlo[BATCH*D*C];
__device__ __nv_bfloat16 g_mhi[(size_t)CB*384]; // m' = [h, ht, h*ht]
__device__ __nv_bfloat16 g_mlo[(size_t)CB*384];
__device__ __nv_bfloat16 g_Whi[256*384];
__device__ __nv_bfloat16 g_Wlo[256*384];
__device__ float g_z[(size_t)CB*256];

// ----------------------------------------------------------------- helpers
__device__ __forceinline__ uint32_t smem_u32(const void* p) {
    uint32_t a;
    asm("{ .reg .u64 t; cvta.to.shared.u64 t, %1; cvt.u32.u64 %0, t; }" : "=r"(a) : "l"(p));
    return a;
}
__device__ __forceinline__ void mma16816(float* c, const uint32_t* a, const uint32_t* b) {
    asm volatile(
        "mma.sync.aligned.m16n8k16.row.col.f32.bf16.bf16.f32 "
        "{%0,%1,%2,%3}, {%4,%5,%6,%7}, {%8,%9}, {%0,%1,%2,%3};"
        : "+f"(c[0]), "+f"(c[1]), "+f"(c[2]), "+f"(c[3])
        : "r"(a[0]), "r"(a[1]), "r"(a[2]), "r"(a[3]), "r"(b[0]), "r"(b[1]));
}
__device__ __forceinline__ void mma16832f8(float* c, const uint32_t* a, const uint32_t* b) {
    asm volatile(
        "mma.sync.aligned.m16n8k32.row.col.f32.e4m3.e4m3.f32 "
        "{%0,%1,%2,%3}, {%4,%5,%6,%7}, {%8,%9}, {%0,%1,%2,%3};"
        : "+f"(c[0]), "+f"(c[1]), "+f"(c[2]), "+f"(c[3])
        : "r"(a[0]), "r"(a[1]), "r"(a[2]), "r"(a[3]), "r"(b[0]), "r"(b[1]));
}
__device__ __forceinline__ void ldsm4(uint32_t a, uint32_t* r) {
    asm volatile("ldmatrix.sync.aligned.m8n8.x4.shared.b16 {%0,%1,%2,%3}, [%4];"
        : "=r"(r[0]), "=r"(r[1]), "=r"(r[2]), "=r"(r[3]) : "r"(a));
}
__device__ __forceinline__ void cp16(uint32_t s, const void* g) {
    asm volatile("cp.async.cg.shared.global [%0], [%1], 16;" :: "r"(s), "l"(g));
}
#define CP_COMMIT() asm volatile("cp.async.commit_group;" ::: "memory")
#define CP_WAITN(n) asm volatile("cp.async.wait_group %0;" :: "n"(n) : "memory")

__device__ __forceinline__ void split2(float2 v, __nv_bfloat162& hi, __nv_bfloat162& lo) {
    hi.x = __float2bfloat16(v.x); lo.x = __float2bfloat16(v.x - __bfloat162float(hi.x));
    hi.y = __float2bfloat16(v.y); lo.y = __float2bfloat16(v.y - __bfloat162float(hi.y));
}
__device__ __forceinline__ uint8_t to_e4m3(float x) {
    return (uint8_t)__nv_cvt_float_to_fp8(x, __NV_SATFINITE, __NV_E4M3);
}

// ldmatrix per-lane address offsets (row stride LDKB=144 for all tiles)
__device__ __forceinline__ uint32_t a_lane_off(int warp_row, int lid) {
    int mi = lid >> 3, l7 = lid & 7;
    return (uint32_t)((warp_row + (mi & 1)*8 + l7)*LDKB + (mi >> 1)*16);
}
__device__ __forceinline__ uint32_t b_lane_off(int warp_col, int lid) {
    int mi = lid >> 3, l7 = lid & 7;
    return (uint32_t)((warp_col + (mi >> 1)*8 + l7)*LDKB + (mi & 1)*16);
}

// load one 2-tile bf16 chunk (A, B), 128 rows x 64 bf16 each
__device__ __forceinline__ void issue_single(
    uint32_t sb, int tid,
    const __nv_bfloat16* A, const __nv_bfloat16* Bp, size_t rs)
{
#pragma unroll
    for (int q = 0; q < 4; q++) {
        int idx = q*256 + tid;
        int row = idx >> 3, seg = idx & 7;
        size_t g = (size_t)row*rs + seg*8;
        uint32_t so = row*LDKB + seg*16;
        cp16(sb +          so, A  + g);
        cp16(sb + TILE_B + so, Bp + g);
    }
}

// load one 2-tile fp8 chunk (A, B), 128 rows x 128 e4m3 bytes each (K=128)
__device__ __forceinline__ void issue_fp8_128(
    uint32_t sb, int tid, const uint8_t* A, const uint8_t* Bp, size_t rs)
{
#pragma unroll
    for (int q = 0; q < 8; q++) {
        int idx = q*256 + tid;
        int tile = idx >> 10;
        int row  = (idx >> 3) & 127;
        int seg  = idx & 7;
        const uint8_t* src = tile ? Bp : A;
        cp16(sb + tile*TILE8_B + row*LDK8 + seg*16,
             src + (size_t)row*rs + seg*16);
    }
}

// load one 4-tile bf16 chunk (Ah, Al, Bh, Bl), 128 rows each
__device__ __forceinline__ void issue_tiles(
    uint32_t sb, int tid,
    const __nv_bfloat16* Ah, const __nv_bfloat16* Al,
    const __nv_bfloat16* Bh, const __nv_bfloat16* Bl,
    size_t rsA, size_t rsB)
{
#pragma unroll
    for (int q = 0; q < 4; q++) {
        int idx = q*256 + tid;
        int row = idx >> 3, seg = idx & 7;
        size_t gA = (size_t)row*rsA + seg*8;
        size_t gB = (size_t)row*rsB + seg*8;
        uint32_t so = row*LDKB + seg*16;
        cp16(sb +            so, Ah + gA);
        cp16(sb +   TILE_B + so, Al + gA);
        cp16(sb + 2*TILE_B + so, Bh + gB);
        cp16(sb + 3*TILE_B + so, Bl + gB);
    }
}

// bf16 single-precision chunk (K=64), ldmatrix operands
__device__ __forceinline__ void compute_chunk1(
    uint32_t sA, uint32_t sB, float acc[4][4][4], int wm, int wn, int lid)
{
    uint32_t aoff = sA + a_lane_off(wm*64, lid);
    uint32_t boff = sB + b_lane_off(wn*32, lid);
#pragma unroll
    for (int ks = 0; ks < 4; ks++) {
        uint32_t a[4][4], bb[2][4];
#pragma unroll
        for (int im = 0; im < 4; im++) ldsm4(aoff + im*(16*LDKB) + ks*32, a[im]);
#pragma unroll
        for (int p = 0; p < 2; p++)  ldsm4(boff + p*(16*LDKB) + ks*32, bb[p]);
#pragma unroll
        for (int im = 0; im < 4; im++)
#pragma unroll
            for (int jn = 0; jn < 4; jn++)
                mma16816(acc[im][jn], a[im], &bb[jn>>1][(jn&1)*2]);
    }
}

// fp8 chunk (K=128): 4 x m16n8k32 ksteps, ldmatrix operands
__device__ __forceinline__ void compute_chunk_fp8(
    uint32_t sA, uint32_t sB, float acc[4][4][4], int wm, int wn, int lid)
{
    uint32_t aoff = sA + a_lane_off(wm*64, lid);
    uint32_t boff = sB + b_lane_off(wn*32, lid);
#pragma unroll
    for (int ks = 0; ks < 4; ks++) {
        uint32_t a[4][4], bb[2][4];
#pragma unroll
        for (int im = 0; im < 4; im++) ldsm4(aoff + im*(16*LDKB) + ks*32, a[im]);
#pragma unroll
        for (int p = 0; p < 2; p++)  ldsm4(boff + p*(16*LDKB) + ks*32, bb[p]);
#pragma unroll
        for (int im = 0; im < 4; im++)
#pragma unroll
            for (int jn = 0; jn < 4; jn++)
                mma16832f8(acc[im][jn], a[im], &bb[jn>>1][(jn&1)*2]);
    }
}

// split-bf16 (3-mma) chunk, 128x128 tile, ldmatrix operands
__device__ __forceinline__ void compute_chunk(
    uint32_t base, float acc[4][4][4], int wm, int wn, int lid)
{
    uint32_t aoffh = base +            a_lane_off(wm*64, lid);
    uint32_t aoffl = base +   TILE_B + a_lane_off(wm*64, lid);
    uint32_t boffh = base + 2*TILE_B + b_lane_off(wn*32, lid);
    uint32_t boffl = base + 3*TILE_B + b_lane_off(wn*32, lid);
#pragma unroll
    for (int ks = 0; ks < 4; ks++) {
        uint32_t ah[4][4], al[4][4], bh[2][4], bl[2][4];
#pragma unroll
        for (int im = 0; im < 4; im++) {
            ldsm4(aoffh + im*(16*LDKB) + ks*32, ah[im]);
            ldsm4(aoffl + im*(16*LDKB) + ks*32, al[im]);
        }
#pragma unroll
        for (int p = 0; p < 2; p++) {
            ldsm4(boffh + p*(16*LDKB) + ks*32, bh[p]);
            ldsm4(boffl + p*(16*LDKB) + ks*32, bl[p]);
        }
#pragma unroll
        for (int im = 0; im < 4; im++)
#pragma unroll
            for (int jn = 0; jn < 4; jn++) {
                mma16816(acc[im][jn], ah[im], &bh[jn>>1][(jn&1)*2]);
                mma16816(acc[im][jn], ah[im], &bl[jn>>1][(jn&1)*2]);
                mma16816(acc[im][jn], al[im], &bh[jn>>1][(jn&1)*2]);
            }
    }
}

// ---------------------------------------------------------------- FC kernel
__global__ void __launch_bounds__(256) fc_kernel(
    const float* __restrict__ h,
    const float* __restrict__ W1, const float* __restrict__ b1,
    const float* __restrict__ W2, const float* __restrict__ b2)
{
    __shared__ float As[16][64];
    __shared__ float Bs[16][64];
    int t  = threadIdx.x;
    int tx = t & 15, ty = t >> 4;
    int bm = blockIdx.x, bn = blockIdx.y;

    float acc[4][4] = {};
    int ar = t >> 2;
    int kc = (t & 3) << 2;
    int rowA = bm*64 + ar;
    int e    = bn*64 + ar;
    const float* Bptr = (e < 128) ? (W1 + e*128) : (W2 + (e-128)*128);

    for (int kt = 0; kt < 128; kt += 16) {
        float4 av = *(const float4*)(h + (size_t)rowA*128 + kt + kc);
        float4 bv = *(const float4*)(Bptr + kt + kc);
        As[kc+0][ar]=av.x; As[kc+1][ar]=av.y; As[kc+2][ar]=av.z; As[kc+3][ar]=av.w;
        Bs[kc+0][ar]=bv.x; Bs[kc+1][ar]=bv.y; Bs[kc+2][ar]=bv.z; Bs[kc+3][ar]=bv.w;
        __syncthreads();
#pragma unroll
        for (int k = 0; k < 16; k++) {
            float a[4], bb[4];
#pragma unroll
            for (int i = 0; i < 4; i++) a[i]  = As[k][ty*4+i];
#pragma unroll
            for (int j = 0; j < 4; j++) bb[j] = Bs[k][tx*4+j];
#pragma unroll
            for (int i = 0; i < 4; i++)
#pragma unroll
                for (int j = 0; j < 4; j++)
                    acc[i][j] += a[i]*bb[j];
        }
        __syncthreads();
    }

#pragma unroll
    for (int i = 0; i < 4; i++) {
        int r = bm*64 + ty*4 + i;
        int c = r >> 4, b = r & 15;
#pragma unroll
        for (int j = 0; j < 4; j++) {
            int ee = bn*64 + tx*4 + j;
            float bias = (ee < 128) ? b1[ee] : b2[ee-128];
            float v = acc[i][j] + bias;
            v = v > 0.f ? v : 0.f;
            __nv_bfloat16 hi = __float2bfloat16(v);
            __nv_bfloat16 lo = __float2bfloat16(v - __bfloat162float(hi));
            size_t idx = ((size_t)(b*C + c))*D + (ee & 127);
            if (ee < 128) { g_h1hi[idx] = hi; g_h1lo[idx] = lo; }
            else          { g_h2hi[idx] = hi; g_h2lo[idx] = lo; }
        }
    }
}

// ----------------- fused exp of B_t on 128x128 tiles (e4m3 smem tile) -------
#define LDT 132   // byte stride of the e4m3 tile
__global__ void __launch_bounds__(256) esplit_kernel(
    const float* __restrict__ Bt, const int* __restrict__ mask)
{
    __shared__ uint8_t tile[128*LDT];
    __shared__ float scol[128];
    int b  = blockIdx.z;
    int x0 = blockIdx.y * 128;
    int y0 = blockIdx.x * 128;
    int w = threadIdx.x >> 5, lid = threadIdx.x & 31;

    if (threadIdx.x < 128) scol[threadIdx.x] = 0.f;
    __syncthreads();

    int4 my4 = *(const int4*)(mask + b*C + y0 + lid*4);
    float yf0 = my4.x ? 1.f : 0.f, yf1 = my4.y ? 1.f : 0.f;
    float yf2 = my4.z ? 1.f : 0.f, yf3 = my4.w ? 1.f : 0.f;
    uint32_t ymask = (my4.x ? 0xFFu : 0) | (my4.y ? 0xFF00u : 0)
                   | (my4.z ? 0xFF0000u : 0) | (my4.w ? 0xFF000000u : 0);

    float gs0 = 0.f, gs1 = 0.f, gs2 = 0.f, gs3 = 0.f;
#pragma unroll 4
    for (int i = 0; i < 16; i++) {
        int xl = w*16 + i;
        int x = x0 + xl;
        float4 v = *(const float4*)(Bt + (size_t)b*CC + (size_t)x*C + y0 + lid*4);
        float e0 = __expf(v.x), e1 = __expf(v.y), e2 = __expf(v.z), e3 = __expf(v.w);
        float s = e0*yf0 + e1*yf1 + e2*yf2 + e3*yf3;
#pragma unroll
        for (int o = 16; o > 0; o >>= 1) s += __shfl_xor_sync(0xffffffffu, s, o);
        if (lid == 0) atomicAdd(g_sumF + b*C + x, s);
        uint32_t pk =  (uint32_t)to_e4m3(e0)        | ((uint32_t)to_e4m3(e1) << 8)
                    | ((uint32_t)to_e4m3(e2) << 16) | ((uint32_t)to_e4m3(e3) << 24);
        *(uint32_t*)(tile + xl*LDT + lid*4) = pk;
        *(uint32_t*)(g_F8 + (size_t)b*CC + (size_t)x*C + y0 + lid*4) = pk & ymask;
        float mrow = mask[b*C + x] ? 1.f : 0.f;
        gs0 += e0*mrow; gs1 += e1*mrow; gs2 += e2*mrow; gs3 += e3*mrow;
    }
    atomicAdd(&scol[lid*4 + 0], gs0);
    atomicAdd(&scol[lid*4 + 1], gs1);
    atomicAdd(&scol[lid*4 + 2], gs2);
    atomicAdd(&scol[lid*4 + 3], gs3);
    __syncthreads();
    if (threadIdx.x < 128)
        atomicAdd(g_sumG + b*C + y0 + threadIdx.x, scol[threadIdx.x]);

    int xq = lid*4;
    const int* mk = mask + b*C + x0 + xq;
    uint32_t xmask = (mk[0] ? 0xFFu : 0) | (mk[1] ? 0xFF00u : 0)
                   | (mk[2] ? 0xFF0000u : 0) | (mk[3] ? 0xFF000000u : 0);
#pragma unroll 4
    for (int i = 0; i < 16; i++) {
        int yl = w*16 + i;
        int y = y0 + yl;
        uint32_t pk =  (uint32_t)tile[(xq+0)*LDT + yl]
                    | ((uint32_t)tile[(xq+1)*LDT + yl] << 8)
                    | ((uint32_t)tile[(xq+2)*LDT + yl] << 16)
                    | ((uint32_t)tile[(xq+3)*LDT + yl] << 24);
        *(uint32_t*)(g_GT8 + (size_t)b*CC + (size_t)y*C + x0 + xq) = pk & xmask;
    }
}

// ------------------------------------ hT transpose: h(c,b,d) -> [b][d][c] hi/lo
__global__ void __launch_bounds__(256) ht_transpose_kernel(const float* __restrict__ h)
{
    __shared__ float tileT[32][33];
    int b  = blockIdx.z;
    int c0 = blockIdx.x * 32;
    int d0 = blockIdx.y * 32;
    int tx = threadIdx.x & 31, ty = threadIdx.x >> 5;

#pragma unroll
    for (int r = ty; r < 32; r += 8)
        tileT[r][tx] = h[(size_t)((c0 + r)*16 + b)*128 + d0 + tx];
    __syncthreads();
#pragma unroll
    for (int r = ty; r < 32; r += 8) {
        float x = tileT[tx][r];
        __nv_bfloat16 hi = __float2bfloat16(x);
        __nv_bfloat16 lo = __float2bfloat16(x - __bfloat162float(hi));
        size_t o = (size_t)b*D*C + (size_t)(d0 + r)*C + c0 + tx;
        g_hThi[o] = hi;
        g_hTlo[o] = lo;
    }
}

// --------- folded weight stack + sum zeroing --------------------------------
__global__ void __launch_bounds__(256) wsplit_kernel(
    const float* __restrict__ Wr, const float* __restrict__ Wg)
{
    int idx = blockIdx.x*256 + threadIdx.x;
    if (idx < 3*BATCH*C) {
        if (idx < BATCH*C)          g_sumF[idx] = 0.f;
        else if (idx < 2*BATCH*C)   g_sumG[idx - BATCH*C] = 0.f;
        else                        g_sum2[idx - 2*BATCH*C] = 0.f;
    }
    int n = idx / 384, k = idx % 384;
    const float* W = (n < 128) ? (Wr + n*512) : (Wg + (n-128)*512);
    float x;
    if (k < 128)       x = W[k] + W[384 + k];
    else if (k < 256)  x = W[k] - W[k + 256];     // W1 - W3
    else               x = W[k];
    __nv_bfloat16 hi = __float2bfloat16(x);
    g_Whi[idx] = hi;
    g_Wlo[idx] = __float2bfloat16(x - __bfloat162float(hi));
}

// ============================ B_new GEMM + fused softmax epilogue ===========
// ring-3, issue distance 2, single barrier per chunk
__global__ void __launch_bounds__(256, 2) bnew_mma_kernel(
    const float* __restrict__ gamma_p, const int* __restrict__ mask,
    float* __restrict__ out)
{
    extern __shared__ char smc[];
    __shared__ int   sMask[128];
    __shared__ float sRow[128];
    int tid = threadIdx.x, wid = tid >> 5, lid = tid & 31;
    int b = blockIdx.z, it = blockIdx.y, jt = blockIdx.x;
    int wm = wid & 1, wn = wid >> 1;
    uint32_t sb = smem_u32(smc);

    if (tid < 128) { sMask[tid] = mask[b*C + jt*128 + tid]; sRow[tid] = 0.f; }

    float acc[4][4][4] = {};
    float gma = gamma_p[0];
    int lrow = lid >> 2, lcol2 = (lid & 3) << 1;

    auto issue = [&](int c) {
        uint32_t slot = sb + (uint32_t)(c % 3)*BUF2_B;
        if (c < 8) {
            const uint8_t* A  = g_F8  + ((size_t)b*C + (size_t)it*128)*C + (size_t)c*128;
            const uint8_t* Bp = g_GT8 + ((size_t)b*C + (size_t)jt*128)*C + (size_t)c*128;
            issue_fp8_128(slot, tid, A, Bp, C);
        } else {
            int tm = (c - 8) >> 1, kh = (c - 8) & 1;
            const __nv_bfloat16* A1 = (tm < 2)  ? g_h1hi : g_h1lo;
            const __nv_bfloat16* B1 = (tm == 1) ? g_h2lo : g_h2hi;
            issue_single(slot, tid,
                         A1 + ((size_t)b*C + (size_t)it*128)*D + kh*64,
                         B1 + ((size_t)b*C + (size_t)jt*128)*D + kh*64, D);
        }
    };

    issue(0); CP_COMMIT();
    issue(1); CP_COMMIT();

    for (int c = 0; c < 14; c++) {
        if (c == 13) CP_WAITN(0); else CP_WAITN(1);
        __syncthreads();
        if (c == 8) {
            float invR[8], invCv[8];
#pragma unroll
            for (int im = 0; im < 4; im++) {
                int r = it*128 + wm*64 + lrow + im*16;
                invR[2*im]   = gma / g_sumF[b*C + r];
                invR[2*im+1] = gma / g_sumF[b*C + r + 8];
            }
#pragma unroll
            for (int jn = 0; jn < 4; jn++) {
                int cj = jt*128 + wn*32 + lcol2 + jn*8;
                invCv[2*jn]   = 1.0f / g_sumG[b*C + cj];
                invCv[2*jn+1] = 1.0f / g_sumG[b*C + cj + 1];
            }
#pragma unroll
            for (int im = 0; im < 4; im++)
#pragma unroll
                for (int jn = 0; jn < 4; jn++) {
                    acc[im][jn][0] *= invR[2*im]   * invCv[2*jn];
                    acc[im][jn][1] *= invR[2*im]   * invCv[2*jn+1];
                    acc[im][jn][2] *= invR[2*im+1] * invCv[2*jn];
                    acc[im][jn][3] *= invR[2*im+1] * invCv[2*jn+1];
                }
        }
        if (c + 2 < 14) { issue(c + 2); CP_COMMIT(); }
        uint32_t base = sb + (uint32_t)(c % 3)*BUF2_B;
        if (c < 8) compute_chunk_fp8(base, base + TILE8_B, acc, wm, wn, lid);
        else       compute_chunk1(base, base + TILE_B, acc, wm, wn, lid);
    }

    // ---- epilogue: diag zero, store fp32, fused masked exp + row sums ----
    int gi0 = it*128 + wm*64 + lrow;
    int gj0 = jt*128 + wn*32 + lcol2;
    float* obase = out + (size_t)b*CC;
#pragma unroll
    for (int im = 0; im < 4; im++) {
        int r = gi0 + im*16;
        float rp0 = 0.f, rp1 = 0.f;
#pragma unroll
        for (int jn = 0; jn < 4; jn++) {
            int cj = gj0 + jn*8;
            int lc = wn*32 + lcol2 + jn*8;
            float2 v0 = make_float2(acc[im][jn][0], acc[im][jn][1]);
            float2 v1 = make_float2(acc[im][jn][2], acc[im][jn][3]);
            if (r == cj)        v0.x = 0.f;
            else if (r == cj+1) v0.y = 0.f;
            if (r+8 == cj)      v1.x = 0.f;
            else if (r+8 == cj+1) v1.y = 0.f;
            *(float2*)(obase + (size_t)r*C + cj)     = v0;
            *(float2*)(obase + (size_t)(r+8)*C + cj) = v1;

            int m0 = sMask[lc], m1 = sMask[lc+1];
            float2 e0 = make_float2(m0 ? __expf(v0.x) : 0.f, m1 ? __expf(v0.y) : 0.f);
            float2 e1 = make_float2(m0 ? __expf(v1.x) : 0.f, m1 ? __expf(v1.y) : 0.f);
            rp0 += e0.x + e0.y;
            rp1 += e1.x + e1.y;
            __nv_bfloat162 h0, l0, h1, l1;
            split2(e0, h0, l0);
            split2(e1, h1, l1);
            size_t o0 = (size_t)b*CC + (size_t)r*C + cj;
            size_t o1 = (size_t)b*CC + (size_t)(r+8)*C + cj;
            *(__nv_bfloat162*)(g_E2hi + o0) = h0;
            *(__nv_bfloat162*)(g_E2lo + o0) = l0;
            *(__nv_bfloat162*)(g_E2hi + o1) = h1;
            *(__nv_bfloat162*)(g_E2lo + o1) = l1;
        }
        atomicAdd(&sRow[wm*64 + lrow + im*16],     rp0);
        atomicAdd(&sRow[wm*64 + lrow + im*16 + 8], rp1);
    }
    __syncthreads();
    if (tid < 128) atomicAdd(g_sum2 + b*C + it*128 + tid, sRow[tid]);
}

// ============================ h_tmp GEMM (M=128) + m' construction ===========
// ring-3 of 4-tile slots, issue distance 2, single barrier per chunk
__global__ void __launch_bounds__(256) htmp_mma_kernel(const float* __restrict__ h)
{
    extern __shared__ char smc[];
    int tid = threadIdx.x, wid = tid >> 5, lid = tid & 31;
    int it = blockIdx.x, b = blockIdx.y;
    int wm = wid & 1, wn = wid >> 1;
    uint32_t sb = smem_u32(smc);

    float acc[4][4][4] = {};

    auto issue = [&](int c) {
        size_t offA = ((size_t)b*C + (size_t)it*128)*C + (size_t)c*64;
        size_t offB = (size_t)b*D*C + (size_t)c*64;
        issue_tiles(sb + (uint32_t)(c % 3)*BUF4_B, tid,
                    g_E2hi + offA, g_E2lo + offA,
                    g_hThi + offB, g_hTlo + offB, C, C);
    };

    issue(0); CP_COMMIT();
    issue(1); CP_COMMIT();
    for (int c = 0; c < 16; c++) {
        if (c == 15) CP_WAITN(0); else CP_WAITN(1);
        __syncthreads();
        if (c + 2 < 16) { issue(c + 2); CP_COMMIT(); }
        compute_chunk(sb + (uint32_t)(c % 3)*BUF4_B, acc, wm, wn, lid);
    }

    int lrow = lid >> 2, lcol2 = (lid & 3) << 1;
    int ci0 = it*128 + wm*64 + lrow;
    int d0  = wn*32 + lcol2;
#pragma unroll
    for (int im = 0; im < 4; im++) {
#pragma unroll
        for (int half = 0; half < 2; half++) {
            int cg = ci0 + im*16 + half*8;
            int r  = cg*16 + b;
            float inv = 1.0f / g_sum2[b*C + cg];
#pragma unroll
            for (int jn = 0; jn < 4; jn++) {
                int dj = d0 + jn*8;
                float2 ht = half ? make_float2(acc[im][jn][2], acc[im][jn][3])
                                 : make_float2(acc[im][jn][0], acc[im][jn][1]);
                ht.x *= inv; ht.y *= inv;
                float2 hv = *(const float2*)(h + (size_t)r*128 + dj);
                float2 seg[3];
                seg[0] = hv;
                seg[1] = ht;
                seg[2] = make_float2(hv.x*ht.x, hv.y*ht.y);
#pragma unroll
                for (int s = 0; s < 3; s++) {
                    __nv_bfloat162 hi, lo;
                    split2(seg[s], hi, lo);
                    size_t o = (size_t)r*384 + s*128 + dj;
                    *(__nv_bfloat162*)(g_mhi + o) = hi;
                    *(__nv_bfloat162*)(g_mlo + o) = lo;
                }
            }
        }
    }
}

// ============================ gate GEMM: z = m' . W'^T =======================
__global__ void __launch_bounds__(256) gate_mma_kernel()
{
    extern __shared__ char smc[];
    int tid = threadIdx.x, wid = tid >> 5, lid = tid & 31;
    int bm = blockIdx.x, half = blockIdx.y;
    int wm = wid & 1, wn = wid >> 1;
    uint32_t sb = smem_u32(smc);

    float acc[4][4][4] = {};

    auto issue = [&](int c) {
        size_t offA = ((size_t)bm*128)*384 + (size_t)c*64;
        size_t offB = ((size_t)half*128)*384 + (size_t)c*64;
        issue_tiles(sb + (uint32_t)(c % 3)*BUF4_B, tid,
                    g_mhi + offA, g_mlo + offA,
                    g_Whi + offB, g_Wlo + offB, 384, 384);
    };

    issue(0); CP_COMMIT();
    issue(1); CP_COMMIT();
    for (int c = 0; c < 6; c++) {
        if (c == 5) CP_WAITN(0); else CP_WAITN(1);
        __syncthreads();
        if (c + 2 < 6) { issue(c + 2); CP_COMMIT(); }
        compute_chunk(sb + (uint32_t)(c % 3)*BUF4_B, acc, wm, wn, lid);
    }

    int lrow = lid >> 2, lcol2 = (lid & 3) << 1;
    int r0 = bm*128 + wm*64 + lrow;
    int n0 = half*128 + wn*32 + lcol2;
#pragma unroll
    for (int im = 0; im < 4; im++) {
        int r = r0 + im*16;
#pragma unroll
        for (int jn = 0; jn < 4; jn++) {
            int n = n0 + jn*8;
            *(float2*)(g_z + (size_t)r*256 + n)     = make_float2(acc[im][jn][0], acc[im][jn][1]);
            *(float2*)(g_z + (size_t)(r+8)*256 + n) = make_float2(acc[im][jn][2], acc[im][jn][3]);
        }
    }
}

// ------------------------------------------------ combine: o = x*g + (1-g)*h
__global__ void __launch_bounds__(256) combine_kernel(
    const float* __restrict__ h, float* __restrict__ o)
{
    int idx = blockIdx.x*256 + threadIdx.x;
    int r = idx >> 5, q = idx & 31;
    float4 zr = *(const float4*)(g_z + (size_t)r*256 + q*4);
    float4 zg = *(const float4*)(g_z + (size_t)r*256 + 128 + q*4);
    float4 hv = *(const float4*)(h + (size_t)r*128 + q*4);
    float4 ov;
    { float x = fmaxf(zr.x, 0.f), gg = 1.0f/(1.0f + __expf(-zg.x)); ov.x = x*gg + (1.0f-gg)*hv.x; }
    { float x = fmaxf(zr.y, 0.f), gg = 1.0f/(1.0f + __expf(-zg.y)); ov.y = x*gg + (1.0f-gg)*hv.y; }
    { float x = fmaxf(zr.z, 0.f), gg = 1.0f/(1.0f + __expf(-zg.z)); ov.z = x*gg + (1.0f-gg)*hv.z; }
    { float x = fmaxf(zr.w, 0.f), gg = 1.0f/(1.0f + __expf(-zg.w)); ov.w = x*gg + (1.0f-gg)*hv.w; }
    *(float4*)(o + (size_t)r*128 + q*4) = ov;
}

// ---------------------------------------------------------------------------
extern "C" void kernel_launch(void* const* d_in, const int* in_sizes, int n_in,
                              void* d_out, int out_size)
{
    const float* h   = (const float*)d_in[0];
    const int*   hm  = (const int*)  d_in[1];
    const float* Bt  = (const float*)d_in[2];
    const float* W1w = (const float*)d_in[3];
    const float* W1b = (const float*)d_in[4];
    const float* W2w = (const float*)d_in[5];
    const float* W2b = (const float*)d_in[6];
    const float* gam = (const float*)d_in[7];
    const float* Wrw = (const float*)d_in[8];
    const float* Wgw = (const float*)d_in[9];

    float* o_out    = (float*)d_out;
    float* bnew_out = (float*)d_out + (size_t)CB*D;

    const int BNEW_SMEM = 3*BUF2_B;        // 110592 -> 2 CTAs/SM
    const int MMA_SMEM  = 3*BUF4_B;        // 221184 -> 1 CTA/SM, ring-3
    cudaFuncSetAttribute(bnew_mma_kernel, cudaFuncAttributeMaxDynamicSharedMemorySize, BNEW_SMEM);
    cudaFuncSetAttribute(htmp_mma_kernel, cudaFuncAttributeMaxDynamicSharedMemorySize, MMA_SMEM);
    cudaFuncSetAttribute(gate_mma_kernel, cudaFuncAttributeMaxDynamicSharedMemorySize, MMA_SMEM);

    wsplit_kernel<<<256*384/256, 256>>>(Wrw, Wgw);   // also zeroes sums
    fc_kernel<<<dim3(CB/64, 4), 256>>>(h, W1w, W1b, W2w, W2b);
    ht_transpose_kernel<<<dim3(C/32, D/32, BATCH), 256>>>(h);
    esplit_kernel<<<dim3(8, 8, BATCH), 256>>>(Bt, hm);
    bnew_mma_kernel<<<dim3(C/128, C/128, BATCH), 256, BNEW_SMEM>>>(gam, hm, bnew_out);
    htmp_mma_kernel<<<dim3(C/128, BATCH), 256, MMA_SMEM>>>(h);
    gate_mma_kernel<<<dim3(CB/128, 2), 256, MMA_SMEM>>>();
    combine_kernel<<<CB*32/256, 256>>>(h, o_out);
}

// round 14
// speedup vs baseline: 1.1915x; 1.0530x over previous
#include <cuda_runtime.h>
#include <cuda_bf16.h>
#include <cuda_fp8.h>
#include <math.h>
#include <cstdint>

#define C 1024
#define BATCH 16
#define D 128
#define CB (C*BATCH)
#define CC (C*C)

#define LDK 72                     // padded SMEM row (bf16 elems) -> 144 bytes
#define LDKB 144                   // row stride in bytes (shared by bf16 & fp8)
#define TILE_E (128*LDK)           // elems per 128-row bf16 tile
#define TILE_B (TILE_E*2)          // bytes per 128-row bf16 tile (18432)
#define BUF2_B (2*TILE_B)          // 2-tile slot bytes (36864)
#define BUF3_B (3*TILE_B)          // 3-tile slot bytes (55296)
#define BUF4_B (4*TILE_B)          // 4-tile slot bytes (73728)

#define LDK8 144                   // padded fp8 row (bytes), K=128
#define TILE8_B (128*LDK8)         // 18432 = TILE_B

// ---------------- scratch (static device memory, no runtime allocation) ----
__device__ uint8_t g_F8[BATCH*CC];           // e4m3 exp(B_t)*mask[col]   [b][i][k]
__device__ uint8_t g_GT8[BATCH*CC];          // e4m3 exp(B_t)^T*mask[col] [b][j][k]
__device__ float g_sumF[BATCH*C];
__device__ float g_sumG[BATCH*C];
__device__ float g_sum2[BATCH*C];
__device__ __nv_bfloat16 g_E2[BATCH*CC];     // masked exp(B_new), single bf16
__device__ __nv_bfloat16 g_h1hi[CB*D];
__device__ __nv_bfloat16 g_h1lo[CB*D];
__device__ __nv_bfloat16 g_h2hi[CB*D];
__device__ __nv_bfloat16 g_h2lo[CB*D];
__device__ __nv_bfloat16 g_hThi[BATCH*D*C];  // [b][d][c]
__device__ __nv_bfloat16 g_hTlo[BATCH*D*C];
__device__ __nv_bfloat16 g_mhi[(size_t)CB*384]; // m' = [h, ht, h*ht]
__device__ __nv_bfloat16 g_mlo[(size_t)CB*384];
__device__ __nv_bfloat16 g_Whi[256*384];
__device__ __nv_bfloat16 g_Wlo[256*384];
__device__ float g_z[(size_t)CB*256];

// ----------------------------------------------------------------- helpers
__device__ __forceinline__ uint32_t smem_u32(const void* p) {
    uint32_t a;
    asm("{ .reg .u64 t; cvta.to.shared.u64 t, %1; cvt.u32.u64 %0, t; }" : "=r"(a) : "l"(p));
    return a;
}
__device__ __forceinline__ void mma16816(float* c, const uint32_t* a, const uint32_t* b) {
    asm volatile(
        "mma.sync.aligned.m16n8k16.row.col.f32.bf16.bf16.f32 "
        "{%0,%1,%2,%3}, {%4,%5,%6,%7}, {%8,%9}, {%0,%1,%2,%3};"
        : "+f"(c[0]), "+f"(c[1]), "+f"(c[2]), "+f"(c[3])
        : "r"(a[0]), "r"(a[1]), "r"(a[2]), "r"(a[3]), "r"(b[0]), "r"(b[1]));
}
__device__ __forceinline__ void mma16832f8(float* c, const uint32_t* a, const uint32_t* b) {
    asm volatile(
        "mma.sync.aligned.m16n8k32.row.col.f32.e4m3.e4m3.f32 "
        "{%0,%1,%2,%3}, {%4,%5,%6,%7}, {%8,%9}, {%0,%1,%2,%3};"
        : "+f"(c[0]), "+f"(c[1]), "+f"(c[2]), "+f"(c[3])
        : "r"(a[0]), "r"(a[1]), "r"(a[2]), "r"(a[3]), "r"(b[0]), "r"(b[1]));
}
__device__ __forceinline__ void ldsm4(uint32_t a, uint32_t* r) {
    asm volatile("ldmatrix.sync.aligned.m8n8.x4.shared.b16 {%0,%1,%2,%3}, [%4];"
        : "=r"(r[0]), "=r"(r[1]), "=r"(r[2]), "=r"(r[3]) : "r"(a));
}
__device__ __forceinline__ void cp16(uint32_t s, const void* g) {
    asm volatile("cp.async.cg.shared.global [%0], [%1], 16;" :: "r"(s), "l"(g));
}
#define CP_COMMIT() asm volatile("cp.async.commit_group;" ::: "memory")
#define CP_WAITN(n) asm volatile("cp.async.wait_group %0;" :: "n"(n) : "memory")

__device__ __forceinline__ void split2(float2 v, __nv_bfloat162& hi, __nv_bfloat162& lo) {
    hi.x = __float2bfloat16(v.x); lo.x = __float2bfloat16(v.x - __bfloat162float(hi.x));
    hi.y = __float2bfloat16(v.y); lo.y = __float2bfloat16(v.y - __bfloat162float(hi.y));
}
__device__ __forceinline__ uint8_t to_e4m3(float x) {
    return (uint8_t)__nv_cvt_float_to_fp8(x, __NV_SATFINITE, __NV_E4M3);
}

// ldmatrix per-lane address offsets (row stride LDKB=144 for all tiles)
__device__ __forceinline__ uint32_t a_lane_off(int warp_row, int lid) {
    int mi = lid >> 3, l7 = lid & 7;
    return (uint32_t)((warp_row + (mi & 1)*8 + l7)*LDKB + (mi >> 1)*16);
}
__device__ __forceinline__ uint32_t b_lane_off(int warp_col, int lid) {
    int mi = lid >> 3, l7 = lid & 7;
    return (uint32_t)((warp_col + (mi >> 1)*8 + l7)*LDKB + (mi & 1)*16);
}

// load one 2-tile bf16 chunk (A, B), 128 rows x 64 bf16 each
__device__ __forceinline__ void issue_single(
    uint32_t sb, int tid,
    const __nv_bfloat16* A, const __nv_bfloat16* Bp, size_t rs)
{
#pragma unroll
    for (int q = 0; q < 4; q++) {
        int idx = q*256 + tid;
        int row = idx >> 3, seg = idx & 7;
        size_t g = (size_t)row*rs + seg*8;
        uint32_t so = row*LDKB + seg*16;
        cp16(sb +          so, A  + g);
        cp16(sb + TILE_B + so, Bp + g);
    }
}

// load one 2-tile fp8 chunk (A, B), 128 rows x 128 e4m3 bytes each (K=128)
__device__ __forceinline__ void issue_fp8_128(
    uint32_t sb, int tid, const uint8_t* A, const uint8_t* Bp, size_t rs)
{
#pragma unroll
    for (int q = 0; q < 8; q++) {
        int idx = q*256 + tid;
        int tile = idx >> 10;
        int row  = (idx >> 3) & 127;
        int seg  = idx & 7;
        const uint8_t* src = tile ? Bp : A;
        cp16(sb + tile*TILE8_B + row*LDK8 + seg*16,
             src + (size_t)row*rs + seg*16);
    }
}

// load one 3-tile bf16 chunk (A, Bh, Bl), 128 rows x 64 bf16 each
__device__ __forceinline__ void issue_tiles3(
    uint32_t sb, int tid,
    const __nv_bfloat16* A,
    const __nv_bfloat16* Bh, const __nv_bfloat16* Bl,
    size_t rsA, size_t rsB)
{
#pragma unroll
    for (int q = 0; q < 4; q++) {
        int idx = q*256 + tid;
        int row = idx >> 3, seg = idx & 7;
        size_t gA = (size_t)row*rsA + seg*8;
        size_t gB = (size_t)row*rsB + seg*8;
        uint32_t so = row*LDKB + seg*16;
        cp16(sb +            so, A  + gA);
        cp16(sb +   TILE_B + so, Bh + gB);
        cp16(sb + 2*TILE_B + so, Bl + gB);
    }
}

// load one 4-tile bf16 chunk (Ah, Al, Bh, Bl), 128 rows each
__device__ __forceinline__ void issue_tiles(
    uint32_t sb, int tid,
    const __nv_bfloat16* Ah, const __nv_bfloat16* Al,
    const __nv_bfloat16* Bh, const __nv_bfloat16* Bl,
    size_t rsA, size_t rsB)
{
#pragma unroll
    for (int q = 0; q < 4; q++) {
        int idx = q*256 + tid;
        int row = idx >> 3, seg = idx & 7;
        size_t gA = (size_t)row*rsA + seg*8;
        size_t gB = (size_t)row*rsB + seg*8;
        uint32_t so = row*LDKB + seg*16;
        cp16(sb +            so, Ah + gA);
        cp16(sb +   TILE_B + so, Al + gA);
        cp16(sb + 2*TILE_B + so, Bh + gB);
        cp16(sb + 3*TILE_B + so, Bl + gB);
    }
}

// bf16 single-precision chunk (K=64), ldmatrix operands
__device__ __forceinline__ void compute_chunk1(
    uint32_t sA, uint32_t sB, float acc[4][4][4], int wm, int wn, int lid)
{
    uint32_t aoff = sA + a_lane_off(wm*64, lid);
    uint32_t boff = sB + b_lane_off(wn*32, lid);
#pragma unroll
    for (int ks = 0; ks < 4; ks++) {
        uint32_t a[4][4], bb[2][4];
#pragma unroll
        for (int im = 0; im < 4; im++) ldsm4(aoff + im*(16*LDKB) + ks*32, a[im]);
#pragma unroll
        for (int p = 0; p < 2; p++)  ldsm4(boff + p*(16*LDKB) + ks*32, bb[p]);
#pragma unroll
        for (int im = 0; im < 4; im++)
#pragma unroll
            for (int jn = 0; jn < 4; jn++)
                mma16816(acc[im][jn], a[im], &bb[jn>>1][(jn&1)*2]);
    }
}

// fp8 chunk (K=128): 4 x m16n8k32 ksteps, ldmatrix operands
__device__ __forceinline__ void compute_chunk_fp8(
    uint32_t sA, uint32_t sB, float acc[4][4][4], int wm, int wn, int lid)
{
    uint32_t aoff = sA + a_lane_off(wm*64, lid);
    uint32_t boff = sB + b_lane_off(wn*32, lid);
#pragma unroll
    for (int ks = 0; ks < 4; ks++) {
        uint32_t a[4][4], bb[2][4];
#pragma unroll
        for (int im = 0; im < 4; im++) ldsm4(aoff + im*(16*LDKB) + ks*32, a[im]);
#pragma unroll
        for (int p = 0; p < 2; p++)  ldsm4(boff + p*(16*LDKB) + ks*32, bb[p]);
#pragma unroll
        for (int im = 0; im < 4; im++)
#pragma unroll
            for (int jn = 0; jn < 4; jn++)
                mma16832f8(acc[im][jn], a[im], &bb[jn>>1][(jn&1)*2]);
    }
}

// 2-mma chunk (A single, B hi/lo), 128x128 tile
__device__ __forceinline__ void compute_chunk2(
    uint32_t base, float acc[4][4][4], int wm, int wn, int lid)
{
    uint32_t aoff  = base +            a_lane_off(wm*64, lid);
    uint32_t boffh = base +   TILE_B + b_lane_off(wn*32, lid);
    uint32_t boffl = base + 2*TILE_B + b_lane_off(wn*32, lid);
#pragma unroll
    for (int ks = 0; ks < 4; ks++) {
        uint32_t a[4][4], bh[2][4], bl[2][4];
#pragma unroll
        for (int im = 0; im < 4; im++) ldsm4(aoff + im*(16*LDKB) + ks*32, a[im]);
#pragma unroll
        for (int p = 0; p < 2; p++) {
            ldsm4(boffh + p*(16*LDKB) + ks*32, bh[p]);
            ldsm4(boffl + p*(16*LDKB) + ks*32, bl[p]);
        }
#pragma unroll
        for (int im = 0; im < 4; im++)
#pragma unroll
            for (int jn = 0; jn < 4; jn++) {
                mma16816(acc[im][jn], a[im], &bh[jn>>1][(jn&1)*2]);
                mma16816(acc[im][jn], a[im], &bl[jn>>1][(jn&1)*2]);
            }
    }
}

// split-bf16 (3-mma) chunk, 128x128 tile, ldmatrix operands
__device__ __forceinline__ void compute_chunk(
    uint32_t base, float acc[4][4][4], int wm, int wn, int lid)
{
    uint32_t aoffh = base +            a_lane_off(wm*64, lid);
    uint32_t aoffl = base +   TILE_B + a_lane_off(wm*64, lid);
    uint32_t boffh = base + 2*TILE_B + b_lane_off(wn*32, lid);
    uint32_t boffl = base + 3*TILE_B + b_lane_off(wn*32, lid);
#pragma unroll
    for (int ks = 0; ks < 4; ks++) {
        uint32_t ah[4][4], al[4][4], bh[2][4], bl[2][4];
#pragma unroll
        for (int im = 0; im < 4; im++) {
            ldsm4(aoffh + im*(16*LDKB) + ks*32, ah[im]);
            ldsm4(aoffl + im*(16*LDKB) + ks*32, al[im]);
        }
#pragma unroll
        for (int p = 0; p < 2; p++) {
            ldsm4(boffh + p*(16*LDKB) + ks*32, bh[p]);
            ldsm4(boffl + p*(16*LDKB) + ks*32, bl[p]);
        }
#pragma unroll
        for (int im = 0; im < 4; im++)
#pragma unroll
            for (int jn = 0; jn < 4; jn++) {
                mma16816(acc[im][jn], ah[im], &bh[jn>>1][(jn&1)*2]);
                mma16816(acc[im][jn], ah[im], &bl[jn>>1][(jn&1)*2]);
                mma16816(acc[im][jn], al[im], &bh[jn>>1][(jn&1)*2]);
            }
    }
}

// ---------------------------------------------------------------- FC kernel
__global__ void __launch_bounds__(256) fc_kernel(
    const float* __restrict__ h,
    const float* __restrict__ W1, const float* __restrict__ b1,
    const float* __restrict__ W2, const float* __restrict__ b2)
{
    __shared__ float As[16][64];
    __shared__ float Bs[16][64];
    int t  = threadIdx.x;
    int tx = t & 15, ty = t >> 4;
    int bm = blockIdx.x, bn = blockIdx.y;

    float acc[4][4] = {};
    int ar = t >> 2;
    int kc = (t & 3) << 2;
    int rowA = bm*64 + ar;
    int e    = bn*64 + ar;
    const float* Bptr = (e < 128) ? (W1 + e*128) : (W2 + (e-128)*128);

    for (int kt = 0; kt < 128; kt += 16) {
        float4 av = *(const float4*)(h + (size_t)rowA*128 + kt + kc);
        float4 bv = *(const float4*)(Bptr + kt + kc);
        As[kc+0][ar]=av.x; As[kc+1][ar]=av.y; As[kc+2][ar]=av.z; As[kc+3][ar]=av.w;
        Bs[kc+0][ar]=bv.x; Bs[kc+1][ar]=bv.y; Bs[kc+2][ar]=bv.z; Bs[kc+3][ar]=bv.w;
        __syncthreads();
#pragma unroll
        for (int k = 0; k < 16; k++) {
            float a[4], bb[4];
#pragma unroll
            for (int i = 0; i < 4; i++) a[i]  = As[k][ty*4+i];
#pragma unroll
            for (int j = 0; j < 4; j++) bb[j] = Bs[k][tx*4+j];
#pragma unroll
            for (int i = 0; i < 4; i++)
#pragma unroll
                for (int j = 0; j < 4; j++)
                    acc[i][j] += a[i]*bb[j];
        }
        __syncthreads();
    }

#pragma unroll
    for (int i = 0; i < 4; i++) {
        int r = bm*64 + ty*4 + i;
        int c = r >> 4, b = r & 15;
#pragma unroll
        for (int j = 0; j < 4; j++) {
            int ee = bn*64 + tx*4 + j;
            float bias = (ee < 128) ? b1[ee] : b2[ee-128];
            float v = acc[i][j] + bias;
            v = v > 0.f ? v : 0.f;
            __nv_bfloat16 hi = __float2bfloat16(v);
            __nv_bfloat16 lo = __float2bfloat16(v - __bfloat162float(hi));
            size_t idx = ((size_t)(b*C + c))*D + (ee & 127);
            if (ee < 128) { g_h1hi[idx] = hi; g_h1lo[idx] = lo; }
            else          { g_h2hi[idx] = hi; g_h2lo[idx] = lo; }
        }
    }
}

// ----------------- fused exp of B_t on 128x128 tiles (e4m3 smem tile) -------
#define LDT 132   // byte stride of the e4m3 tile
__global__ void __launch_bounds__(256) esplit_kernel(
    const float* __restrict__ Bt, const int* __restrict__ mask)
{
    __shared__ uint8_t tile[128*LDT];
    __shared__ float scol[128];
    int b  = blockIdx.z;
    int x0 = blockIdx.y * 128;
    int y0 = blockIdx.x * 128;
    int w = threadIdx.x >> 5, lid = threadIdx.x & 31;

    if (threadIdx.x < 128) scol[threadIdx.x] = 0.f;
    __syncthreads();

    int4 my4 = *(const int4*)(mask + b*C + y0 + lid*4);
    float yf0 = my4.x ? 1.f : 0.f, yf1 = my4.y ? 1.f : 0.f;
    float yf2 = my4.z ? 1.f : 0.f, yf3 = my4.w ? 1.f : 0.f;
    uint32_t ymask = (my4.x ? 0xFFu : 0) | (my4.y ? 0xFF00u : 0)
                   | (my4.z ? 0xFF0000u : 0) | (my4.w ? 0xFF000000u : 0);

    float gs0 = 0.f, gs1 = 0.f, gs2 = 0.f, gs3 = 0.f;
#pragma unroll 4
    for (int i = 0; i < 16; i++) {
        int xl = w*16 + i;
        int x = x0 + xl;
        float4 v = *(const float4*)(Bt + (size_t)b*CC + (size_t)x*C + y0 + lid*4);
        float e0 = __expf(v.x), e1 = __expf(v.y), e2 = __expf(v.z), e3 = __expf(v.w);
        float s = e0*yf0 + e1*yf1 + e2*yf2 + e3*yf3;
#pragma unroll
        for (int o = 16; o > 0; o >>= 1) s += __shfl_xor_sync(0xffffffffu, s, o);
        if (lid == 0) atomicAdd(g_sumF + b*C + x, s);
        uint32_t pk =  (uint32_t)to_e4m3(e0)        | ((uint32_t)to_e4m3(e1) << 8)
                    | ((uint32_t)to_e4m3(e2) << 16) | ((uint32_t)to_e4m3(e3) << 24);
        *(uint32_t*)(tile + xl*LDT + lid*4) = pk;
        *(uint32_t*)(g_F8 + (size_t)b*CC + (size_t)x*C + y0 + lid*4) = pk & ymask;
        float mrow = mask[b*C + x] ? 1.f : 0.f;
        gs0 += e0*mrow; gs1 += e1*mrow; gs2 += e2*mrow; gs3 += e3*mrow;
    }
    atomicAdd(&scol[lid*4 + 0], gs0);
    atomicAdd(&scol[lid*4 + 1], gs1);
    atomicAdd(&scol[lid*4 + 2], gs2);
    atomicAdd(&scol[lid*4 + 3], gs3);
    __syncthreads();
    if (threadIdx.x < 128)
        atomicAdd(g_sumG + b*C + y0 + threadIdx.x, scol[threadIdx.x]);

    int xq = lid*4;
    const int* mk = mask + b*C + x0 + xq;
    uint32_t xmask = (mk[0] ? 0xFFu : 0) | (mk[1] ? 0xFF00u : 0)
                   | (mk[2] ? 0xFF0000u : 0) | (mk[3] ? 0xFF000000u : 0);
#pragma unroll 4
    for (int i = 0; i < 16; i++) {
        int yl = w*16 + i;
        int y = y0 + yl;
        uint32_t pk =  (uint32_t)tile[(xq+0)*LDT + yl]
                    | ((uint32_t)tile[(xq+1)*LDT + yl] << 8)
                    | ((uint32_t)tile[(xq+2)*LDT + yl] << 16)
                    | ((uint32_t)tile[(xq+3)*LDT + yl] << 24);
        *(uint32_t*)(g_GT8 + (size_t)b*CC + (size_t)y*C + x0 + xq) = pk & xmask;
    }
}

// ------------------------------------ hT transpose: h(c,b,d) -> [b][d][c] hi/lo
__global__ void __launch_bounds__(256) ht_transpose_kernel(const float* __restrict__ h)
{
    __shared__ float tileT[32][33];
    int b  = blockIdx.z;
    int c0 = blockIdx.x * 32;
    int d0 = blockIdx.y * 32;
    int tx = threadIdx.x & 31, ty = threadIdx.x >> 5;

#pragma unroll
    for (int r = ty; r < 32; r += 8)
        tileT[r][tx] = h[(size_t)((c0 + r)*16 + b)*128 + d0 + tx];
    __syncthreads();
#pragma unroll
    for (int r = ty; r < 32; r += 8) {
        float x = tileT[tx][r];
        __nv_bfloat16 hi = __float2bfloat16(x);
        __nv_bfloat16 lo = __float2bfloat16(x - __bfloat162float(hi));
        size_t o = (size_t)b*D*C + (size_t)(d0 + r)*C + c0 + tx;
        g_hThi[o] = hi;
        g_hTlo[o] = lo;
    }
}

// --------- folded weight stack + sum zeroing --------------------------------
__global__ void __launch_bounds__(256) wsplit_kernel(
    const float* __restrict__ Wr, const float* __restrict__ Wg)
{
    int idx = blockIdx.x*256 + threadIdx.x;
    if (idx < 3*BATCH*C) {
        if (idx < BATCH*C)          g_sumF[idx] = 0.f;
        else if (idx < 2*BATCH*C)   g_sumG[idx - BATCH*C] = 0.f;
        else                        g_sum2[idx - 2*BATCH*C] = 0.f;
    }
    int n = idx / 384, k = idx % 384;
    const float* W = (n < 128) ? (Wr + n*512) : (Wg + (n-128)*512);
    float x;
    if (k < 128)       x = W[k] + W[384 + k];
    else if (k < 256)  x = W[k] - W[k + 256];     // W1 - W3
    else               x = W[k];
    __nv_bfloat16 hi = __float2bfloat16(x);
    g_Whi[idx] = hi;
    g_Wlo[idx] = __float2bfloat16(x - __bfloat162float(hi));
}

// ============================ B_new GEMM + fused softmax epilogue ===========
__global__ void __launch_bounds__(256, 2) bnew_mma_kernel(
    const float* __restrict__ gamma_p, const int* __restrict__ mask,
    float* __restrict__ out)
{
    extern __shared__ char smc[];
    __shared__ int   sMask[128];
    __shared__ float sRow[128];
    int tid = threadIdx.x, wid = tid >> 5, lid = tid & 31;
    int b = blockIdx.z, it = blockIdx.y, jt = blockIdx.x;
    int wm = wid & 1, wn = wid >> 1;
    uint32_t sb = smem_u32(smc);

    if (tid < 128) { sMask[tid] = mask[b*C + jt*128 + tid]; sRow[tid] = 0.f; }

    float acc[4][4][4] = {};
    float gma = gamma_p[0];
    int lrow = lid >> 2, lcol2 = (lid & 3) << 1;

    auto issue = [&](int c) {
        uint32_t slot = sb + (uint32_t)(c % 3)*BUF2_B;
        if (c < 8) {
            const uint8_t* A  = g_F8  + ((size_t)b*C + (size_t)it*128)*C + (size_t)c*128;
            const uint8_t* Bp = g_GT8 + ((size_t)b*C + (size_t)jt*128)*C + (size_t)c*128;
            issue_fp8_128(slot, tid, A, Bp, C);
        } else {
            int tm = (c - 8) >> 1, kh = (c - 8) & 1;
            const __nv_bfloat16* A1 = (tm < 2)  ? g_h1hi : g_h1lo;
            const __nv_bfloat16* B1 = (tm == 1) ? g_h2lo : g_h2hi;
            issue_single(slot, tid,
                         A1 + ((size_t)b*C + (size_t)it*128)*D + kh*64,
                         B1 + ((size_t)b*C + (size_t)jt*128)*D + kh*64, D);
        }
    };

    issue(0); CP_COMMIT();
    issue(1); CP_COMMIT();

    for (int c = 0; c < 14; c++) {
        if (c == 13) CP_WAITN(0); else CP_WAITN(1);
        __syncthreads();
        if (c == 8) {
            float invR[8], invCv[8];
#pragma unroll
            for (int im = 0; im < 4; im++) {
                int r = it*128 + wm*64 + lrow + im*16;
                invR[2*im]   = gma / g_sumF[b*C + r];
                invR[2*im+1] = gma / g_sumF[b*C + r + 8];
            }
#pragma unroll
            for (int jn = 0; jn < 4; jn++) {
                int cj = jt*128 + wn*32 + lcol2 + jn*8;
                invCv[2*jn]   = 1.0f / g_sumG[b*C + cj];
                invCv[2*jn+1] = 1.0f / g_sumG[b*C + cj + 1];
            }
#pragma unroll
            for (int im = 0; im < 4; im++)
#pragma unroll
                for (int jn = 0; jn < 4; jn++) {
                    acc[im][jn][0] *= invR[2*im]   * invCv[2*jn];
                    acc[im][jn][1] *= invR[2*im]   * invCv[2*jn+1];
                    acc[im][jn][2] *= invR[2*im+1] * invCv[2*jn];
                    acc[im][jn][3] *= invR[2*im+1] * invCv[2*jn+1];
                }
        }
        if (c + 2 < 14) { issue(c + 2); CP_COMMIT(); }
        uint32_t base = sb + (uint32_t)(c % 3)*BUF2_B;
        if (c < 8) compute_chunk_fp8(base, base + TILE8_B, acc, wm, wn, lid);
        else       compute_chunk1(base, base + TILE_B, acc, wm, wn, lid);
    }

    // ---- epilogue: diag zero, store fp32, fused masked exp (single bf16) ----
    int gi0 = it*128 + wm*64 + lrow;
    int gj0 = jt*128 + wn*32 + lcol2;
    float* obase = out + (size_t)b*CC;
#pragma unroll
    for (int im = 0; im < 4; im++) {
        int r = gi0 + im*16;
        float rp0 = 0.f, rp1 = 0.f;
#pragma unroll
        for (int jn = 0; jn < 4; jn++) {
            int cj = gj0 + jn*8;
            int lc = wn*32 + lcol2 + jn*8;
            float2 v0 = make_float2(acc[im][jn][0], acc[im][jn][1]);
            float2 v1 = make_float2(acc[im][jn][2], acc[im][jn][3]);
            if (r == cj)        v0.x = 0.f;
            else if (r == cj+1) v0.y = 0.f;
            if (r+8 == cj)      v1.x = 0.f;
            else if (r+8 == cj+1) v1.y = 0.f;
            *(float2*)(obase + (size_t)r*C + cj)     = v0;
            *(float2*)(obase + (size_t)(r+8)*C + cj) = v1;

            int m0 = sMask[lc], m1 = sMask[lc+1];
            float2 e0 = make_float2(m0 ? __expf(v0.x) : 0.f, m1 ? __expf(v0.y) : 0.f);
            float2 e1 = make_float2(m0 ? __expf(v1.x) : 0.f, m1 ? __expf(v1.y) : 0.f);
            rp0 += e0.x + e0.y;
            rp1 += e1.x + e1.y;
            __nv_bfloat162 q0, q1;
            q0.x = __float2bfloat16(e0.x); q0.y = __float2bfloat16(e0.y);
            q1.x = __float2bfloat16(e1.x); q1.y = __float2bfloat16(e1.y);
            *(__nv_bfloat162*)(g_E2 + (size_t)b*CC + (size_t)r*C + cj)     = q0;
            *(__nv_bfloat162*)(g_E2 + (size_t)b*CC + (size_t)(r+8)*C + cj) = q1;
        }
        atomicAdd(&sRow[wm*64 + lrow + im*16],     rp0);
        atomicAdd(&sRow[wm*64 + lrow + im*16 + 8], rp1);
    }
    __syncthreads();
    if (tid < 128) atomicAdd(g_sum2 + b*C + it*128 + tid, sRow[tid]);
}

// ============================ h_tmp GEMM (M=128, 2-mma) + m' construction ====
__global__ void __launch_bounds__(256) htmp_mma_kernel(const float* __restrict__ h)
{
    extern __shared__ char smc[];
    int tid = threadIdx.x, wid = tid >> 5, lid = tid & 31;
    int it = blockIdx.x, b = blockIdx.y;
    int wm = wid & 1, wn = wid >> 1;
    uint32_t sb = smem_u32(smc);

    float acc[4][4][4] = {};

    auto issue = [&](int c) {
        size_t offA = ((size_t)b*C + (size_t)it*128)*C + (size_t)c*64;
        size_t offB = (size_t)b*D*C + (size_t)c*64;
        issue_tiles3(sb + (uint32_t)(c % 3)*BUF3_B, tid,
                     g_E2 + offA,
                     g_hThi + offB, g_hTlo + offB, C, C);
    };

    issue(0); CP_COMMIT();
    issue(1); CP_COMMIT();
    for (int c = 0; c < 16; c++) {
        if (c == 15) CP_WAITN(0); else CP_WAITN(1);
        __syncthreads();
        if (c + 2 < 16) { issue(c + 2); CP_COMMIT(); }
        compute_chunk2(sb + (uint32_t)(c % 3)*BUF3_B, acc, wm, wn, lid);
    }

    int lrow = lid >> 2, lcol2 = (lid & 3) << 1;
    int ci0 = it*128 + wm*64 + lrow;
    int d0  = wn*32 + lcol2;
#pragma unroll
    for (int im = 0; im < 4; im++) {
#pragma unroll
        for (int half = 0; half < 2; half++) {
            int cg = ci0 + im*16 + half*8;
            int r  = cg*16 + b;
            float inv = 1.0f / g_sum2[b*C + cg];
#pragma unroll
            for (int jn = 0; jn < 4; jn++) {
                int dj = d0 + jn*8;
                float2 ht = half ? make_float2(acc[im][jn][2], acc[im][jn][3])
                                 : make_float2(acc[im][jn][0], acc[im][jn][1]);
                ht.x *= inv; ht.y *= inv;
                float2 hv = *(const float2*)(h + (size_t)r*128 + dj);
                float2 seg[3];
                seg[0] = hv;
                seg[1] = ht;
                seg[2] = make_float2(hv.x*ht.x, hv.y*ht.y);
#pragma unroll
                for (int s = 0; s < 3; s++) {
                    __nv_bfloat162 hi, lo;
                    split2(seg[s], hi, lo);
                    size_t o = (size_t)r*384 + s*128 + dj;
                    *(__nv_bfloat162*)(g_mhi + o) = hi;
                    *(__nv_bfloat162*)(g_mlo + o) = lo;
                }
            }
        }
    }
}

// ============================ gate GEMM: z = m' . W'^T =======================
__global__ void __launch_bounds__(256) gate_mma_kernel()
{
    extern __shared__ char smc[];
    int tid = threadIdx.x, wid = tid >> 5, lid = tid & 31;
    int bm = blockIdx.x, half = blockIdx.y;
    int wm = wid & 1, wn = wid >> 1;
    uint32_t sb = smem_u32(smc);

    float acc[4][4][4] = {};

    auto issue = [&](int c) {
        size_t offA = ((size_t)bm*128)*384 + (size_t)c*64;
        size_t offB = ((size_t)half*128)*384 + (size_t)c*64;
        issue_tiles(sb + (uint32_t)(c % 3)*BUF4_B, tid,
                    g_mhi + offA, g_mlo + offA,
                    g_Whi + offB, g_Wlo + offB, 384, 384);
    };

    issue(0); CP_COMMIT();
    issue(1); CP_COMMIT();
    for (int c = 0; c < 6; c++) {
        if (c == 5) CP_WAITN(0); else CP_WAITN(1);
        __syncthreads();
        if (c + 2 < 6) { issue(c + 2); CP_COMMIT(); }
        compute_chunk(sb + (uint32_t)(c % 3)*BUF4_B, acc, wm, wn, lid);
    }

    int lrow = lid >> 2, lcol2 = (lid & 3) << 1;
    int r0 = bm*128 + wm*64 + lrow;
    int n0 = half*128 + wn*32 + lcol2;
#pragma unroll
    for (int im = 0; im < 4; im++) {
        int r = r0 + im*16;
#pragma unroll
        for (int jn = 0; jn < 4; jn++) {
            int n = n0 + jn*8;
            *(float2*)(g_z + (size_t)r*256 + n)     = make_float2(acc[im][jn][0], acc[im][jn][1]);
            *(float2*)(g_z + (size_t)(r+8)*256 + n) = make_float2(acc[im][jn][2], acc[im][jn][3]);
        }
    }
}

// ------------------------------------------------ combine: o = x*g + (1-g)*h
__global__ void __launch_bounds__(256) combine_kernel(
    const float* __restrict__ h, float* __restrict__ o)
{
    int idx = blockIdx.x*256 + threadIdx.x;
    int r = idx >> 5, q = idx & 31;
    float4 zr = *(const float4*)(g_z + (size_t)r*256 + q*4);
    float4 zg = *(const float4*)(g_z + (size_t)r*256 + 128 + q*4);
    float4 hv = *(const float4*)(h + (size_t)r*128 + q*4);
    float4 ov;
    { float x = fmaxf(zr.x, 0.f), gg = 1.0f/(1.0f + __expf(-zg.x)); ov.x = x*gg + (1.0f-gg)*hv.x; }
    { float x = fmaxf(zr.y, 0.f), gg = 1.0f/(1.0f + __expf(-zg.y)); ov.y = x*gg + (1.0f-gg)*hv.y; }
    { float x = fmaxf(zr.z, 0.f), gg = 1.0f/(1.0f + __expf(-zg.z)); ov.z = x*gg + (1.0f-gg)*hv.z; }
    { float x = fmaxf(zr.w, 0.f), gg = 1.0f/(1.0f + __expf(-zg.w)); ov.w = x*gg + (1.0f-gg)*hv.w; }
    *(float4*)(o + (size_t)r*128 + q*4) = ov;
}

// ---------------------------------------------------------------------------
extern "C" void kernel_launch(void* const* d_in, const int* in_sizes, int n_in,
                              void* d_out, int out_size)
{
    const float* h   = (const float*)d_in[0];
    const int*   hm  = (const int*)  d_in[1];
    const float* Bt  = (const float*)d_in[2];
    const float* W1w = (const float*)d_in[3];
    const float* W1b = (const float*)d_in[4];
    const float* W2w = (const float*)d_in[5];
    const float* W2b = (const float*)d_in[6];
    const float* gam = (const float*)d_in[7];
    const float* Wrw = (const float*)d_in[8];
    const float* Wgw = (const float*)d_in[9];

    float* o_out    = (float*)d_out;
    float* bnew_out = (float*)d_out + (size_t)CB*D;

    const int BNEW_SMEM = 3*BUF2_B;        // 110592 -> 2 CTAs/SM
    const int HTMP_SMEM = 3*BUF3_B;        // 165888 -> 1 CTA/SM, ring-3
    const int GATE_SMEM = 3*BUF4_B;        // 221184 -> 1 CTA/SM, ring-3
    cudaFuncSetAttribute(bnew_mma_kernel, cudaFuncAttributeMaxDynamicSharedMemorySize, BNEW_SMEM);
    cudaFuncSetAttribute(htmp_mma_kernel, cudaFuncAttributeMaxDynamicSharedMemorySize, HTMP_SMEM);
    cudaFuncSetAttribute(gate_mma_kernel, cudaFuncAttributeMaxDynamicSharedMemorySize, GATE_SMEM);

    wsplit_kernel<<<256*384/256, 256>>>(Wrw, Wgw);   // also zeroes sums
    fc_kernel<<<dim3(CB/64, 4), 256>>>(h, W1w, W1b, W2w, W2b);
    ht_transpose_kernel<<<dim3(C/32, D/32, BATCH), 256>>>(h);
    esplit_kernel<<<dim3(8, 8, BATCH), 256>>>(Bt, hm);
    bnew_mma_kernel<<<dim3(C/128, C/128, BATCH), 256, BNEW_SMEM>>>(gam, hm, bnew_out);
    htmp_mma_kernel<<<dim3(C/128, BATCH), 256, HTMP_SMEM>>>(h);
    gate_mma_kernel<<<dim3(CB/128, 2), 256, GATE_SMEM>>>();
    combine_kernel<<<CB*32/256, 256>>>(h, o_out);
}

// round 15
// speedup vs baseline: 1.2012x; 1.0082x over previous
#include <cuda_runtime.h>
#include <cuda_bf16.h>
#include <cuda_fp8.h>
#include <math.h>
#include <cstdint>

#define C 1024
#define BATCH 16
#define D 128
#define CB (C*BATCH)
#define CC (C*C)

#define LDK 72                     // padded SMEM row (bf16 elems) -> 144 bytes
#define LDKB 144                   // row stride in bytes (shared by bf16 & fp8)
#define TILE_E (128*LDK)           // elems per 128-row bf16 tile
#define TILE_B (TILE_E*2)          // bytes per 128-row bf16 tile (18432)
#define WTILE_B (2*TILE_B)         // 256-row bf16 tile (36864)
#define BUF2_B (2*TILE_B)          // 2-tile slot bytes (36864)
#define BUF3_B (3*TILE_B)          // 3-tile slot bytes (55296)
#define GSLOT_B (2*TILE_B + 2*WTILE_B)  // gate slot: A hi/lo + W hi/lo (110592)

#define LDK8 144                   // padded fp8 row (bytes), K=128
#define TILE8_B (128*LDK8)         // 18432 = TILE_B

// ---------------- scratch (static device memory, no runtime allocation) ----
__device__ uint8_t g_F8[BATCH*CC];           // e4m3 exp(B_t)*mask[col]   [b][i][k]
__device__ uint8_t g_GT8[BATCH*CC];          // e4m3 exp(B_t)^T*mask[col] [b][j][k]
__device__ float g_sumF[BATCH*C];
__device__ float g_sumG[BATCH*C];
__device__ float g_sum2[BATCH*C];
__device__ __nv_bfloat16 g_E2[BATCH*CC];     // masked exp(B_new), single bf16
__device__ __nv_bfloat16 g_h1hi[CB*D];
__device__ __nv_bfloat16 g_h1lo[CB*D];
__device__ __nv_bfloat16 g_h2hi[CB*D];
__device__ __nv_bfloat16 g_h2lo[CB*D];
__device__ __nv_bfloat16 g_hThi[BATCH*D*C];  // [b][d][c]
__device__ __nv_bfloat16 g_hTlo[BATCH*D*C];
__device__ __nv_bfloat16 g_mhi[(size_t)CB*384]; // m' = [h, ht, h*ht]
__device__ __nv_bfloat16 g_mlo[(size_t)CB*384];
__device__ __nv_bfloat16 g_Whi[256*384];     // rows 0:128 -> Wr', 128:256 -> Wg'
__device__ __nv_bfloat16 g_Wlo[256*384];

// ----------------------------------------------------------------- helpers
__device__ __forceinline__ uint32_t smem_u32(const void* p) {
    uint32_t a;
    asm("{ .reg .u64 t; cvta.to.shared.u64 t, %1; cvt.u32.u64 %0, t; }" : "=r"(a) : "l"(p));
    return a;
}
__device__ __forceinline__ void mma16816(float* c, const uint32_t* a, const uint32_t* b) {
    asm volatile(
        "mma.sync.aligned.m16n8k16.row.col.f32.bf16.bf16.f32 "
        "{%0,%1,%2,%3}, {%4,%5,%6,%7}, {%8,%9}, {%0,%1,%2,%3};"
        : "+f"(c[0]), "+f"(c[1]), "+f"(c[2]), "+f"(c[3])
        : "r"(a[0]), "r"(a[1]), "r"(a[2]), "r"(a[3]), "r"(b[0]), "r"(b[1]));
}
__device__ __forceinline__ void mma16832f8(float* c, const uint32_t* a, const uint32_t* b) {
    asm volatile(
        "mma.sync.aligned.m16n8k32.row.col.f32.e4m3.e4m3.f32 "
        "{%0,%1,%2,%3}, {%4,%5,%6,%7}, {%8,%9}, {%0,%1,%2,%3};"
        : "+f"(c[0]), "+f"(c[1]), "+f"(c[2]), "+f"(c[3])
        : "r"(a[0]), "r"(a[1]), "r"(a[2]), "r"(a[3]), "r"(b[0]), "r"(b[1]));
}
__device__ __forceinline__ void ldsm4(uint32_t a, uint32_t* r) {
    asm volatile("ldmatrix.sync.aligned.m8n8.x4.shared.b16 {%0,%1,%2,%3}, [%4];"
        : "=r"(r[0]), "=r"(r[1]), "=r"(r[2]), "=r"(r[3]) : "r"(a));
}
__device__ __forceinline__ void cp16(uint32_t s, const void* g) {
    asm volatile("cp.async.cg.shared.global [%0], [%1], 16;" :: "r"(s), "l"(g));
}
#define CP_COMMIT() asm volatile("cp.async.commit_group;" ::: "memory")
#define CP_WAITN(n) asm volatile("cp.async.wait_group %0;" :: "n"(n) : "memory")

__device__ __forceinline__ void split2(float2 v, __nv_bfloat162& hi, __nv_bfloat162& lo) {
    hi.x = __float2bfloat16(v.x); lo.x = __float2bfloat16(v.x - __bfloat162float(hi.x));
    hi.y = __float2bfloat16(v.y); lo.y = __float2bfloat16(v.y - __bfloat162float(hi.y));
}
__device__ __forceinline__ uint8_t to_e4m3(float x) {
    return (uint8_t)__nv_cvt_float_to_fp8(x, __NV_SATFINITE, __NV_E4M3);
}

// ldmatrix per-lane address offsets (row stride LDKB=144 for all tiles)
__device__ __forceinline__ uint32_t a_lane_off(int warp_row, int lid) {
    int mi = lid >> 3, l7 = lid & 7;
    return (uint32_t)((warp_row + (mi & 1)*8 + l7)*LDKB + (mi >> 1)*16);
}
__device__ __forceinline__ uint32_t b_lane_off(int warp_col, int lid) {
    int mi = lid >> 3, l7 = lid & 7;
    return (uint32_t)((warp_col + (mi >> 1)*8 + l7)*LDKB + (mi & 1)*16);
}

// load one 2-tile bf16 chunk (A, B), 128 rows x 64 bf16 each
__device__ __forceinline__ void issue_single(
    uint32_t sb, int tid,
    const __nv_bfloat16* A, const __nv_bfloat16* Bp, size_t rs)
{
#pragma unroll
    for (int q = 0; q < 4; q++) {
        int idx = q*256 + tid;
        int row = idx >> 3, seg = idx & 7;
        size_t g = (size_t)row*rs + seg*8;
        uint32_t so = row*LDKB + seg*16;
        cp16(sb +          so, A  + g);
        cp16(sb + TILE_B + so, Bp + g);
    }
}

// load one 2-tile fp8 chunk (A, B), 128 rows x 128 e4m3 bytes each (K=128)
__device__ __forceinline__ void issue_fp8_128(
    uint32_t sb, int tid, const uint8_t* A, const uint8_t* Bp, size_t rs)
{
#pragma unroll
    for (int q = 0; q < 8; q++) {
        int idx = q*256 + tid;
        int tile = idx >> 10;
        int row  = (idx >> 3) & 127;
        int seg  = idx & 7;
        const uint8_t* src = tile ? Bp : A;
        cp16(sb + tile*TILE8_B + row*LDK8 + seg*16,
             src + (size_t)row*rs + seg*16);
    }
}

// load one 3-tile bf16 chunk (A, Bh, Bl), 128 rows x 64 bf16 each
__device__ __forceinline__ void issue_tiles3(
    uint32_t sb, int tid,
    const __nv_bfloat16* A,
    const __nv_bfloat16* Bh, const __nv_bfloat16* Bl,
    size_t rsA, size_t rsB)
{
#pragma unroll
    for (int q = 0; q < 4; q++) {
        int idx = q*256 + tid;
        int row = idx >> 3, seg = idx & 7;
        size_t gA = (size_t)row*rsA + seg*8;
        size_t gB = (size_t)row*rsB + seg*8;
        uint32_t so = row*LDKB + seg*16;
        cp16(sb +            so, A  + gA);
        cp16(sb +   TILE_B + so, Bh + gB);
        cp16(sb + 2*TILE_B + so, Bl + gB);
    }
}

// gate chunk load: A (m hi/lo, 128 rows) + W (hi/lo, 256 rows), 64 cols
__device__ __forceinline__ void issue_gate(
    uint32_t sb, int tid,
    const __nv_bfloat16* Ah, const __nv_bfloat16* Al,
    const __nv_bfloat16* Wh, const __nv_bfloat16* Wl)
{
#pragma unroll
    for (int q = 0; q < 4; q++) {
        int idx = q*256 + tid;
        int row = idx >> 3, seg = idx & 7;
        size_t g = (size_t)row*384 + seg*8;
        uint32_t so = row*LDKB + seg*16;
        cp16(sb +          so, Ah + g);
        cp16(sb + TILE_B + so, Al + g);
    }
#pragma unroll
    for (int q = 0; q < 8; q++) {
        int idx = q*256 + tid;
        int row = idx >> 3, seg = idx & 7;   // row 0..255
        size_t g = (size_t)row*384 + seg*8;
        uint32_t so = row*LDKB + seg*16;
        cp16(sb + 2*TILE_B +           so, Wh + g);
        cp16(sb + 2*TILE_B + WTILE_B + so, Wl + g);
    }
}

// bf16 single-precision chunk (K=64), ldmatrix operands
__device__ __forceinline__ void compute_chunk1(
    uint32_t sA, uint32_t sB, float acc[4][4][4], int wm, int wn, int lid)
{
    uint32_t aoff = sA + a_lane_off(wm*64, lid);
    uint32_t boff = sB + b_lane_off(wn*32, lid);
#pragma unroll
    for (int ks = 0; ks < 4; ks++) {
        uint32_t a[4][4], bb[2][4];
#pragma unroll
        for (int im = 0; im < 4; im++) ldsm4(aoff + im*(16*LDKB) + ks*32, a[im]);
#pragma unroll
        for (int p = 0; p < 2; p++)  ldsm4(boff + p*(16*LDKB) + ks*32, bb[p]);
#pragma unroll
        for (int im = 0; im < 4; im++)
#pragma unroll
            for (int jn = 0; jn < 4; jn++)
                mma16816(acc[im][jn], a[im], &bb[jn>>1][(jn&1)*2]);
    }
}

// fp8 chunk (K=128): 4 x m16n8k32 ksteps, ldmatrix operands
__device__ __forceinline__ void compute_chunk_fp8(
    uint32_t sA, uint32_t sB, float acc[4][4][4], int wm, int wn, int lid)
{
    uint32_t aoff = sA + a_lane_off(wm*64, lid);
    uint32_t boff = sB + b_lane_off(wn*32, lid);
#pragma unroll
    for (int ks = 0; ks < 4; ks++) {
        uint32_t a[4][4], bb[2][4];
#pragma unroll
        for (int im = 0; im < 4; im++) ldsm4(aoff + im*(16*LDKB) + ks*32, a[im]);
#pragma unroll
        for (int p = 0; p < 2; p++)  ldsm4(boff + p*(16*LDKB) + ks*32, bb[p]);
#pragma unroll
        for (int im = 0; im < 4; im++)
#pragma unroll
            for (int jn = 0; jn < 4; jn++)
                mma16832f8(acc[im][jn], a[im], &bb[jn>>1][(jn&1)*2]);
    }
}

// 2-mma chunk (A single, B hi/lo), 128x128 tile
__device__ __forceinline__ void compute_chunk2(
    uint32_t base, float acc[4][4][4], int wm, int wn, int lid)
{
    uint32_t aoff  = base +            a_lane_off(wm*64, lid);
    uint32_t boffh = base +   TILE_B + b_lane_off(wn*32, lid);
    uint32_t boffl = base + 2*TILE_B + b_lane_off(wn*32, lid);
#pragma unroll
    for (int ks = 0; ks < 4; ks++) {
        uint32_t a[4][4], bh[2][4], bl[2][4];
#pragma unroll
        for (int im = 0; im < 4; im++) ldsm4(aoff + im*(16*LDKB) + ks*32, a[im]);
#pragma unroll
        for (int p = 0; p < 2; p++) {
            ldsm4(boffh + p*(16*LDKB) + ks*32, bh[p]);
            ldsm4(boffl + p*(16*LDKB) + ks*32, bl[p]);
        }
#pragma unroll
        for (int im = 0; im < 4; im++)
#pragma unroll
            for (int jn = 0; jn < 4; jn++) {
                mma16816(acc[im][jn], a[im], &bh[jn>>1][(jn&1)*2]);
                mma16816(acc[im][jn], a[im], &bl[jn>>1][(jn&1)*2]);
            }
    }
}

// gate chunk: 3-mma split, A 128 rows, dual B (r rows 0:128, g rows 128:256)
__device__ __forceinline__ void compute_gate(
    uint32_t base, float accR[4][4][4], float accG[4][4][4],
    int wm, int wn, int lid)
{
    uint32_t aoffh = base +          a_lane_off(wm*64, lid);
    uint32_t aoffl = base + TILE_B + a_lane_off(wm*64, lid);
    uint32_t wh = base + 2*TILE_B;
    uint32_t wl = wh + WTILE_B;
    uint32_t bRh = wh + b_lane_off(wn*32, lid);
    uint32_t bGh = wh + b_lane_off(128 + wn*32, lid);
    uint32_t bRl = wl + b_lane_off(wn*32, lid);
    uint32_t bGl = wl + b_lane_off(128 + wn*32, lid);
#pragma unroll
    for (int ks = 0; ks < 4; ks++) {
        uint32_t ah[4][4], al[4][4];
        uint32_t rh[2][4], rl[2][4], gh[2][4], gl[2][4];
#pragma unroll
        for (int im = 0; im < 4; im++) {
            ldsm4(aoffh + im*(16*LDKB) + ks*32, ah[im]);
            ldsm4(aoffl + im*(16*LDKB) + ks*32, al[im]);
        }
#pragma unroll
        for (int p = 0; p < 2; p++) {
            ldsm4(bRh + p*(16*LDKB) + ks*32, rh[p]);
            ldsm4(bRl + p*(16*LDKB) + ks*32, rl[p]);
            ldsm4(bGh + p*(16*LDKB) + ks*32, gh[p]);
            ldsm4(bGl + p*(16*LDKB) + ks*32, gl[p]);
        }
#pragma unroll
        for (int im = 0; im < 4; im++)
#pragma unroll
            for (int jn = 0; jn < 4; jn++) {
                mma16816(accR[im][jn], ah[im], &rh[jn>>1][(jn&1)*2]);
                mma16816(accR[im][jn], ah[im], &rl[jn>>1][(jn&1)*2]);
                mma16816(accR[im][jn], al[im], &rh[jn>>1][(jn&1)*2]);
                mma16816(accG[im][jn], ah[im], &gh[jn>>1][(jn&1)*2]);
                mma16816(accG[im][jn], ah[im], &gl[jn>>1][(jn&1)*2]);
                mma16816(accG[im][jn], al[im], &gh[jn>>1][(jn&1)*2]);
            }
    }
}

// ---------------------------------------------------------------- FC kernel
__global__ void __launch_bounds__(256) fc_kernel(
    const float* __restrict__ h,
    const float* __restrict__ W1, const float* __restrict__ b1,
    const float* __restrict__ W2, const float* __restrict__ b2)
{
    __shared__ float As[16][64];
    __shared__ float Bs[16][64];
    int t  = threadIdx.x;
    int tx = t & 15, ty = t >> 4;
    int bm = blockIdx.x, bn = blockIdx.y;

    float acc[4][4] = {};
    int ar = t >> 2;
    int kc = (t & 3) << 2;
    int rowA = bm*64 + ar;
    int e    = bn*64 + ar;
    const float* Bptr = (e < 128) ? (W1 + e*128) : (W2 + (e-128)*128);

    for (int kt = 0; kt < 128; kt += 16) {
        float4 av = *(const float4*)(h + (size_t)rowA*128 + kt + kc);
        float4 bv = *(const float4*)(Bptr + kt + kc);
        As[kc+0][ar]=av.x; As[kc+1][ar]=av.y; As[kc+2][ar]=av.z; As[kc+3][ar]=av.w;
        Bs[kc+0][ar]=bv.x; Bs[kc+1][ar]=bv.y; Bs[kc+2][ar]=bv.z; Bs[kc+3][ar]=bv.w;
        __syncthreads();
#pragma unroll
        for (int k = 0; k < 16; k++) {
            float a[4], bb[4];
#pragma unroll
            for (int i = 0; i < 4; i++) a[i]  = As[k][ty*4+i];
#pragma unroll
            for (int j = 0; j < 4; j++) bb[j] = Bs[k][tx*4+j];
#pragma unroll
            for (int i = 0; i < 4; i++)
#pragma unroll
                for (int j = 0; j < 4; j++)
                    acc[i][j] += a[i]*bb[j];
        }
        __syncthreads();
    }

#pragma unroll
    for (int i = 0; i < 4; i++) {
        int r = bm*64 + ty*4 + i;
        int c = r >> 4, b = r & 15;
#pragma unroll
        for (int j = 0; j < 4; j++) {
            int ee = bn*64 + tx*4 + j;
            float bias = (ee < 128) ? b1[ee] : b2[ee-128];
            float v = acc[i][j] + bias;
            v = v > 0.f ? v : 0.f;
            __nv_bfloat16 hi = __float2bfloat16(v);
            __nv_bfloat16 lo = __float2bfloat16(v - __bfloat162float(hi));
            size_t idx = ((size_t)(b*C + c))*D + (ee & 127);
            if (ee < 128) { g_h1hi[idx] = hi; g_h1lo[idx] = lo; }
            else          { g_h2hi[idx] = hi; g_h2lo[idx] = lo; }
        }
    }
}

// ----------------- fused exp of B_t on 128x128 tiles (e4m3 smem tile) -------
#define LDT 132   // byte stride of the e4m3 tile
__global__ void __launch_bounds__(256) esplit_kernel(
    const float* __restrict__ Bt, const int* __restrict__ mask)
{
    __shared__ uint8_t tile[128*LDT];
    __shared__ float scol[128];
    int b  = blockIdx.z;
    int x0 = blockIdx.y * 128;
    int y0 = blockIdx.x * 128;
    int w = threadIdx.x >> 5, lid = threadIdx.x & 31;

    if (threadIdx.x < 128) scol[threadIdx.x] = 0.f;
    __syncthreads();

    int4 my4 = *(const int4*)(mask + b*C + y0 + lid*4);
    float yf0 = my4.x ? 1.f : 0.f, yf1 = my4.y ? 1.f : 0.f;
    float yf2 = my4.z ? 1.f : 0.f, yf3 = my4.w ? 1.f : 0.f;
    uint32_t ymask = (my4.x ? 0xFFu : 0) | (my4.y ? 0xFF00u : 0)
                   | (my4.z ? 0xFF0000u : 0) | (my4.w ? 0xFF000000u : 0);

    float gs0 = 0.f, gs1 = 0.f, gs2 = 0.f, gs3 = 0.f;
#pragma unroll 4
    for (int i = 0; i < 16; i++) {
        int xl = w*16 + i;
        int x = x0 + xl;
        float4 v = *(const float4*)(Bt + (size_t)b*CC + (size_t)x*C + y0 + lid*4);
        float e0 = __expf(v.x), e1 = __expf(v.y), e2 = __expf(v.z), e3 = __expf(v.w);
        float s = e0*yf0 + e1*yf1 + e2*yf2 + e3*yf3;
#pragma unroll
        for (int o = 16; o > 0; o >>= 1) s += __shfl_xor_sync(0xffffffffu, s, o);
        if (lid == 0) atomicAdd(g_sumF + b*C + x, s);
        uint32_t pk =  (uint32_t)to_e4m3(e0)        | ((uint32_t)to_e4m3(e1) << 8)
                    | ((uint32_t)to_e4m3(e2) << 16) | ((uint32_t)to_e4m3(e3) << 24);
        *(uint32_t*)(tile + xl*LDT + lid*4) = pk;
        *(uint32_t*)(g_F8 + (size_t)b*CC + (size_t)x*C + y0 + lid*4) = pk & ymask;
        float mrow = mask[b*C + x] ? 1.f : 0.f;
        gs0 += e0*mrow; gs1 += e1*mrow; gs2 += e2*mrow; gs3 += e3*mrow;
    }
    atomicAdd(&scol[lid*4 + 0], gs0);
    atomicAdd(&scol[lid*4 + 1], gs1);
    atomicAdd(&scol[lid*4 + 2], gs2);
    atomicAdd(&scol[lid*4 + 3], gs3);
    __syncthreads();
    if (threadIdx.x < 128)
        atomicAdd(g_sumG + b*C + y0 + threadIdx.x, scol[threadIdx.x]);

    int xq = lid*4;
    const int* mk = mask + b*C + x0 + xq;
    uint32_t xmask = (mk[0] ? 0xFFu : 0) | (mk[1] ? 0xFF00u : 0)
                   | (mk[2] ? 0xFF0000u : 0) | (mk[3] ? 0xFF000000u : 0);
#pragma unroll 4
    for (int i = 0; i < 16; i++) {
        int yl = w*16 + i;
        int y = y0 + yl;
        uint32_t pk =  (uint32_t)tile[(xq+0)*LDT + yl]
                    | ((uint32_t)tile[(xq+1)*LDT + yl] << 8)
                    | ((uint32_t)tile[(xq+2)*LDT + yl] << 16)
                    | ((uint32_t)tile[(xq+3)*LDT + yl] << 24);
        *(uint32_t*)(g_GT8 + (size_t)b*CC + (size_t)y*C + x0 + xq) = pk & xmask;
    }
}

// ------------------------------------ hT transpose: h(c,b,d) -> [b][d][c] hi/lo
__global__ void __launch_bounds__(256) ht_transpose_kernel(const float* __restrict__ h)
{
    __shared__ float tileT[32][33];
    int b  = blockIdx.z;
    int c0 = blockIdx.x * 32;
    int d0 = blockIdx.y * 32;
    int tx = threadIdx.x & 31, ty = threadIdx.x >> 5;

#pragma unroll
    for (int r = ty; r < 32; r += 8)
        tileT[r][tx] = h[(size_t)((c0 + r)*16 + b)*128 + d0 + tx];
    __syncthreads();
#pragma unroll
    for (int r = ty; r < 32; r += 8) {
        float x = tileT[tx][r];
        __nv_bfloat16 hi = __float2bfloat16(x);
        __nv_bfloat16 lo = __float2bfloat16(x - __bfloat162float(hi));
        size_t o = (size_t)b*D*C + (size_t)(d0 + r)*C + c0 + tx;
        g_hThi[o] = hi;
        g_hTlo[o] = lo;
    }
}

// --------- folded weight stack + sum zeroing --------------------------------
__global__ void __launch_bounds__(256) wsplit_kernel(
    const float* __restrict__ Wr, const float* __restrict__ Wg)
{
    int idx = blockIdx.x*256 + threadIdx.x;
    if (idx < 3*BATCH*C) {
        if (idx < BATCH*C)          g_sumF[idx] = 0.f;
        else if (idx < 2*BATCH*C)   g_sumG[idx - BATCH*C] = 0.f;
        else                        g_sum2[idx - 2*BATCH*C] = 0.f;
    }
    int n = idx / 384, k = idx % 384;
    const float* W = (n < 128) ? (Wr + n*512) : (Wg + (n-128)*512);
    float x;
    if (k < 128)       x = W[k] + W[384 + k];
    else if (k < 256)  x = W[k] - W[k + 256];     // W1 - W3
    else               x = W[k];
    __nv_bfloat16 hi = __float2bfloat16(x);
    g_Whi[idx] = hi;
    g_Wlo[idx] = __float2bfloat16(x - __bfloat162float(hi));
}

// ============================ B_new GEMM + fused softmax epilogue ===========
__global__ void __launch_bounds__(256, 2) bnew_mma_kernel(
    const float* __restrict__ gamma_p, const int* __restrict__ mask,
    float* __restrict__ out)
{
    extern __shared__ char smc[];
    __shared__ int   sMask[128];
    __shared__ float sRow[128];
    int tid = threadIdx.x, wid = tid >> 5, lid = tid & 31;
    int b = blockIdx.z, it = blockIdx.y, jt = blockIdx.x;
    int wm = wid & 1, wn = wid >> 1;
    uint32_t sb = smem_u32(smc);

    if (tid < 128) { sMask[tid] = mask[b*C + jt*128 + tid]; sRow[tid] = 0.f; }

    float acc[4][4][4] = {};
    float gma = gamma_p[0];
    int lrow = lid >> 2, lcol2 = (lid & 3) << 1;

    auto issue = [&](int c) {
        uint32_t slot = sb + (uint32_t)(c % 3)*BUF2_B;
        if (c < 8) {
            const uint8_t* A  = g_F8  + ((size_t)b*C + (size_t)it*128)*C + (size_t)c*128;
            const uint8_t* Bp = g_GT8 + ((size_t)b*C + (size_t)jt*128)*C + (size_t)c*128;
            issue_fp8_128(slot, tid, A, Bp, C);
        } else {
            int tm = (c - 8) >> 1, kh = (c - 8) & 1;
            const __nv_bfloat16* A1 = (tm < 2)  ? g_h1hi : g_h1lo;
            const __nv_bfloat16* B1 = (tm == 1) ? g_h2lo : g_h2hi;
            issue_single(slot, tid,
                         A1 + ((size_t)b*C + (size_t)it*128)*D + kh*64,
                         B1 + ((size_t)b*C + (size_t)jt*128)*D + kh*64, D);
        }
    };

    issue(0); CP_COMMIT();
    issue(1); CP_COMMIT();

    for (int c = 0; c < 14; c++) {
        if (c == 13) CP_WAITN(0); else CP_WAITN(1);
        __syncthreads();
        if (c == 8) {
            float invR[8], invCv[8];
#pragma unroll
            for (int im = 0; im < 4; im++) {
                int r = it*128 + wm*64 + lrow + im*16;
                invR[2*im]   = gma / g_sumF[b*C + r];
                invR[2*im+1] = gma / g_sumF[b*C + r + 8];
            }
#pragma unroll
            for (int jn = 0; jn < 4; jn++) {
                int cj = jt*128 + wn*32 + lcol2 + jn*8;
                invCv[2*jn]   = 1.0f / g_sumG[b*C + cj];
                invCv[2*jn+1] = 1.0f / g_sumG[b*C + cj + 1];
            }
#pragma unroll
            for (int im = 0; im < 4; im++)
#pragma unroll
                for (int jn = 0; jn < 4; jn++) {
                    acc[im][jn][0] *= invR[2*im]   * invCv[2*jn];
                    acc[im][jn][1] *= invR[2*im]   * invCv[2*jn+1];
                    acc[im][jn][2] *= invR[2*im+1] * invCv[2*jn];
                    acc[im][jn][3] *= invR[2*im+1] * invCv[2*jn+1];
                }
        }
        if (c + 2 < 14) { issue(c + 2); CP_COMMIT(); }
        uint32_t base = sb + (uint32_t)(c % 3)*BUF2_B;
        if (c < 8) compute_chunk_fp8(base, base + TILE8_B, acc, wm, wn, lid);
        else       compute_chunk1(base, base + TILE_B, acc, wm, wn, lid);
    }

    // ---- epilogue: diag zero, store fp32, fused masked exp (single bf16) ----
    int gi0 = it*128 + wm*64 + lrow;
    int gj0 = jt*128 + wn*32 + lcol2;
    float* obase = out + (size_t)b*CC;
#pragma unroll
    for (int im = 0; im < 4; im++) {
        int r = gi0 + im*16;
        float rp0 = 0.f, rp1 = 0.f;
#pragma unroll
        for (int jn = 0; jn < 4; jn++) {
            int cj = gj0 + jn*8;
            int lc = wn*32 + lcol2 + jn*8;
            float2 v0 = make_float2(acc[im][jn][0], acc[im][jn][1]);
            float2 v1 = make_float2(acc[im][jn][2], acc[im][jn][3]);
            if (r == cj)        v0.x = 0.f;
            else if (r == cj+1) v0.y = 0.f;
            if (r+8 == cj)      v1.x = 0.f;
            else if (r+8 == cj+1) v1.y = 0.f;
            *(float2*)(obase + (size_t)r*C + cj)     = v0;
            *(float2*)(obase + (size_t)(r+8)*C + cj) = v1;

            int m0 = sMask[lc], m1 = sMask[lc+1];
            float2 e0 = make_float2(m0 ? __expf(v0.x) : 0.f, m1 ? __expf(v0.y) : 0.f);
            float2 e1 = make_float2(m0 ? __expf(v1.x) : 0.f, m1 ? __expf(v1.y) : 0.f);
            rp0 += e0.x + e0.y;
            rp1 += e1.x + e1.y;
            __nv_bfloat162 q0, q1;
            q0.x = __float2bfloat16(e0.x); q0.y = __float2bfloat16(e0.y);
            q1.x = __float2bfloat16(e1.x); q1.y = __float2bfloat16(e1.y);
            *(__nv_bfloat162*)(g_E2 + (size_t)b*CC + (size_t)r*C + cj)     = q0;
            *(__nv_bfloat162*)(g_E2 + (size_t)b*CC + (size_t)(r+8)*C + cj) = q1;
        }
        atomicAdd(&sRow[wm*64 + lrow + im*16],     rp0);
        atomicAdd(&sRow[wm*64 + lrow + im*16 + 8], rp1);
    }
    __syncthreads();
    if (tid < 128) atomicAdd(g_sum2 + b*C + it*128 + tid, sRow[tid]);
}

// ============================ h_tmp GEMM (M=128, 2-mma) + m' construction ====
__global__ void __launch_bounds__(256) htmp_mma_kernel(const float* __restrict__ h)
{
    extern __shared__ char smc[];
    int tid = threadIdx.x, wid = tid >> 5, lid = tid & 31;
    int it = blockIdx.x, b = blockIdx.y;
    int wm = wid & 1, wn = wid >> 1;
    uint32_t sb = smem_u32(smc);

    float acc[4][4][4] = {};

    auto issue = [&](int c) {
        size_t offA = ((size_t)b*C + (size_t)it*128)*C + (size_t)c*64;
        size_t offB = (size_t)b*D*C + (size_t)c*64;
        issue_tiles3(sb + (uint32_t)(c % 3)*BUF3_B, tid,
                     g_E2 + offA,
                     g_hThi + offB, g_hTlo + offB, C, C);
    };

    issue(0); CP_COMMIT();
    issue(1); CP_COMMIT();
    for (int c = 0; c < 16; c++) {
        if (c == 15) CP_WAITN(0); else CP_WAITN(1);
        __syncthreads();
        if (c + 2 < 16) { issue(c + 2); CP_COMMIT(); }
        compute_chunk2(sb + (uint32_t)(c % 3)*BUF3_B, acc, wm, wn, lid);
    }

    int lrow = lid >> 2, lcol2 = (lid & 3) << 1;
    int ci0 = it*128 + wm*64 + lrow;
    int d0  = wn*32 + lcol2;
#pragma unroll
    for (int im = 0; im < 4; im++) {
#pragma unroll
        for (int half = 0; half < 2; half++) {
            int cg = ci0 + im*16 + half*8;
            int r  = cg*16 + b;
            float inv = 1.0f / g_sum2[b*C + cg];
#pragma unroll
            for (int jn = 0; jn < 4; jn++) {
                int dj = d0 + jn*8;
                float2 ht = half ? make_float2(acc[im][jn][2], acc[im][jn][3])
                                 : make_float2(acc[im][jn][0], acc[im][jn][1]);
                ht.x *= inv; ht.y *= inv;
                float2 hv = *(const float2*)(h + (size_t)r*128 + dj);
                float2 seg[3];
                seg[0] = hv;
                seg[1] = ht;
                seg[2] = make_float2(hv.x*ht.x, hv.y*ht.y);
#pragma unroll
                for (int s = 0; s < 3; s++) {
                    __nv_bfloat162 hi, lo;
                    split2(seg[s], hi, lo);
                    size_t o = (size_t)r*384 + s*128 + dj;
                    *(__nv_bfloat162*)(g_mhi + o) = hi;
                    *(__nv_bfloat162*)(g_mlo + o) = lo;
                }
            }
        }
    }
}

// ======== fused gate GEMM + combine: o = relu(m.Wr')*sig(m.Wg') + (1-sig)*h ==
// one CTA: 128 rows x both 128-col halves; ring-2 slots, distance-1 overlap
__global__ void __launch_bounds__(256) gate_mma_kernel(
    const float* __restrict__ h, float* __restrict__ o)
{
    extern __shared__ char smc[];
    int tid = threadIdx.x, wid = tid >> 5, lid = tid & 31;
    int bm = blockIdx.x;
    int wm = wid & 1, wn = wid >> 1;
    uint32_t sb = smem_u32(smc);

    float accR[4][4][4] = {}, accG[4][4][4] = {};

    auto issue = [&](int c) {
        size_t offA = ((size_t)bm*128)*384 + (size_t)c*64;
        size_t offW = (size_t)c*64;
        issue_gate(sb + (uint32_t)(c & 1)*GSLOT_B, tid,
                   g_mhi + offA, g_mlo + offA,
                   g_Whi + offW, g_Wlo + offW);
    };

    issue(0); CP_COMMIT();
    for (int c = 0; c < 6; c++) {
        CP_WAITN(0);
        __syncthreads();
        if (c + 1 < 6) { issue(c + 1); CP_COMMIT(); }
        compute_gate(sb + (uint32_t)(c & 1)*GSLOT_B, accR, accG, wm, wn, lid);
    }

    int lrow = lid >> 2, lcol2 = (lid & 3) << 1;
    int r0 = bm*128 + wm*64 + lrow;
#pragma unroll
    for (int im = 0; im < 4; im++) {
#pragma unroll
        for (int half = 0; half < 2; half++) {
            int r = r0 + im*16 + half*8;
#pragma unroll
            for (int jn = 0; jn < 4; jn++) {
                int dj = wn*32 + jn*8 + lcol2;
                float zr0 = accR[im][jn][half*2],     zr1 = accR[im][jn][half*2+1];
                float zg0 = accG[im][jn][half*2],     zg1 = accG[im][jn][half*2+1];
                float2 hv = *(const float2*)(h + (size_t)r*128 + dj);
                float x0 = fmaxf(zr0, 0.f), s0 = 1.0f/(1.0f + __expf(-zg0));
                float x1 = fmaxf(zr1, 0.f), s1 = 1.0f/(1.0f + __expf(-zg1));
                float2 ov;
                ov.x = x0*s0 + (1.0f - s0)*hv.x;
                ov.y = x1*s1 + (1.0f - s1)*hv.y;
                *(float2*)(o + (size_t)r*128 + dj) = ov;
            }
        }
    }
}

// ---------------------------------------------------------------------------
extern "C" void kernel_launch(void* const* d_in, const int* in_sizes, int n_in,
                              void* d_out, int out_size)
{
    const float* h   = (const float*)d_in[0];
    const int*   hm  = (const int*)  d_in[1];
    const float* Bt  = (const float*)d_in[2];
    const float* W1w = (const float*)d_in[3];
    const float* W1b = (const float*)d_in[4];
    const float* W2w = (const float*)d_in[5];
    const float* W2b = (const float*)d_in[6];
    const float* gam = (const float*)d_in[7];
    const float* Wrw = (const float*)d_in[8];
    const float* Wgw = (const float*)d_in[9];

    float* o_out    = (float*)d_out;
    float* bnew_out = (float*)d_out + (size_t)CB*D;

    const int BNEW_SMEM = 3*BUF2_B;        // 110592 -> 2 CTAs/SM
    const int HTMP_SMEM = 3*BUF3_B;        // 165888 -> 1 CTA/SM, ring-3
    const int GATE_SMEM = 2*GSLOT_B;       // 221184 -> 1 CTA/SM, ring-2
    cudaFuncSetAttribute(bnew_mma_kernel, cudaFuncAttributeMaxDynamicSharedMemorySize, BNEW_SMEM);
    cudaFuncSetAttribute(htmp_mma_kernel, cudaFuncAttributeMaxDynamicSharedMemorySize, HTMP_SMEM);
    cudaFuncSetAttribute(gate_mma_kernel, cudaFuncAttributeMaxDynamicSharedMemorySize, GATE_SMEM);

    wsplit_kernel<<<256*384/256, 256>>>(Wrw, Wgw);   // also zeroes sums
    fc_kernel<<<dim3(CB/64, 4), 256>>>(h, W1w, W1b, W2w, W2b);
    ht_transpose_kernel<<<dim3(C/32, D/32, BATCH), 256>>>(h);
    esplit_kernel<<<dim3(8, 8, BATCH), 256>>>(Bt, hm);
    bnew_mma_kernel<<<dim3(C/128, C/128, BATCH), 256, BNEW_SMEM>>>(gam, hm, bnew_out);
    htmp_mma_kernel<<<dim3(C/128, BATCH), 256, HTMP_SMEM>>>(h);
    gate_mma_kernel<<<CB/128, 256, GATE_SMEM>>>(h, o_out);
}

// round 16
// speedup vs baseline: 1.2914x; 1.0751x over previous
#include <cuda_runtime.h>
#include <cuda_bf16.h>
#include <cuda_fp8.h>
#include <math.h>
#include <cstdint>

#define C 1024
#define BATCH 16
#define D 128
#define CB (C*BATCH)
#define CC (C*C)

#define LDK 72                     // padded SMEM row (bf16 elems) -> 144 bytes
#define LDKB 144                   // row stride in bytes (shared by bf16 & fp8)
#define TILE_E (128*LDK)           // elems per 128-row bf16 tile
#define TILE_B (TILE_E*2)          // bytes per 128-row bf16 tile (18432)
#define WTILE_B (2*TILE_B)         // 256-row bf16 tile (36864)
#define BUF2_B (2*TILE_B)          // 2-tile slot bytes (36864)
#define BUF3_B (3*TILE_B)          // 3-tile slot bytes (55296)
#define GSLOT_B (2*TILE_B + 2*WTILE_B)  // A hi/lo + 256-row W hi/lo (110592)

#define LDK8 144                   // padded fp8 row (bytes), K=128
#define TILE8_B (128*LDK8)         // 18432 = TILE_B

// ---------------- scratch (static device memory, no runtime allocation) ----
__device__ uint8_t g_F8[BATCH*CC];           // e4m3 exp(B_t)*mask[col]   [b][i][k]
__device__ uint8_t g_GT8[BATCH*CC];          // e4m3 exp(B_t)^T*mask[col] [b][j][k]
__device__ float g_sumF[BATCH*C];
__device__ float g_sumG[BATCH*C];
__device__ float g_sum2[BATCH*C];
__device__ __nv_bfloat16 g_E2[BATCH*CC];     // masked exp(B_new), single bf16
__device__ __nv_bfloat16 g_hhi[CB*D];        // h rows r=c*16+b, hi/lo
__device__ __nv_bfloat16 g_hlo[CB*D];
__device__ __nv_bfloat16 g_h1hi[CB*D];       // [b][c][d]
__device__ __nv_bfloat16 g_h1lo[CB*D];
__device__ __nv_bfloat16 g_h2hi[CB*D];
__device__ __nv_bfloat16 g_h2lo[CB*D];
__device__ __nv_bfloat16 g_hThi[BATCH*D*C];  // [b][d][c]
__device__ __nv_bfloat16 g_hTlo[BATCH*D*C];
__device__ __nv_bfloat16 g_mhi[(size_t)CB*384]; // m' = [h, ht, h*ht]
__device__ __nv_bfloat16 g_mlo[(size_t)CB*384];
__device__ __nv_bfloat16 g_Whi[256*384];     // gate W': rows 0:128 Wr', 128:256 Wg'
__device__ __nv_bfloat16 g_Wlo[256*384];
__device__ __nv_bfloat16 g_Vhi[256*128];     // fc W: rows 0:128 W1, 128:256 W2
__device__ __nv_bfloat16 g_Vlo[256*128];
__device__ float g_bias[256];                // [b1; b2]

// ----------------------------------------------------------------- helpers
__device__ __forceinline__ uint32_t smem_u32(const void* p) {
    uint32_t a;
    asm("{ .reg .u64 t; cvta.to.shared.u64 t, %1; cvt.u32.u64 %0, t; }" : "=r"(a) : "l"(p));
    return a;
}
__device__ __forceinline__ void mma16816(float* c, const uint32_t* a, const uint32_t* b) {
    asm volatile(
        "mma.sync.aligned.m16n8k16.row.col.f32.bf16.bf16.f32 "
        "{%0,%1,%2,%3}, {%4,%5,%6,%7}, {%8,%9}, {%0,%1,%2,%3};"
        : "+f"(c[0]), "+f"(c[1]), "+f"(c[2]), "+f"(c[3])
        : "r"(a[0]), "r"(a[1]), "r"(a[2]), "r"(a[3]), "r"(b[0]), "r"(b[1]));
}
__device__ __forceinline__ void mma16832f8(float* c, const uint32_t* a, const uint32_t* b) {
    asm volatile(
        "mma.sync.aligned.m16n8k32.row.col.f32.e4m3.e4m3.f32 "
        "{%0,%1,%2,%3}, {%4,%5,%6,%7}, {%8,%9}, {%0,%1,%2,%3};"
        : "+f"(c[0]), "+f"(c[1]), "+f"(c[2]), "+f"(c[3])
        : "r"(a[0]), "r"(a[1]), "r"(a[2]), "r"(a[3]), "r"(b[0]), "r"(b[1]));
}
__device__ __forceinline__ void ldsm4(uint32_t a, uint32_t* r) {
    asm volatile("ldmatrix.sync.aligned.m8n8.x4.shared.b16 {%0,%1,%2,%3}, [%4];"
        : "=r"(r[0]), "=r"(r[1]), "=r"(r[2]), "=r"(r[3]) : "r"(a));
}
__device__ __forceinline__ void cp16(uint32_t s, const void* g) {
    asm volatile("cp.async.cg.shared.global [%0], [%1], 16;" :: "r"(s), "l"(g));
}
#define CP_COMMIT() asm volatile("cp.async.commit_group;" ::: "memory")
#define CP_WAITN(n) asm volatile("cp.async.wait_group %0;" :: "n"(n) : "memory")

__device__ __forceinline__ void split2(float2 v, __nv_bfloat162& hi, __nv_bfloat162& lo) {
    hi.x = __float2bfloat16(v.x); lo.x = __float2bfloat16(v.x - __bfloat162float(hi.x));
    hi.y = __float2bfloat16(v.y); lo.y = __float2bfloat16(v.y - __bfloat162float(hi.y));
}
__device__ __forceinline__ uint8_t to_e4m3(float x) {
    return (uint8_t)__nv_cvt_float_to_fp8(x, __NV_SATFINITE, __NV_E4M3);
}

// ldmatrix per-lane address offsets (row stride LDKB=144 for all tiles)
__device__ __forceinline__ uint32_t a_lane_off(int warp_row, int lid) {
    int mi = lid >> 3, l7 = lid & 7;
    return (uint32_t)((warp_row + (mi & 1)*8 + l7)*LDKB + (mi >> 1)*16);
}
__device__ __forceinline__ uint32_t b_lane_off(int warp_col, int lid) {
    int mi = lid >> 3, l7 = lid & 7;
    return (uint32_t)((warp_col + (mi >> 1)*8 + l7)*LDKB + (mi & 1)*16);
}

// load one 2-tile bf16 chunk (A, B), 128 rows x 64 bf16 each
__device__ __forceinline__ void issue_single(
    uint32_t sb, int tid,
    const __nv_bfloat16* A, const __nv_bfloat16* Bp, size_t rs)
{
#pragma unroll
    for (int q = 0; q < 4; q++) {
        int idx = q*256 + tid;
        int row = idx >> 3, seg = idx & 7;
        size_t g = (size_t)row*rs + seg*8;
        uint32_t so = row*LDKB + seg*16;
        cp16(sb +          so, A  + g);
        cp16(sb + TILE_B + so, Bp + g);
    }
}

// load one 2-tile fp8 chunk (A, B), 128 rows x 128 e4m3 bytes each (K=128)
__device__ __forceinline__ void issue_fp8_128(
    uint32_t sb, int tid, const uint8_t* A, const uint8_t* Bp, size_t rs)
{
#pragma unroll
    for (int q = 0; q < 8; q++) {
        int idx = q*256 + tid;
        int tile = idx >> 10;
        int row  = (idx >> 3) & 127;
        int seg  = idx & 7;
        const uint8_t* src = tile ? Bp : A;
        cp16(sb + tile*TILE8_B + row*LDK8 + seg*16,
             src + (size_t)row*rs + seg*16);
    }
}

// load one 3-tile bf16 chunk (A, Bh, Bl), 128 rows x 64 bf16 each
__device__ __forceinline__ void issue_tiles3(
    uint32_t sb, int tid,
    const __nv_bfloat16* A,
    const __nv_bfloat16* Bh, const __nv_bfloat16* Bl,
    size_t rsA, size_t rsB)
{
#pragma unroll
    for (int q = 0; q < 4; q++) {
        int idx = q*256 + tid;
        int row = idx >> 3, seg = idx & 7;
        size_t gA = (size_t)row*rsA + seg*8;
        size_t gB = (size_t)row*rsB + seg*8;
        uint32_t so = row*LDKB + seg*16;
        cp16(sb +            so, A  + gA);
        cp16(sb +   TILE_B + so, Bh + gB);
        cp16(sb + 2*TILE_B + so, Bl + gB);
    }
}

// gate/fc chunk load: A (hi/lo, 128 rows) + W (hi/lo, 256 rows), 64 cols, stride rs
__device__ __forceinline__ void issue_gate(
    uint32_t sb, int tid,
    const __nv_bfloat16* Ah, const __nv_bfloat16* Al,
    const __nv_bfloat16* Wh, const __nv_bfloat16* Wl, size_t rs)
{
#pragma unroll
    for (int q = 0; q < 4; q++) {
        int idx = q*256 + tid;
        int row = idx >> 3, seg = idx & 7;
        size_t g = (size_t)row*rs + seg*8;
        uint32_t so = row*LDKB + seg*16;
        cp16(sb +          so, Ah + g);
        cp16(sb + TILE_B + so, Al + g);
    }
#pragma unroll
    for (int q = 0; q < 8; q++) {
        int idx = q*256 + tid;
        int row = idx >> 3, seg = idx & 7;   // row 0..255
        size_t g = (size_t)row*rs + seg*8;
        uint32_t so = row*LDKB + seg*16;
        cp16(sb + 2*TILE_B +           so, Wh + g);
        cp16(sb + 2*TILE_B + WTILE_B + so, Wl + g);
    }
}

// bf16 single-precision chunk (K=64), ldmatrix operands
__device__ __forceinline__ void compute_chunk1(
    uint32_t sA, uint32_t sB, float acc[4][4][4], int wm, int wn, int lid)
{
    uint32_t aoff = sA + a_lane_off(wm*64, lid);
    uint32_t boff = sB + b_lane_off(wn*32, lid);
#pragma unroll
    for (int ks = 0; ks < 4; ks++) {
        uint32_t a[4][4], bb[2][4];
#pragma unroll
        for (int im = 0; im < 4; im++) ldsm4(aoff + im*(16*LDKB) + ks*32, a[im]);
#pragma unroll
        for (int p = 0; p < 2; p++)  ldsm4(boff + p*(16*LDKB) + ks*32, bb[p]);
#pragma unroll
        for (int im = 0; im < 4; im++)
#pragma unroll
            for (int jn = 0; jn < 4; jn++)
                mma16816(acc[im][jn], a[im], &bb[jn>>1][(jn&1)*2]);
    }
}

// fp8 chunk (K=128): 4 x m16n8k32 ksteps, ldmatrix operands
__device__ __forceinline__ void compute_chunk_fp8(
    uint32_t sA, uint32_t sB, float acc[4][4][4], int wm, int wn, int lid)
{
    uint32_t aoff = sA + a_lane_off(wm*64, lid);
    uint32_t boff = sB + b_lane_off(wn*32, lid);
#pragma unroll
    for (int ks = 0; ks < 4; ks++) {
        uint32_t a[4][4], bb[2][4];
#pragma unroll
        for (int im = 0; im < 4; im++) ldsm4(aoff + im*(16*LDKB) + ks*32, a[im]);
#pragma unroll
        for (int p = 0; p < 2; p++)  ldsm4(boff + p*(16*LDKB) + ks*32, bb[p]);
#pragma unroll
        for (int im = 0; im < 4; im++)
#pragma unroll
            for (int jn = 0; jn < 4; jn++)
                mma16832f8(acc[im][jn], a[im], &bb[jn>>1][(jn&1)*2]);
    }
}

// 2-mma chunk (A single, B hi/lo), 128x128 tile
__device__ __forceinline__ void compute_chunk2(
    uint32_t base, float acc[4][4][4], int wm, int wn, int lid)
{
    uint32_t aoff  = base +            a_lane_off(wm*64, lid);
    uint32_t boffh = base +   TILE_B + b_lane_off(wn*32, lid);
    uint32_t boffl = base + 2*TILE_B + b_lane_off(wn*32, lid);
#pragma unroll
    for (int ks = 0; ks < 4; ks++) {
        uint32_t a[4][4], bh[2][4], bl[2][4];
#pragma unroll
        for (int im = 0; im < 4; im++) ldsm4(aoff + im*(16*LDKB) + ks*32, a[im]);
#pragma unroll
        for (int p = 0; p < 2; p++) {
            ldsm4(boffh + p*(16*LDKB) + ks*32, bh[p]);
            ldsm4(boffl + p*(16*LDKB) + ks*32, bl[p]);
        }
#pragma unroll
        for (int im = 0; im < 4; im++)
#pragma unroll
            for (int jn = 0; jn < 4; jn++) {
                mma16816(acc[im][jn], a[im], &bh[jn>>1][(jn&1)*2]);
                mma16816(acc[im][jn], a[im], &bl[jn>>1][(jn&1)*2]);
            }
    }
}

// gate/fc chunk: 3-mma split, A 128 rows, dual B (rows 0:128 -> R, 128:256 -> G)
__device__ __forceinline__ void compute_gate(
    uint32_t base, float accR[4][4][4], float accG[4][4][4],
    int wm, int wn, int lid)
{
    uint32_t aoffh = base +          a_lane_off(wm*64, lid);
    uint32_t aoffl = base + TILE_B + a_lane_off(wm*64, lid);
    uint32_t wh = base + 2*TILE_B;
    uint32_t wl = wh + WTILE_B;
    uint32_t bRh = wh + b_lane_off(wn*32, lid);
    uint32_t bGh = wh + b_lane_off(128 + wn*32, lid);
    uint32_t bRl = wl + b_lane_off(wn*32, lid);
    uint32_t bGl = wl + b_lane_off(128 + wn*32, lid);
#pragma unroll
    for (int ks = 0; ks < 4; ks++) {
        uint32_t ah[4][4], al[4][4];
        uint32_t rh[2][4], rl[2][4], gh[2][4], gl[2][4];
#pragma unroll
        for (int im = 0; im < 4; im++) {
            ldsm4(aoffh + im*(16*LDKB) + ks*32, ah[im]);
            ldsm4(aoffl + im*(16*LDKB) + ks*32, al[im]);
        }
#pragma unroll
        for (int p = 0; p < 2; p++) {
            ldsm4(bRh + p*(16*LDKB) + ks*32, rh[p]);
            ldsm4(bRl + p*(16*LDKB) + ks*32, rl[p]);
            ldsm4(bGh + p*(16*LDKB) + ks*32, gh[p]);
            ldsm4(bGl + p*(16*LDKB) + ks*32, gl[p]);
        }
#pragma unroll
        for (int im = 0; im < 4; im++)
#pragma unroll
            for (int jn = 0; jn < 4; jn++) {
                mma16816(accR[im][jn], ah[im], &rh[jn>>1][(jn&1)*2]);
                mma16816(accR[im][jn], ah[im], &rl[jn>>1][(jn&1)*2]);
                mma16816(accR[im][jn], al[im], &rh[jn>>1][(jn&1)*2]);
                mma16816(accG[im][jn], ah[im], &gh[jn>>1][(jn&1)*2]);
                mma16816(accG[im][jn], ah[im], &gl[jn>>1][(jn&1)*2]);
                mma16816(accG[im][jn], al[im], &gh[jn>>1][(jn&1)*2]);
            }
    }
}

// ----------------- fused exp of B_t on 128x128 tiles (e4m3 smem tile) -------
#define LDT 132   // byte stride of the e4m3 tile
__global__ void __launch_bounds__(256) esplit_kernel(
    const float* __restrict__ Bt, const int* __restrict__ mask)
{
    __shared__ uint8_t tile[128*LDT];
    __shared__ float scol[128];
    int b  = blockIdx.z;
    int x0 = blockIdx.y * 128;
    int y0 = blockIdx.x * 128;
    int w = threadIdx.x >> 5, lid = threadIdx.x & 31;

    if (threadIdx.x < 128) scol[threadIdx.x] = 0.f;
    __syncthreads();

    int4 my4 = *(const int4*)(mask + b*C + y0 + lid*4);
    float yf0 = my4.x ? 1.f : 0.f, yf1 = my4.y ? 1.f : 0.f;
    float yf2 = my4.z ? 1.f : 0.f, yf3 = my4.w ? 1.f : 0.f;
    uint32_t ymask = (my4.x ? 0xFFu : 0) | (my4.y ? 0xFF00u : 0)
                   | (my4.z ? 0xFF0000u : 0) | (my4.w ? 0xFF000000u : 0);

    float gs0 = 0.f, gs1 = 0.f, gs2 = 0.f, gs3 = 0.f;
#pragma unroll 4
    for (int i = 0; i < 16; i++) {
        int xl = w*16 + i;
        int x = x0 + xl;
        float4 v = *(const float4*)(Bt + (size_t)b*CC + (size_t)x*C + y0 + lid*4);
        float e0 = __expf(v.x), e1 = __expf(v.y), e2 = __expf(v.z), e3 = __expf(v.w);
        float s = e0*yf0 + e1*yf1 + e2*yf2 + e3*yf3;
#pragma unroll
        for (int o = 16; o > 0; o >>= 1) s += __shfl_xor_sync(0xffffffffu, s, o);
        if (lid == 0) atomicAdd(g_sumF + b*C + x, s);
        uint32_t pk =  (uint32_t)to_e4m3(e0)        | ((uint32_t)to_e4m3(e1) << 8)
                    | ((uint32_t)to_e4m3(e2) << 16) | ((uint32_t)to_e4m3(e3) << 24);
        *(uint32_t*)(tile + xl*LDT + lid*4) = pk;
        *(uint32_t*)(g_F8 + (size_t)b*CC + (size_t)x*C + y0 + lid*4) = pk & ymask;
        float mrow = mask[b*C + x] ? 1.f : 0.f;
        gs0 += e0*mrow; gs1 += e1*mrow; gs2 += e2*mrow; gs3 += e3*mrow;
    }
    atomicAdd(&scol[lid*4 + 0], gs0);
    atomicAdd(&scol[lid*4 + 1], gs1);
    atomicAdd(&scol[lid*4 + 2], gs2);
    atomicAdd(&scol[lid*4 + 3], gs3);
    __syncthreads();
    if (threadIdx.x < 128)
        atomicAdd(g_sumG + b*C + y0 + threadIdx.x, scol[threadIdx.x]);

    int xq = lid*4;
    const int* mk = mask + b*C + x0 + xq;
    uint32_t xmask = (mk[0] ? 0xFFu : 0) | (mk[1] ? 0xFF00u : 0)
                   | (mk[2] ? 0xFF0000u : 0) | (mk[3] ? 0xFF000000u : 0);
#pragma unroll 4
    for (int i = 0; i < 16; i++) {
        int yl = w*16 + i;
        int y = y0 + yl;
        uint32_t pk =  (uint32_t)tile[(xq+0)*LDT + yl]
                    | ((uint32_t)tile[(xq+1)*LDT + yl] << 8)
                    | ((uint32_t)tile[(xq+2)*LDT + yl] << 16)
                    | ((uint32_t)tile[(xq+3)*LDT + yl] << 24);
        *(uint32_t*)(g_GT8 + (size_t)b*CC + (size_t)y*C + x0 + xq) = pk & xmask;
    }
}

// --------- hT transpose + fused h hi/lo split: h(c,b,d) -> [b][d][c] & rows --
__global__ void __launch_bounds__(256) ht_transpose_kernel(const float* __restrict__ h)
{
    __shared__ float tileT[32][33];
    int b  = blockIdx.z;
    int c0 = blockIdx.x * 32;
    int d0 = blockIdx.y * 32;
    int tx = threadIdx.x & 31, ty = threadIdx.x >> 5;

#pragma unroll
    for (int r = ty; r < 32; r += 8) {
        size_t hidx = (size_t)((c0 + r)*16 + b)*128 + d0 + tx;
        float x = h[hidx];
        tileT[r][tx] = x;
        __nv_bfloat16 hi = __float2bfloat16(x);
        g_hhi[hidx] = hi;
        g_hlo[hidx] = __float2bfloat16(x - __bfloat162float(hi));
    }
    __syncthreads();
#pragma unroll
    for (int r = ty; r < 32; r += 8) {
        float x = tileT[tx][r];
        __nv_bfloat16 hi = __float2bfloat16(x);
        __nv_bfloat16 lo = __float2bfloat16(x - __bfloat162float(hi));
        size_t o = (size_t)b*D*C + (size_t)(d0 + r)*C + c0 + tx;
        g_hThi[o] = hi;
        g_hTlo[o] = lo;
    }
}

// --------- weight folds (gate W' + fc V + bias) + sum zeroing ----------------
__global__ void __launch_bounds__(256) wsplit_kernel(
    const float* __restrict__ Wr, const float* __restrict__ Wg,
    const float* __restrict__ W1, const float* __restrict__ W2,
    const float* __restrict__ b1, const float* __restrict__ b2)
{
    int idx = blockIdx.x*256 + threadIdx.x;      // 0 .. 98303
    if (idx < 3*BATCH*C) {
        if (idx < BATCH*C)          g_sumF[idx] = 0.f;
        else if (idx < 2*BATCH*C)   g_sumG[idx - BATCH*C] = 0.f;
        else                        g_sum2[idx - 2*BATCH*C] = 0.f;
    }
    if (idx < 256*128) {                         // fc weight split
        int n = idx >> 7, k = idx & 127;
        float x = (n < 128) ? W1[n*128 + k] : W2[(n-128)*128 + k];
        __nv_bfloat16 hi = __float2bfloat16(x);
        g_Vhi[idx] = hi;
        g_Vlo[idx] = __float2bfloat16(x - __bfloat162float(hi));
    }
    if (idx < 256) g_bias[idx] = (idx < 128) ? b1[idx] : b2[idx - 128];

    int n = idx / 384, k = idx % 384;
    const float* W = (n < 128) ? (Wr + n*512) : (Wg + (n-128)*512);
    float x;
    if (k < 128)       x = W[k] + W[384 + k];
    else if (k < 256)  x = W[k] - W[k + 256];     // W1 - W3
    else               x = W[k];
    __nv_bfloat16 hi = __float2bfloat16(x);
    g_Whi[idx] = hi;
    g_Wlo[idx] = __float2bfloat16(x - __bfloat162float(hi));
}

// ============ fc GEMM (mma): h1/h2 = relu(h.[W1;W2]^T + bias) ================
__global__ void __launch_bounds__(256) fc_mma_kernel()
{
    extern __shared__ char smc[];
    int tid = threadIdx.x, wid = tid >> 5, lid = tid & 31;
    int bm = blockIdx.x;
    int wm = wid & 1, wn = wid >> 1;
    uint32_t sb = smem_u32(smc);

    float accR[4][4][4] = {}, accG[4][4][4] = {};

    auto issue = [&](int c) {
        size_t offA = ((size_t)bm*128)*128 + (size_t)c*64;
        size_t offW = (size_t)c*64;
        issue_gate(sb + (uint32_t)(c & 1)*GSLOT_B, tid,
                   g_hhi + offA, g_hlo + offA,
                   g_Vhi + offW, g_Vlo + offW, 128);
    };

    issue(0); CP_COMMIT();
    for (int c = 0; c < 2; c++) {
        CP_WAITN(0);
        __syncthreads();
        if (c + 1 < 2) { issue(c + 1); CP_COMMIT(); }
        compute_gate(sb + (uint32_t)(c & 1)*GSLOT_B, accR, accG, wm, wn, lid);
    }

    int lrow = lid >> 2, lcol2 = (lid & 3) << 1;
    int r0 = bm*128 + wm*64 + lrow;
#pragma unroll
    for (int im = 0; im < 4; im++) {
#pragma unroll
        for (int half = 0; half < 2; half++) {
            int r = r0 + im*16 + half*8;
            int cc = r >> 4, b = r & 15;
            size_t base = ((size_t)(b*C + cc))*D;
#pragma unroll
            for (int jn = 0; jn < 4; jn++) {
                int e = wn*32 + jn*8 + lcol2;
                float v0 = fmaxf(accR[im][jn][half*2]   + g_bias[e],     0.f);
                float v1 = fmaxf(accR[im][jn][half*2+1] + g_bias[e+1],   0.f);
                float w0 = fmaxf(accG[im][jn][half*2]   + g_bias[128+e],   0.f);
                float w1 = fmaxf(accG[im][jn][half*2+1] + g_bias[128+e+1], 0.f);
                __nv_bfloat162 hi, lo;
                split2(make_float2(v0, v1), hi, lo);
                *(__nv_bfloat162*)(g_h1hi + base + e) = hi;
                *(__nv_bfloat162*)(g_h1lo + base + e) = lo;
                split2(make_float2(w0, w1), hi, lo);
                *(__nv_bfloat162*)(g_h2hi + base + e) = hi;
                *(__nv_bfloat162*)(g_h2lo + base + e) = lo;
            }
        }
    }
}

// ============================ B_new GEMM + fused softmax epilogue ===========
__global__ void __launch_bounds__(256, 2) bnew_mma_kernel(
    const float* __restrict__ gamma_p, const int* __restrict__ mask,
    float* __restrict__ out)
{
    extern __shared__ char smc[];
    __shared__ int   sMask[128];
    __shared__ float sRow[128];
    int tid = threadIdx.x, wid = tid >> 5, lid = tid & 31;
    int b = blockIdx.z, it = blockIdx.y, jt = blockIdx.x;
    int wm = wid & 1, wn = wid >> 1;
    uint32_t sb = smem_u32(smc);

    if (tid < 128) { sMask[tid] = mask[b*C + jt*128 + tid]; sRow[tid] = 0.f; }

    float acc[4][4][4] = {};
    float gma = gamma_p[0];
    int lrow = lid >> 2, lcol2 = (lid & 3) << 1;

    auto issue = [&](int c) {
        uint32_t slot = sb + (uint32_t)(c % 3)*BUF2_B;
        if (c < 8) {
            const uint8_t* A  = g_F8  + ((size_t)b*C + (size_t)it*128)*C + (size_t)c*128;
            const uint8_t* Bp = g_GT8 + ((size_t)b*C + (size_t)jt*128)*C + (size_t)c*128;
            issue_fp8_128(slot, tid, A, Bp, C);
        } else {
            int tm = (c - 8) >> 1, kh = (c - 8) & 1;
            const __nv_bfloat16* A1 = (tm < 2)  ? g_h1hi : g_h1lo;
            const __nv_bfloat16* B1 = (tm == 1) ? g_h2lo : g_h2hi;
            issue_single(slot, tid,
                         A1 + ((size_t)b*C + (size_t)it*128)*D + kh*64,
                         B1 + ((size_t)b*C + (size_t)jt*128)*D + kh*64, D);
        }
    };

    issue(0); CP_COMMIT();
    issue(1); CP_COMMIT();

    for (int c = 0; c < 14; c++) {
        if (c == 13) CP_WAITN(0); else CP_WAITN(1);
        __syncthreads();
        if (c == 8) {
            float invR[8], invCv[8];
#pragma unroll
            for (int im = 0; im < 4; im++) {
                int r = it*128 + wm*64 + lrow + im*16;
                invR[2*im]   = gma / g_sumF[b*C + r];
                invR[2*im+1] = gma / g_sumF[b*C + r + 8];
            }
#pragma unroll
            for (int jn = 0; jn < 4; jn++) {
                int cj = jt*128 + wn*32 + lcol2 + jn*8;
                invCv[2*jn]   = 1.0f / g_sumG[b*C + cj];
                invCv[2*jn+1] = 1.0f / g_sumG[b*C + cj + 1];
            }
#pragma unroll
            for (int im = 0; im < 4; im++)
#pragma unroll
                for (int jn = 0; jn < 4; jn++) {
                    acc[im][jn][0] *= invR[2*im]   * invCv[2*jn];
                    acc[im][jn][1] *= invR[2*im]   * invCv[2*jn+1];
                    acc[im][jn][2] *= invR[2*im+1] * invCv[2*jn];
                    acc[im][jn][3] *= invR[2*im+1] * invCv[2*jn+1];
                }
        }
        if (c + 2 < 14) { issue(c + 2); CP_COMMIT(); }
        uint32_t base = sb + (uint32_t)(c % 3)*BUF2_B;
        if (c < 8) compute_chunk_fp8(base, base + TILE8_B, acc, wm, wn, lid);
        else       compute_chunk1(base, base + TILE_B, acc, wm, wn, lid);
    }

    // ---- epilogue: diag zero, store fp32, fused masked exp (single bf16) ----
    int gi0 = it*128 + wm*64 + lrow;
    int gj0 = jt*128 + wn*32 + lcol2;
    float* obase = out + (size_t)b*CC;
#pragma unroll
    for (int im = 0; im < 4; im++) {
        int r = gi0 + im*16;
        float rp0 = 0.f, rp1 = 0.f;
#pragma unroll
        for (int jn = 0; jn < 4; jn++) {
            int cj = gj0 + jn*8;
            int lc = wn*32 + lcol2 + jn*8;
            float2 v0 = make_float2(acc[im][jn][0], acc[im][jn][1]);
            float2 v1 = make_float2(acc[im][jn][2], acc[im][jn][3]);
            if (r == cj)        v0.x = 0.f;
            else if (r == cj+1) v0.y = 0.f;
            if (r+8 == cj)      v1.x = 0.f;
            else if (r+8 == cj+1) v1.y = 0.f;
            *(float2*)(obase + (size_t)r*C + cj)     = v0;
            *(float2*)(obase + (size_t)(r+8)*C + cj) = v1;

            int m0 = sMask[lc], m1 = sMask[lc+1];
            float2 e0 = make_float2(m0 ? __expf(v0.x) : 0.f, m1 ? __expf(v0.y) : 0.f);
            float2 e1 = make_float2(m0 ? __expf(v1.x) : 0.f, m1 ? __expf(v1.y) : 0.f);
            rp0 += e0.x + e0.y;
            rp1 += e1.x + e1.y;
            __nv_bfloat162 q0, q1;
            q0.x = __float2bfloat16(e0.x); q0.y = __float2bfloat16(e0.y);
            q1.x = __float2bfloat16(e1.x); q1.y = __float2bfloat16(e1.y);
            *(__nv_bfloat162*)(g_E2 + (size_t)b*CC + (size_t)r*C + cj)     = q0;
            *(__nv_bfloat162*)(g_E2 + (size_t)b*CC + (size_t)(r+8)*C + cj) = q1;
        }
        atomicAdd(&sRow[wm*64 + lrow + im*16],     rp0);
        atomicAdd(&sRow[wm*64 + lrow + im*16 + 8], rp1);
    }
    __syncthreads();
    if (tid < 128) atomicAdd(g_sum2 + b*C + it*128 + tid, sRow[tid]);
}

// ============================ h_tmp GEMM (M=128, 2-mma) + m' construction ====
__global__ void __launch_bounds__(256) htmp_mma_kernel(const float* __restrict__ h)
{
    extern __shared__ char smc[];
    int tid = threadIdx.x, wid = tid >> 5, lid = tid & 31;
    int it = blockIdx.x, b = blockIdx.y;
    int wm = wid & 1, wn = wid >> 1;
    uint32_t sb = smem_u32(smc);

    float acc[4][4][4] = {};

    auto issue = [&](int c) {
        size_t offA = ((size_t)b*C + (size_t)it*128)*C + (size_t)c*64;
        size_t offB = (size_t)b*D*C + (size_t)c*64;
        issue_tiles3(sb + (uint32_t)(c % 3)*BUF3_B, tid,
                     g_E2 + offA,
                     g_hThi + offB, g_hTlo + offB, C, C);
    };

    issue(0); CP_COMMIT();
    issue(1); CP_COMMIT();
    for (int c = 0; c < 16; c++) {
        if (c == 15) CP_WAITN(0); else CP_WAITN(1);
        __syncthreads();
        if (c + 2 < 16) { issue(c + 2); CP_COMMIT(); }
        compute_chunk2(sb + (uint32_t)(c % 3)*BUF3_B, acc, wm, wn, lid);
    }

    int lrow = lid >> 2, lcol2 = (lid & 3) << 1;
    int ci0 = it*128 + wm*64 + lrow;
    int d0  = wn*32 + lcol2;
#pragma unroll
    for (int im = 0; im < 4; im++) {
#pragma unroll
        for (int half = 0; half < 2; half++) {
            int cg = ci0 + im*16 + half*8;
            int r  = cg*16 + b;
            float inv = 1.0f / g_sum2[b*C + cg];
#pragma unroll
            for (int jn = 0; jn < 4; jn++) {
                int dj = d0 + jn*8;
                float2 ht = half ? make_float2(acc[im][jn][2], acc[im][jn][3])
                                 : make_float2(acc[im][jn][0], acc[im][jn][1]);
                ht.x *= inv; ht.y *= inv;
                float2 hv = *(const float2*)(h + (size_t)r*128 + dj);
                float2 seg[3];
                seg[0] = hv;
                seg[1] = ht;
                seg[2] = make_float2(hv.x*ht.x, hv.y*ht.y);
#pragma unroll
                for (int s = 0; s < 3; s++) {
                    __nv_bfloat162 hi, lo;
                    split2(seg[s], hi, lo);
                    size_t o = (size_t)r*384 + s*128 + dj;
                    *(__nv_bfloat162*)(g_mhi + o) = hi;
                    *(__nv_bfloat162*)(g_mlo + o) = lo;
                }
            }
        }
    }
}

// ======== fused gate GEMM + combine: o = relu(m.Wr')*sig(m.Wg') + (1-sig)*h ==
__global__ void __launch_bounds__(256) gate_mma_kernel(
    const float* __restrict__ h, float* __restrict__ o)
{
    extern __shared__ char smc[];
    int tid = threadIdx.x, wid = tid >> 5, lid = tid & 31;
    int bm = blockIdx.x;
    int wm = wid & 1, wn = wid >> 1;
    uint32_t sb = smem_u32(smc);

    float accR[4][4][4] = {}, accG[4][4][4] = {};

    auto issue = [&](int c) {
        size_t offA = ((size_t)bm*128)*384 + (size_t)c*64;
        size_t offW = (size_t)c*64;
        issue_gate(sb + (uint32_t)(c & 1)*GSLOT_B, tid,
                   g_mhi + offA, g_mlo + offA,
                   g_Whi + offW, g_Wlo + offW, 384);
    };

    issue(0); CP_COMMIT();
    for (int c = 0; c < 6; c++) {
        CP_WAITN(0);
        __syncthreads();
        if (c + 1 < 6) { issue(c + 1); CP_COMMIT(); }
        compute_gate(sb + (uint32_t)(c & 1)*GSLOT_B, accR, accG, wm, wn, lid);
    }

    int lrow = lid >> 2, lcol2 = (lid & 3) << 1;
    int r0 = bm*128 + wm*64 + lrow;
#pragma unroll
    for (int im = 0; im < 4; im++) {
#pragma unroll
        for (int half = 0; half < 2; half++) {
            int r = r0 + im*16 + half*8;
#pragma unroll
            for (int jn = 0; jn < 4; jn++) {
                int dj = wn*32 + jn*8 + lcol2;
                float zr0 = accR[im][jn][half*2],     zr1 = accR[im][jn][half*2+1];
                float zg0 = accG[im][jn][half*2],     zg1 = accG[im][jn][half*2+1];
                float2 hv = *(const float2*)(h + (size_t)r*128 + dj);
                float x0 = fmaxf(zr0, 0.f), s0 = 1.0f/(1.0f + __expf(-zg0));
                float x1 = fmaxf(zr1, 0.f), s1 = 1.0f/(1.0f + __expf(-zg1));
                float2 ov;
                ov.x = x0*s0 + (1.0f - s0)*hv.x;
                ov.y = x1*s1 + (1.0f - s1)*hv.y;
                *(float2*)(o + (size_t)r*128 + dj) = ov;
            }
        }
    }
}

// ---------------------------------------------------------------------------
extern "C" void kernel_launch(void* const* d_in, const int* in_sizes, int n_in,
                              void* d_out, int out_size)
{
    const float* h   = (const float*)d_in[0];
    const int*   hm  = (const int*)  d_in[1];
    const float* Bt  = (const float*)d_in[2];
    const float* W1w = (const float*)d_in[3];
    const float* W1b = (const float*)d_in[4];
    const float* W2w = (const float*)d_in[5];
    const float* W2b = (const float*)d_in[6];
    const float* gam = (const float*)d_in[7];
    const float* Wrw = (const float*)d_in[8];
    const float* Wgw = (const float*)d_in[9];

    float* o_out    = (float*)d_out;
    float* bnew_out = (float*)d_out + (size_t)CB*D;

    const int BNEW_SMEM = 3*BUF2_B;        // 110592 -> 2 CTAs/SM
    const int HTMP_SMEM = 3*BUF3_B;        // 165888 -> 1 CTA/SM, ring-3
    const int GATE_SMEM = 2*GSLOT_B;       // 221184 -> 1 CTA/SM, ring-2
    cudaFuncSetAttribute(bnew_mma_kernel, cudaFuncAttributeMaxDynamicSharedMemorySize, BNEW_SMEM);
    cudaFuncSetAttribute(htmp_mma_kernel, cudaFuncAttributeMaxDynamicSharedMemorySize, HTMP_SMEM);
    cudaFuncSetAttribute(gate_mma_kernel, cudaFuncAttributeMaxDynamicSharedMemorySize, GATE_SMEM);
    cudaFuncSetAttribute(fc_mma_kernel,  cudaFuncAttributeMaxDynamicSharedMemorySize, GATE_SMEM);

    wsplit_kernel<<<384, 256>>>(Wrw, Wgw, W1w, W2w, W1b, W2b);  // folds + zeroes
    ht_transpose_kernel<<<dim3(C/32, D/32, BATCH), 256>>>(h);   // also emits h hi/lo
    fc_mma_kernel<<<CB/128, 256, GATE_SMEM>>>();
    esplit_kernel<<<dim3(8, 8, BATCH), 256>>>(Bt, hm);
    bnew_mma_kernel<<<dim3(C/128, C/128, BATCH), 256, BNEW_SMEM>>>(gam, hm, bnew_out);
    htmp_mma_kernel<<<dim3(C/128, BATCH), 256, HTMP_SMEM>>>(h);
    gate_mma_kernel<<<CB/128, 256, GATE_SMEM>>>(h, o_out);
}